// round 2
// baseline (speedup 1.0000x reference)
#include <cuda_runtime.h>
#include <math.h>

// ---------------------------------------------------------------------------
// Problem dims
// ---------------------------------------------------------------------------
#define Bsz 8
#define Sq  1024
#define Dm  768
#define Hh  12
#define DHd 64
#define Ff  3072
#define Mrows (Bsz*Sq)        // 8192
#define NQKV  (3*Hh*DHd)      // 2304
#define LN_EPS 1e-5f

// ---------------------------------------------------------------------------
// Scratch (static device globals; no runtime allocation)  ~285 MB total
// ---------------------------------------------------------------------------
__device__ float g_wqkv[Dm*NQKV];     // repacked [D, 3*H*DH]
__device__ float g_bqkv[NQKV];
__device__ float g_h1[Mrows*Dm];      // ln1(x)
__device__ float g_qkv[Mrows*NQKV];   // [b,s, (q|k|v, h, e)]
__device__ float g_ctx[Mrows*Dm];     // [b,s,h,e]
__device__ float g_y1[Mrows*Dm];      // x + attn out
__device__ float g_h2[Mrows*Dm];      // ln2(y1)
__device__ float g_a1[Mrows*Ff];      // gelu(fc1)

// ---------------------------------------------------------------------------
// Repack per-head QKV weights into one [D, 2304] matrix (+ fused bias vector)
// column c = proj*768 + h*64 + e
// ---------------------------------------------------------------------------
__global__ void repack_qkv_kernel(const float* __restrict__ Wq, const float* __restrict__ bq,
                                  const float* __restrict__ Wk, const float* __restrict__ bk,
                                  const float* __restrict__ Wv, const float* __restrict__ bv)
{
    int idx = blockIdx.x * blockDim.x + threadIdx.x;
    if (idx < Dm * NQKV) {
        int d = idx / NQKV;
        int c = idx % NQKV;
        int proj = c / (Hh*DHd);
        int hc   = c % (Hh*DHd);
        int h = hc / DHd;
        int e = hc % DHd;
        const float* W = (proj == 0) ? Wq : (proj == 1) ? Wk : Wv;
        g_wqkv[idx] = W[((size_t)h*Dm + d)*DHd + e];
    }
    if (idx < NQKV) {
        int proj = idx / (Hh*DHd);
        int hc   = idx % (Hh*DHd);
        const float* bb = (proj == 0) ? bq : (proj == 1) ? bk : bv;
        g_bqkv[idx] = bb[hc];
    }
}

// ---------------------------------------------------------------------------
// LayerNorm over last dim (768). One block per row, 256 threads.
// ---------------------------------------------------------------------------
__global__ void __launch_bounds__(256) ln_kernel(const float* __restrict__ x,
                                                 const float* __restrict__ w,
                                                 const float* __restrict__ b,
                                                 float* __restrict__ out)
{
    __shared__ float red[256];
    int row = blockIdx.x;
    int tid = threadIdx.x;
    const float* xr = x + (size_t)row * Dm;
    float* orow = out + (size_t)row * Dm;

    float v0 = xr[tid], v1 = xr[tid + 256], v2 = xr[tid + 512];
    float s = v0 + v1 + v2;
    red[tid] = s; __syncthreads();
    for (int o = 128; o > 0; o >>= 1) { if (tid < o) red[tid] += red[tid + o]; __syncthreads(); }
    float mu = red[0] * (1.0f / Dm);
    __syncthreads();

    float d0 = v0 - mu, d1 = v1 - mu, d2 = v2 - mu;
    red[tid] = d0*d0 + d1*d1 + d2*d2; __syncthreads();
    for (int o = 128; o > 0; o >>= 1) { if (tid < o) red[tid] += red[tid + o]; __syncthreads(); }
    float inv = rsqrtf(red[0] * (1.0f / Dm) + LN_EPS);

    orow[tid      ] = d0 * inv * w[tid      ] + b[tid      ];
    orow[tid + 256] = d1 * inv * w[tid + 256] + b[tid + 256];
    orow[tid + 512] = d2 * inv * w[tid + 512] + b[tid + 512];
}

// ---------------------------------------------------------------------------
// Classic 128x128x8 register-blocked SGEMM, row-major A[M,K] * B[K,N].
// Epilogue flags: 1=bias[n], 2=gelu(exact), 4=residual[m,n]
// Requires M%128==0, N%128==0, K%8==0 (all shapes here satisfy this).
// ---------------------------------------------------------------------------
__device__ __forceinline__ float gelu_exact(float v) {
    return 0.5f * v * (1.0f + erff(v * 0.70710678118654752440f));
}

template<int EPI>
__global__ void __launch_bounds__(256) sgemm128(const float* __restrict__ A,
                                                const float* __restrict__ Bm,
                                                const float* __restrict__ bias,
                                                const float* __restrict__ res,
                                                float* __restrict__ C,
                                                int M, int N, int K)
{
    __shared__ float As[8][128];
    __shared__ float Bs[8][128];
    int tid  = threadIdx.x;
    int row0 = blockIdx.y * 128;
    int col0 = blockIdx.x * 128;
    int tr = (tid / 16) * 8;
    int tc = (tid % 16) * 8;

    float acc[8][8];
    #pragma unroll
    for (int i = 0; i < 8; i++)
        #pragma unroll
        for (int j = 0; j < 8; j++) acc[i][j] = 0.0f;

    int arow = tid >> 1;             // 0..127
    int acol = (tid & 1) * 4;        // 0 or 4
    int brow = tid >> 5;             // 0..7
    int bcol = (tid & 31) * 4;       // 0..124

    const float* Aptr = A + (size_t)(row0 + arow) * K + acol;
    const float* Bptr = Bm + (size_t)brow * N + col0 + bcol;

    for (int k0 = 0; k0 < K; k0 += 8) {
        float4 a4 = *(const float4*)(Aptr + k0);
        float4 b4 = *(const float4*)(Bptr + (size_t)k0 * N);
        As[acol+0][arow] = a4.x;
        As[acol+1][arow] = a4.y;
        As[acol+2][arow] = a4.z;
        As[acol+3][arow] = a4.w;
        *(float4*)&Bs[brow][bcol] = b4;
        __syncthreads();

        #pragma unroll
        for (int kk = 0; kk < 8; kk++) {
            float4 a0 = *(float4*)&As[kk][tr];
            float4 a1 = *(float4*)&As[kk][tr+4];
            float4 b0 = *(float4*)&Bs[kk][tc];
            float4 b1 = *(float4*)&Bs[kk][tc+4];
            float ar[8] = {a0.x,a0.y,a0.z,a0.w,a1.x,a1.y,a1.z,a1.w};
            float br[8] = {b0.x,b0.y,b0.z,b0.w,b1.x,b1.y,b1.z,b1.w};
            #pragma unroll
            for (int i = 0; i < 8; i++)
                #pragma unroll
                for (int j = 0; j < 8; j++)
                    acc[i][j] += ar[i] * br[j];
        }
        __syncthreads();
    }

    #pragma unroll
    for (int i = 0; i < 8; i++) {
        size_t r = row0 + tr + i;
        #pragma unroll
        for (int j = 0; j < 8; j++) {
            int c = col0 + tc + j;
            float v = acc[i][j];
            if (EPI & 1) v += bias[c];
            if (EPI & 2) v = gelu_exact(v);
            if (EPI & 4) v += res[r * N + c];
            C[r * N + c] = v;
        }
    }
}

// ---------------------------------------------------------------------------
// Fused flash-style attention (fp32). One block per (b, h, q-tile of 64).
// Q tile resident in smem; K/V tiles of 64 streamed through a shared buffer.
// Online softmax with per-row (m, l); O accumulated in registers (4x4/thread).
// Writes ctx in [b,s,h,e] layout so it is directly a [8192,768] matrix.
// Dynamic smem: Qs[64*65] + KV[64*65] + Ss[64*65] + m/l/alpha[64 each]
// ---------------------------------------------------------------------------
#define FA_SMEM ((3*64*65 + 3*64) * sizeof(float))

__global__ void __launch_bounds__(256) flash_attn_kernel(const float* __restrict__ qkv,
                                                         float* __restrict__ ctx)
{
    extern __shared__ float sm[];
    float* Qs   = sm;              // [64][65]
    float* KV   = Qs + 64*65;      // [64][65]
    float* Ss   = KV + 64*65;      // [64][65]
    float* mrow = Ss + 64*65;      // [64]
    float* lrow = mrow + 64;       // [64]
    float* arow = lrow + 64;       // [64]

    int bh = blockIdx.y;
    int b = bh / Hh, h = bh % Hh;
    int q0 = blockIdx.x * 64;
    int tid = threadIdx.x;
    int tr = (tid / 16) * 4;       // output row group
    int tc = (tid % 16) * 4;       // output col group

    const float* qbase = qkv + (size_t)(b*Sq) * NQKV + h*DHd;
    const float* kbase = qbase + Hh*DHd;
    const float* vbase = qbase + 2*Hh*DHd;

    // load Q tile
    for (int i = tid; i < 64*16; i += 256) {
        int r = i >> 4, c4 = (i & 15) * 4;
        float4 q4 = *(const float4*)&qbase[(size_t)(q0 + r) * NQKV + c4];
        Qs[r*65 + c4    ] = q4.x; Qs[r*65 + c4 + 1] = q4.y;
        Qs[r*65 + c4 + 2] = q4.z; Qs[r*65 + c4 + 3] = q4.w;
    }
    if (tid < 64) { mrow[tid] = -INFINITY; lrow[tid] = 0.0f; }

    float o[4][4] = {};
    __syncthreads();

    for (int kt = 0; kt < Sq; kt += 64) {
        // load K tile
        for (int i = tid; i < 64*16; i += 256) {
            int r = i >> 4, c4 = (i & 15) * 4;
            float4 k4 = *(const float4*)&kbase[(size_t)(kt + r) * NQKV + c4];
            KV[r*65 + c4    ] = k4.x; KV[r*65 + c4 + 1] = k4.y;
            KV[r*65 + c4 + 2] = k4.z; KV[r*65 + c4 + 3] = k4.w;
        }
        __syncthreads();

        // S = Q K^T / 8 (4x4 per thread) -> Ss
        float sacc[4][4] = {};
        #pragma unroll 8
        for (int e = 0; e < 64; e++) {
            float qv[4], kv[4];
            #pragma unroll
            for (int i = 0; i < 4; i++) qv[i] = Qs[(tr+i)*65 + e];
            #pragma unroll
            for (int j = 0; j < 4; j++) kv[j] = KV[(tc+j)*65 + e];
            #pragma unroll
            for (int i = 0; i < 4; i++)
                #pragma unroll
                for (int j = 0; j < 4; j++) sacc[i][j] += qv[i] * kv[j];
        }
        #pragma unroll
        for (int i = 0; i < 4; i++)
            #pragma unroll
            for (int j = 0; j < 4; j++)
                Ss[(tr+i)*65 + tc + j] = sacc[i][j] * 0.125f;
        __syncthreads();

        // load V tile (KV free: all S reads done at the sync above)
        for (int i = tid; i < 64*16; i += 256) {
            int r = i >> 4, c4 = (i & 15) * 4;
            float4 v4 = *(const float4*)&vbase[(size_t)(kt + r) * NQKV + c4];
            KV[r*65 + c4    ] = v4.x; KV[r*65 + c4 + 1] = v4.y;
            KV[r*65 + c4 + 2] = v4.z; KV[r*65 + c4 + 3] = v4.w;
        }

        // online softmax: 4 threads per row, 16 entries each
        {
            int row  = tid >> 2;
            int part = (tid & 3) * 16;
            float* srow_p = Ss + row*65 + part;
            float tmax = -INFINITY;
            #pragma unroll
            for (int q = 0; q < 16; q++) tmax = fmaxf(tmax, srow_p[q]);
            tmax = fmaxf(tmax, __shfl_xor_sync(0xffffffffu, tmax, 1));
            tmax = fmaxf(tmax, __shfl_xor_sync(0xffffffffu, tmax, 2));
            float mold = mrow[row];
            float mnew = fmaxf(mold, tmax);
            float psum = 0.0f;
            #pragma unroll
            for (int q = 0; q < 16; q++) {
                float e = __expf(srow_p[q] - mnew);
                srow_p[q] = e;
                psum += e;
            }
            psum += __shfl_xor_sync(0xffffffffu, psum, 1);
            psum += __shfl_xor_sync(0xffffffffu, psum, 2);
            if ((tid & 3) == 0) {
                float al = __expf(mold - mnew);
                arow[row] = al;
                lrow[row] = lrow[row] * al + psum;
                mrow[row] = mnew;
            }
        }
        __syncthreads();

        // rescale O and accumulate P @ V
        float al[4];
        #pragma unroll
        for (int i = 0; i < 4; i++) al[i] = arow[tr+i];
        #pragma unroll
        for (int i = 0; i < 4; i++)
            #pragma unroll
            for (int j = 0; j < 4; j++) o[i][j] *= al[i];

        #pragma unroll 8
        for (int kk = 0; kk < 64; kk++) {
            float pv[4], vv[4];
            #pragma unroll
            for (int i = 0; i < 4; i++) pv[i] = Ss[(tr+i)*65 + kk];
            #pragma unroll
            for (int j = 0; j < 4; j++) vv[j] = KV[kk*65 + tc + j];
            #pragma unroll
            for (int i = 0; i < 4; i++)
                #pragma unroll
                for (int j = 0; j < 4; j++) o[i][j] += pv[i] * vv[j];
        }
        __syncthreads();   // protect Ss/KV before next tile
    }

    // normalize and write ctx [b,s,h,e]
    #pragma unroll
    for (int i = 0; i < 4; i++) {
        int s = q0 + tr + i;
        float inv = 1.0f / lrow[tr+i];
        #pragma unroll
        for (int j = 0; j < 4; j++)
            ctx[((size_t)(b*Sq + s) * Hh + h) * DHd + tc + j] = o[i][j] * inv;
    }
}

// ---------------------------------------------------------------------------
// Launch
// ---------------------------------------------------------------------------
extern "C" void kernel_launch(void* const* d_in, const int* in_sizes, int n_in,
                              void* d_out, int out_size)
{
    (void)in_sizes; (void)n_in; (void)out_size;
    const float* x     = (const float*)d_in[0];
    const float* ln1_w = (const float*)d_in[1];
    const float* ln1_b = (const float*)d_in[2];
    const float* ln2_w = (const float*)d_in[3];
    const float* ln2_b = (const float*)d_in[4];
    const float* Wq    = (const float*)d_in[5];
    const float* bq    = (const float*)d_in[6];
    const float* Wk    = (const float*)d_in[7];
    const float* bk    = (const float*)d_in[8];
    const float* Wv    = (const float*)d_in[9];
    const float* bv    = (const float*)d_in[10];
    const float* Wo    = (const float*)d_in[11];
    const float* bo    = (const float*)d_in[12];
    const float* fc1_w = (const float*)d_in[13];
    const float* fc1_b = (const float*)d_in[14];
    const float* fc2_w = (const float*)d_in[15];
    const float* fc2_b = (const float*)d_in[16];
    float* out = (float*)d_out;

    float *p_wqkv, *p_bqkv, *p_h1, *p_qkv, *p_ctx, *p_y1, *p_h2, *p_a1;
    cudaGetSymbolAddress((void**)&p_wqkv, g_wqkv);
    cudaGetSymbolAddress((void**)&p_bqkv, g_bqkv);
    cudaGetSymbolAddress((void**)&p_h1,   g_h1);
    cudaGetSymbolAddress((void**)&p_qkv,  g_qkv);
    cudaGetSymbolAddress((void**)&p_ctx,  g_ctx);
    cudaGetSymbolAddress((void**)&p_y1,   g_y1);
    cudaGetSymbolAddress((void**)&p_h2,   g_h2);
    cudaGetSymbolAddress((void**)&p_a1,   g_a1);

    static int fa_attr_set = 0;
    if (!fa_attr_set) {
        cudaFuncSetAttribute(flash_attn_kernel,
                             cudaFuncAttributeMaxDynamicSharedMemorySize, (int)FA_SMEM);
        fa_attr_set = 1;
    }

    // 1. repack QKV weights/bias
    repack_qkv_kernel<<<(Dm*NQKV + 255)/256, 256>>>(Wq, bq, Wk, bk, Wv, bv);

    // 2. ln1(x) -> h1
    ln_kernel<<<Mrows, 256>>>(x, ln1_w, ln1_b, p_h1);

    // 3. qkv = h1 @ Wqkv + bqkv   [8192, 2304]
    sgemm128<1><<<dim3(NQKV/128, Mrows/128), 256>>>(p_h1, p_wqkv, p_bqkv, nullptr, p_qkv,
                                                    Mrows, NQKV, Dm);

    // 4-6. fused attention -> ctx [8192, 768]
    flash_attn_kernel<<<dim3(Sq/64, Bsz*Hh), 256, FA_SMEM>>>(p_qkv, p_ctx);

    // 7. y1 = x + ctx @ Wo + bo
    sgemm128<1|4><<<dim3(Dm/128, Mrows/128), 256>>>(p_ctx, Wo, bo, x, p_y1,
                                                    Mrows, Dm, Dm);

    // 8. h2 = ln2(y1)
    ln_kernel<<<Mrows, 256>>>(p_y1, ln2_w, ln2_b, p_h2);

    // 9. a1 = gelu(h2 @ fc1_w + fc1_b)
    sgemm128<1|2><<<dim3(Ff/128, Mrows/128), 256>>>(p_h2, fc1_w, fc1_b, nullptr, p_a1,
                                                    Mrows, Ff, Dm);

    // 10. out = y1 + a1 @ fc2_w + fc2_b
    sgemm128<1|4><<<dim3(Dm/128, Mrows/128), 256>>>(p_a1, fc2_w, fc2_b, p_y1, out,
                                                    Mrows, Dm, Ff);
}

// round 4
// speedup vs baseline: 2.0577x; 2.0577x over previous
#include <cuda_runtime.h>
#include <math.h>
#include <stdint.h>

// ---------------------------------------------------------------------------
// Problem dims
// ---------------------------------------------------------------------------
#define Bsz 8
#define Sq  1024
#define Dm  768
#define Hh  12
#define DHd 64
#define Ff  3072
#define Mrows (Bsz*Sq)        // 8192
#define NQKV  (3*Hh*DHd)      // 2304
#define LN_EPS 1e-5f

// ---------------------------------------------------------------------------
// Scratch (static device globals; no runtime allocation)  ~285 MB total
// ---------------------------------------------------------------------------
__device__ float g_wqkv[Dm*NQKV];     // repacked [D, 3*H*DH]
__device__ float g_bqkv[NQKV];
__device__ float g_h1[Mrows*Dm];      // ln1(x)
__device__ float g_qkv[Mrows*NQKV];   // [b,s, (q|k|v, h, e)]
__device__ float g_ctx[Mrows*Dm];     // [b,s,h,e]
__device__ float g_y1[Mrows*Dm];      // x + attn out
__device__ float g_h2[Mrows*Dm];      // ln2(y1)
__device__ float g_a1[Mrows*Ff];      // gelu(fc1)

// ---------------------------------------------------------------------------
// PTX helpers
// ---------------------------------------------------------------------------
__device__ __forceinline__ uint32_t smem_u32(const void* p) {
    return (uint32_t)__cvta_generic_to_shared(p);
}
__device__ __forceinline__ void cp_async16(uint32_t saddr, const void* g) {
    asm volatile("cp.async.cg.shared.global [%0], [%1], 16;" :: "r"(saddr), "l"(g));
}
__device__ __forceinline__ void cp_commit() { asm volatile("cp.async.commit_group;"); }
__device__ __forceinline__ void cp_wait_all() { asm volatile("cp.async.wait_group 0;"); }

__device__ __forceinline__ uint32_t f2tf(float f) {
    uint32_t r; asm("cvt.rna.tf32.f32 %0, %1;" : "=r"(r) : "f"(f)); return r;
}
__device__ __forceinline__ void mma_tf32(float* c, const uint32_t* a, const uint32_t* b) {
    asm volatile("mma.sync.aligned.m16n8k8.row.col.f32.tf32.tf32.f32 "
        "{%0,%1,%2,%3}, {%4,%5,%6,%7}, {%8,%9}, {%0,%1,%2,%3};"
        : "+f"(c[0]), "+f"(c[1]), "+f"(c[2]), "+f"(c[3])
        : "r"(a[0]), "r"(a[1]), "r"(a[2]), "r"(a[3]), "r"(b[0]), "r"(b[1]));
}

__device__ __forceinline__ float gelu_exact(float v) {
    return 0.5f * v * (1.0f + erff(v * 0.70710678118654752440f));
}

// ---------------------------------------------------------------------------
// Repack per-head QKV weights into one [D, 2304] matrix (+ fused bias vector)
// ---------------------------------------------------------------------------
__global__ void repack_qkv_kernel(const float* __restrict__ Wq, const float* __restrict__ bq,
                                  const float* __restrict__ Wk, const float* __restrict__ bk,
                                  const float* __restrict__ Wv, const float* __restrict__ bv)
{
    int idx = blockIdx.x * blockDim.x + threadIdx.x;
    if (idx < Dm * NQKV) {
        int d = idx / NQKV;
        int c = idx % NQKV;
        int proj = c / (Hh*DHd);
        int hc   = c % (Hh*DHd);
        int h = hc / DHd;
        int e = hc % DHd;
        const float* W = (proj == 0) ? Wq : (proj == 1) ? Wk : Wv;
        g_wqkv[idx] = W[((size_t)h*Dm + d)*DHd + e];
    }
    if (idx < NQKV) {
        int proj = idx / (Hh*DHd);
        int hc   = idx % (Hh*DHd);
        const float* bb = (proj == 0) ? bq : (proj == 1) ? bk : bv;
        g_bqkv[idx] = bb[hc];
    }
}

// ---------------------------------------------------------------------------
// LayerNorm over last dim (768). One block per row, 256 threads.
// ---------------------------------------------------------------------------
__global__ void __launch_bounds__(256) ln_kernel(const float* __restrict__ x,
                                                 const float* __restrict__ w,
                                                 const float* __restrict__ b,
                                                 float* __restrict__ out)
{
    __shared__ float red[256];
    int row = blockIdx.x;
    int tid = threadIdx.x;
    const float* xr = x + (size_t)row * Dm;
    float* orow = out + (size_t)row * Dm;

    float v0 = xr[tid], v1 = xr[tid + 256], v2 = xr[tid + 512];
    float s = v0 + v1 + v2;
    red[tid] = s; __syncthreads();
    for (int o = 128; o > 0; o >>= 1) { if (tid < o) red[tid] += red[tid + o]; __syncthreads(); }
    float mu = red[0] * (1.0f / Dm);
    __syncthreads();

    float d0 = v0 - mu, d1 = v1 - mu, d2 = v2 - mu;
    red[tid] = d0*d0 + d1*d1 + d2*d2; __syncthreads();
    for (int o = 128; o > 0; o >>= 1) { if (tid < o) red[tid] += red[tid + o]; __syncthreads(); }
    float inv = rsqrtf(red[0] * (1.0f / Dm) + LN_EPS);

    orow[tid      ] = d0 * inv * w[tid      ] + b[tid      ];
    orow[tid + 256] = d1 * inv * w[tid + 256] + b[tid + 256];
    orow[tid + 512] = d2 * inv * w[tid + 512] + b[tid + 512];
}

// ---------------------------------------------------------------------------
// TF32 tensor-core GEMM: C = A[M,K] * B[K,N], row-major, 128x128x16 tiles.
// 256 threads = 8 warps (4x2). Warp tile 32x64 via mma.m16n8k8 (2 Mfrag x 8 Nfrag).
// 2-stage cp.async double buffering.
// Epilogue flags: 1=bias[n], 2=gelu(exact), 4=residual[m,n]
// Requires M%128==0, N%128==0, K%16==0.
//
// Smem strides chosen for conflict-free fragment reads:
//   As: [128 rows m][stride 20 floats]
//   Bs: [16 rows k][stride 136 floats]
// ---------------------------------------------------------------------------
#define BM 128
#define BN 128
#define BK 16
#define ASTR 20
#define BSTR 136

template<int EPI>
__global__ void __launch_bounds__(256) tgemm128(const float* __restrict__ A,
                                                const float* __restrict__ Bm,
                                                const float* __restrict__ bias,
                                                const float* __restrict__ res,
                                                float* __restrict__ C,
                                                int M, int N, int K)
{
    __shared__ float As[2][BM*ASTR];   // 2*10240 B
    __shared__ float Bs[2][BK*BSTR];   // 2*8704 B

    int tid  = threadIdx.x;
    int lane = tid & 31;
    int wid  = tid >> 5;
    int wm   = wid & 3;           // 0..3 -> 32-row slice
    int wn   = wid >> 2;          // 0..1 -> 64-col slice
    int row0 = blockIdx.y * BM;
    int col0 = blockIdx.x * BN;

    // loader indices
    int ar = tid >> 2;            // 0..63
    int ac = (tid & 3) << 2;      // 0,4,8,12
    int br = tid >> 5;            // 0..7
    int bc = (tid & 31) << 2;     // 0..124

    const float* Ag = A  + (size_t)(row0 + ar) * K + ac;    // + 64 rows for 2nd
    const float* Bg = Bm + (size_t)br * N + col0 + bc;      // + 8 rows for 2nd

    float acc[2][8][4];
    #pragma unroll
    for (int mt = 0; mt < 2; mt++)
        #pragma unroll
        for (int nt = 0; nt < 8; nt++)
            #pragma unroll
            for (int q = 0; q < 4; q++) acc[mt][nt][q] = 0.0f;

    int nk = K / BK;

    // prologue: stage tile 0
    {
        cp_async16(smem_u32(&As[0][ar*ASTR + ac]),        Ag);
        cp_async16(smem_u32(&As[0][(ar+64)*ASTR + ac]),   Ag + (size_t)64*K);
        cp_async16(smem_u32(&Bs[0][br*BSTR + bc]),        Bg);
        cp_async16(smem_u32(&Bs[0][(br+8)*BSTR + bc]),    Bg + (size_t)8*N);
        cp_commit();
    }

    int mrow = wm*32 + (lane >> 2);   // a-frag base row in tile
    int kcol = lane & 3;              // a/b-frag k offset
    int ncol = wn*64 + (lane >> 2);   // b-frag base col in tile

    for (int kt = 0; kt < nk; kt++) {
        cp_wait_all();
        __syncthreads();
        int cur = kt & 1;

        if (kt + 1 < nk) {
            int nxt = cur ^ 1;
            const float* Agn = Ag + (size_t)(kt+1)*BK;
            const float* Bgn = Bg + (size_t)(kt+1)*BK*N;
            cp_async16(smem_u32(&As[nxt][ar*ASTR + ac]),      Agn);
            cp_async16(smem_u32(&As[nxt][(ar+64)*ASTR + ac]), Agn + (size_t)64*K);
            cp_async16(smem_u32(&Bs[nxt][br*BSTR + bc]),      Bgn);
            cp_async16(smem_u32(&Bs[nxt][(br+8)*BSTR + bc]),  Bgn + (size_t)8*N);
            cp_commit();
        }

        const float* Ab = As[cur];
        const float* Bb = Bs[cur];

        #pragma unroll
        for (int kk = 0; kk < 2; kk++) {
            int kl = kk*8 + kcol;
            uint32_t af[2][4];
            #pragma unroll
            for (int mt = 0; mt < 2; mt++) {
                int r = mrow + mt*16;
                af[mt][0] = f2tf(Ab[r*ASTR + kl]);
                af[mt][1] = f2tf(Ab[(r+8)*ASTR + kl]);
                af[mt][2] = f2tf(Ab[r*ASTR + kl + 4]);
                af[mt][3] = f2tf(Ab[(r+8)*ASTR + kl + 4]);
            }
            #pragma unroll
            for (int nt = 0; nt < 8; nt++) {
                uint32_t bf[2];
                int c = ncol + nt*8;
                bf[0] = f2tf(Bb[kl*BSTR + c]);
                bf[1] = f2tf(Bb[(kl+4)*BSTR + c]);
                mma_tf32(acc[0][nt], af[0], bf);
                mma_tf32(acc[1][nt], af[1], bf);
            }
        }
        // top-of-loop sync of iteration kt+1 orders compute(kt) before any
        // overwrite of buffer cur (which happens at issue of tile kt+2).
    }

    // epilogue: c0/c1 at (row, 2q),(row, 2q+1); c2/c3 at row+8
    #pragma unroll
    for (int mt = 0; mt < 2; mt++) {
        #pragma unroll
        for (int i = 0; i < 2; i++) {
            size_t r = row0 + mrow + mt*16 + i*8;
            #pragma unroll
            for (int nt = 0; nt < 8; nt++) {
                int c = col0 + wn*64 + nt*8 + 2*(lane & 3);
                float v0 = acc[mt][nt][2*i + 0];
                float v1 = acc[mt][nt][2*i + 1];
                if (EPI & 1) { v0 += bias[c]; v1 += bias[c+1]; }
                if (EPI & 2) { v0 = gelu_exact(v0); v1 = gelu_exact(v1); }
                if (EPI & 4) {
                    float2 rr = *(const float2*)&res[r * N + c];
                    v0 += rr.x; v1 += rr.y;
                }
                *(float2*)&C[r * N + c] = make_float2(v0, v1);
            }
        }
    }
}

// ---------------------------------------------------------------------------
// Fused flash-style attention (fp32). One block per (b, h, q-tile of 64).
// ---------------------------------------------------------------------------
#define FA_SMEM ((3*64*65 + 3*64) * sizeof(float))

__global__ void __launch_bounds__(256) flash_attn_kernel(const float* __restrict__ qkv,
                                                         float* __restrict__ ctx)
{
    extern __shared__ float sm[];
    float* Qs   = sm;              // [64][65]
    float* KV   = Qs + 64*65;      // [64][65]
    float* Ss   = KV + 64*65;      // [64][65]
    float* mrow = Ss + 64*65;      // [64]
    float* lrow = mrow + 64;       // [64]
    float* arow = lrow + 64;       // [64]

    int bh = blockIdx.y;
    int b = bh / Hh, h = bh % Hh;
    int q0 = blockIdx.x * 64;
    int tid = threadIdx.x;
    int tr = (tid / 16) * 4;
    int tc = (tid % 16) * 4;

    const float* qbase = qkv + (size_t)(b*Sq) * NQKV + h*DHd;
    const float* kbase = qbase + Hh*DHd;
    const float* vbase = qbase + 2*Hh*DHd;

    for (int i = tid; i < 64*16; i += 256) {
        int r = i >> 4, c4 = (i & 15) * 4;
        float4 q4 = *(const float4*)&qbase[(size_t)(q0 + r) * NQKV + c4];
        Qs[r*65 + c4    ] = q4.x; Qs[r*65 + c4 + 1] = q4.y;
        Qs[r*65 + c4 + 2] = q4.z; Qs[r*65 + c4 + 3] = q4.w;
    }
    if (tid < 64) { mrow[tid] = -INFINITY; lrow[tid] = 0.0f; }

    float o[4][4] = {};
    __syncthreads();

    for (int kt = 0; kt < Sq; kt += 64) {
        for (int i = tid; i < 64*16; i += 256) {
            int r = i >> 4, c4 = (i & 15) * 4;
            float4 k4 = *(const float4*)&kbase[(size_t)(kt + r) * NQKV + c4];
            KV[r*65 + c4    ] = k4.x; KV[r*65 + c4 + 1] = k4.y;
            KV[r*65 + c4 + 2] = k4.z; KV[r*65 + c4 + 3] = k4.w;
        }
        __syncthreads();

        float sacc[4][4] = {};
        #pragma unroll 8
        for (int e = 0; e < 64; e++) {
            float qv[4], kv[4];
            #pragma unroll
            for (int i = 0; i < 4; i++) qv[i] = Qs[(tr+i)*65 + e];
            #pragma unroll
            for (int j = 0; j < 4; j++) kv[j] = KV[(tc+j)*65 + e];
            #pragma unroll
            for (int i = 0; i < 4; i++)
                #pragma unroll
                for (int j = 0; j < 4; j++) sacc[i][j] += qv[i] * kv[j];
        }
        #pragma unroll
        for (int i = 0; i < 4; i++)
            #pragma unroll
            for (int j = 0; j < 4; j++)
                Ss[(tr+i)*65 + tc + j] = sacc[i][j] * 0.125f;
        __syncthreads();

        for (int i = tid; i < 64*16; i += 256) {
            int r = i >> 4, c4 = (i & 15) * 4;
            float4 v4 = *(const float4*)&vbase[(size_t)(kt + r) * NQKV + c4];
            KV[r*65 + c4    ] = v4.x; KV[r*65 + c4 + 1] = v4.y;
            KV[r*65 + c4 + 2] = v4.z; KV[r*65 + c4 + 3] = v4.w;
        }

        {
            int row  = tid >> 2;
            int part = (tid & 3) * 16;
            float* srow_p = Ss + row*65 + part;
            float tmax = -INFINITY;
            #pragma unroll
            for (int q = 0; q < 16; q++) tmax = fmaxf(tmax, srow_p[q]);
            tmax = fmaxf(tmax, __shfl_xor_sync(0xffffffffu, tmax, 1));
            tmax = fmaxf(tmax, __shfl_xor_sync(0xffffffffu, tmax, 2));
            float mold = mrow[row];
            float mnew = fmaxf(mold, tmax);
            float psum = 0.0f;
            #pragma unroll
            for (int q = 0; q < 16; q++) {
                float e = __expf(srow_p[q] - mnew);
                srow_p[q] = e;
                psum += e;
            }
            psum += __shfl_xor_sync(0xffffffffu, psum, 1);
            psum += __shfl_xor_sync(0xffffffffu, psum, 2);
            if ((tid & 3) == 0) {
                float al = __expf(mold - mnew);
                arow[row] = al;
                lrow[row] = lrow[row] * al + psum;
                mrow[row] = mnew;
            }
        }
        __syncthreads();

        float al[4];
        #pragma unroll
        for (int i = 0; i < 4; i++) al[i] = arow[tr+i];
        #pragma unroll
        for (int i = 0; i < 4; i++)
            #pragma unroll
            for (int j = 0; j < 4; j++) o[i][j] *= al[i];

        #pragma unroll 8
        for (int kk = 0; kk < 64; kk++) {
            float pv[4], vv[4];
            #pragma unroll
            for (int i = 0; i < 4; i++) pv[i] = Ss[(tr+i)*65 + kk];
            #pragma unroll
            for (int j = 0; j < 4; j++) vv[j] = KV[kk*65 + tc + j];
            #pragma unroll
            for (int i = 0; i < 4; i++)
                #pragma unroll
                for (int j = 0; j < 4; j++) o[i][j] += pv[i] * vv[j];
        }
        __syncthreads();
    }

    #pragma unroll
    for (int i = 0; i < 4; i++) {
        int s = q0 + tr + i;
        float inv = 1.0f / lrow[tr+i];
        #pragma unroll
        for (int j = 0; j < 4; j++)
            ctx[((size_t)(b*Sq + s) * Hh + h) * DHd + tc + j] = o[i][j] * inv;
    }
}

// ---------------------------------------------------------------------------
// Launch
// ---------------------------------------------------------------------------
extern "C" void kernel_launch(void* const* d_in, const int* in_sizes, int n_in,
                              void* d_out, int out_size)
{
    (void)in_sizes; (void)n_in; (void)out_size;
    const float* x     = (const float*)d_in[0];
    const float* ln1_w = (const float*)d_in[1];
    const float* ln1_b = (const float*)d_in[2];
    const float* ln2_w = (const float*)d_in[3];
    const float* ln2_b = (const float*)d_in[4];
    const float* Wq    = (const float*)d_in[5];
    const float* bq    = (const float*)d_in[6];
    const float* Wk    = (const float*)d_in[7];
    const float* bk    = (const float*)d_in[8];
    const float* Wv    = (const float*)d_in[9];
    const float* bv    = (const float*)d_in[10];
    const float* Wo    = (const float*)d_in[11];
    const float* bo    = (const float*)d_in[12];
    const float* fc1_w = (const float*)d_in[13];
    const float* fc1_b = (const float*)d_in[14];
    const float* fc2_w = (const float*)d_in[15];
    const float* fc2_b = (const float*)d_in[16];
    float* out = (float*)d_out;

    float *p_wqkv, *p_bqkv, *p_h1, *p_qkv, *p_ctx, *p_y1, *p_h2, *p_a1;
    cudaGetSymbolAddress((void**)&p_wqkv, g_wqkv);
    cudaGetSymbolAddress((void**)&p_bqkv, g_bqkv);
    cudaGetSymbolAddress((void**)&p_h1,   g_h1);
    cudaGetSymbolAddress((void**)&p_qkv,  g_qkv);
    cudaGetSymbolAddress((void**)&p_ctx,  g_ctx);
    cudaGetSymbolAddress((void**)&p_y1,   g_y1);
    cudaGetSymbolAddress((void**)&p_h2,   g_h2);
    cudaGetSymbolAddress((void**)&p_a1,   g_a1);

    static int fa_attr_set = 0;
    if (!fa_attr_set) {
        cudaFuncSetAttribute(flash_attn_kernel,
                             cudaFuncAttributeMaxDynamicSharedMemorySize, (int)FA_SMEM);
        fa_attr_set = 1;
    }

    // 1. repack QKV weights/bias
    repack_qkv_kernel<<<(Dm*NQKV + 255)/256, 256>>>(Wq, bq, Wk, bk, Wv, bv);

    // 2. ln1(x) -> h1
    ln_kernel<<<Mrows, 256>>>(x, ln1_w, ln1_b, p_h1);

    // 3. qkv = h1 @ Wqkv + bqkv   [8192, 2304]
    tgemm128<1><<<dim3(NQKV/128, Mrows/128), 256>>>(p_h1, p_wqkv, p_bqkv, nullptr, p_qkv,
                                                    Mrows, NQKV, Dm);

    // 4-6. fused attention -> ctx [8192, 768]
    flash_attn_kernel<<<dim3(Sq/64, Bsz*Hh), 256, FA_SMEM>>>(p_qkv, p_ctx);

    // 7. y1 = x + ctx @ Wo + bo
    tgemm128<1|4><<<dim3(Dm/128, Mrows/128), 256>>>(p_ctx, Wo, bo, x, p_y1,
                                                    Mrows, Dm, Dm);

    // 8. h2 = ln2(y1)
    ln_kernel<<<Mrows, 256>>>(p_y1, ln2_w, ln2_b, p_h2);

    // 9. a1 = gelu(h2 @ fc1_w + fc1_b)
    tgemm128<1|2><<<dim3(Ff/128, Mrows/128), 256>>>(p_h2, fc1_w, fc1_b, nullptr, p_a1,
                                                    Mrows, Ff, Dm);

    // 10. out = y1 + a1 @ fc2_w + fc2_b
    tgemm128<1|4><<<dim3(Dm/128, Mrows/128), 256>>>(p_a1, fc2_w, fc2_b, p_y1, out,
                                                    Mrows, Dm, Ff);
}

// round 5
// speedup vs baseline: 2.8626x; 1.3911x over previous
#include <cuda_runtime.h>
#include <math.h>
#include <stdint.h>

// ---------------------------------------------------------------------------
// Problem dims
// ---------------------------------------------------------------------------
#define Bsz 8
#define Sq  1024
#define Dm  768
#define Hh  12
#define DHd 64
#define Ff  3072
#define Mrows (Bsz*Sq)        // 8192
#define NQKV  (3*Hh*DHd)      // 2304
#define LN_EPS 1e-5f

// ---------------------------------------------------------------------------
// Scratch (static device globals; no runtime allocation)  ~285 MB total
// ---------------------------------------------------------------------------
__device__ float g_wqkv[Dm*NQKV];     // repacked [D, 3*H*DH]
__device__ float g_bqkv[NQKV];
__device__ float g_h1[Mrows*Dm];      // ln1(x)
__device__ float g_qkv[Mrows*NQKV];   // [b,s, (q|k|v, h, e)]
__device__ float g_ctx[Mrows*Dm];     // [b,s,h,e]
__device__ float g_y1[Mrows*Dm];      // x + attn out
__device__ float g_h2[Mrows*Dm];      // ln2(y1)
__device__ float g_a1[Mrows*Ff];      // gelu(fc1)

// ---------------------------------------------------------------------------
// PTX helpers
// ---------------------------------------------------------------------------
__device__ __forceinline__ uint32_t smem_u32(const void* p) {
    return (uint32_t)__cvta_generic_to_shared(p);
}
__device__ __forceinline__ void cp_async16(uint32_t saddr, const void* g) {
    asm volatile("cp.async.cg.shared.global [%0], [%1], 16;" :: "r"(saddr), "l"(g));
}
__device__ __forceinline__ void cp_commit() { asm volatile("cp.async.commit_group;"); }
__device__ __forceinline__ void cp_wait_all() { asm volatile("cp.async.wait_group 0;"); }

__device__ __forceinline__ uint32_t f2tf(float f) {
    uint32_t r; asm("cvt.rna.tf32.f32 %0, %1;" : "=r"(r) : "f"(f)); return r;
}
__device__ __forceinline__ void mma_tf32(float* c, const uint32_t* a, const uint32_t* b) {
    asm volatile("mma.sync.aligned.m16n8k8.row.col.f32.tf32.tf32.f32 "
        "{%0,%1,%2,%3}, {%4,%5,%6,%7}, {%8,%9}, {%0,%1,%2,%3};"
        : "+f"(c[0]), "+f"(c[1]), "+f"(c[2]), "+f"(c[3])
        : "r"(a[0]), "r"(a[1]), "r"(a[2]), "r"(a[3]), "r"(b[0]), "r"(b[1]));
}

__device__ __forceinline__ float gelu_exact(float v) {
    return 0.5f * v * (1.0f + erff(v * 0.70710678118654752440f));
}

// ---------------------------------------------------------------------------
// Repack per-head QKV weights into one [D, 2304] matrix (+ fused bias vector)
// ---------------------------------------------------------------------------
__global__ void repack_qkv_kernel(const float* __restrict__ Wq, const float* __restrict__ bq,
                                  const float* __restrict__ Wk, const float* __restrict__ bk,
                                  const float* __restrict__ Wv, const float* __restrict__ bv)
{
    int idx = blockIdx.x * blockDim.x + threadIdx.x;
    if (idx < Dm * NQKV) {
        int d = idx / NQKV;
        int c = idx % NQKV;
        int proj = c / (Hh*DHd);
        int hc   = c % (Hh*DHd);
        int h = hc / DHd;
        int e = hc % DHd;
        const float* W = (proj == 0) ? Wq : (proj == 1) ? Wk : Wv;
        g_wqkv[idx] = W[((size_t)h*Dm + d)*DHd + e];
    }
    if (idx < NQKV) {
        int proj = idx / (Hh*DHd);
        int hc   = idx % (Hh*DHd);
        const float* bb = (proj == 0) ? bq : (proj == 1) ? bk : bv;
        g_bqkv[idx] = bb[hc];
    }
}

// ---------------------------------------------------------------------------
// LayerNorm over last dim (768). One block per row, 256 threads.
// ---------------------------------------------------------------------------
__global__ void __launch_bounds__(256) ln_kernel(const float* __restrict__ x,
                                                 const float* __restrict__ w,
                                                 const float* __restrict__ b,
                                                 float* __restrict__ out)
{
    __shared__ float red[256];
    int row = blockIdx.x;
    int tid = threadIdx.x;
    const float* xr = x + (size_t)row * Dm;
    float* orow = out + (size_t)row * Dm;

    float v0 = xr[tid], v1 = xr[tid + 256], v2 = xr[tid + 512];
    float s = v0 + v1 + v2;
    red[tid] = s; __syncthreads();
    for (int o = 128; o > 0; o >>= 1) { if (tid < o) red[tid] += red[tid + o]; __syncthreads(); }
    float mu = red[0] * (1.0f / Dm);
    __syncthreads();

    float d0 = v0 - mu, d1 = v1 - mu, d2 = v2 - mu;
    red[tid] = d0*d0 + d1*d1 + d2*d2; __syncthreads();
    for (int o = 128; o > 0; o >>= 1) { if (tid < o) red[tid] += red[tid + o]; __syncthreads(); }
    float inv = rsqrtf(red[0] * (1.0f / Dm) + LN_EPS);

    orow[tid      ] = d0 * inv * w[tid      ] + b[tid      ];
    orow[tid + 256] = d1 * inv * w[tid + 256] + b[tid + 256];
    orow[tid + 512] = d2 * inv * w[tid + 512] + b[tid + 512];
}

// ---------------------------------------------------------------------------
// TF32 tensor-core GEMM: C = A[M,K] * B[K,N], row-major, 128x128x16 tiles.
// (unchanged from the 2040us kernel)
// ---------------------------------------------------------------------------
#define BM 128
#define BN 128
#define BK 16
#define ASTR 20
#define BSTR 136

template<int EPI>
__global__ void __launch_bounds__(256) tgemm128(const float* __restrict__ A,
                                                const float* __restrict__ Bm,
                                                const float* __restrict__ bias,
                                                const float* __restrict__ res,
                                                float* __restrict__ C,
                                                int M, int N, int K)
{
    __shared__ float As[2][BM*ASTR];
    __shared__ float Bs[2][BK*BSTR];

    int tid  = threadIdx.x;
    int lane = tid & 31;
    int wid  = tid >> 5;
    int wm   = wid & 3;
    int wn   = wid >> 2;
    int row0 = blockIdx.y * BM;
    int col0 = blockIdx.x * BN;

    int ar = tid >> 2;
    int ac = (tid & 3) << 2;
    int br = tid >> 5;
    int bc = (tid & 31) << 2;

    const float* Ag = A  + (size_t)(row0 + ar) * K + ac;
    const float* Bg = Bm + (size_t)br * N + col0 + bc;

    float acc[2][8][4];
    #pragma unroll
    for (int mt = 0; mt < 2; mt++)
        #pragma unroll
        for (int nt = 0; nt < 8; nt++)
            #pragma unroll
            for (int q = 0; q < 4; q++) acc[mt][nt][q] = 0.0f;

    int nk = K / BK;

    {
        cp_async16(smem_u32(&As[0][ar*ASTR + ac]),        Ag);
        cp_async16(smem_u32(&As[0][(ar+64)*ASTR + ac]),   Ag + (size_t)64*K);
        cp_async16(smem_u32(&Bs[0][br*BSTR + bc]),        Bg);
        cp_async16(smem_u32(&Bs[0][(br+8)*BSTR + bc]),    Bg + (size_t)8*N);
        cp_commit();
    }

    int mrow = wm*32 + (lane >> 2);
    int kcol = lane & 3;
    int ncol = wn*64 + (lane >> 2);

    for (int kt = 0; kt < nk; kt++) {
        cp_wait_all();
        __syncthreads();
        int cur = kt & 1;

        if (kt + 1 < nk) {
            int nxt = cur ^ 1;
            const float* Agn = Ag + (size_t)(kt+1)*BK;
            const float* Bgn = Bg + (size_t)(kt+1)*BK*N;
            cp_async16(smem_u32(&As[nxt][ar*ASTR + ac]),      Agn);
            cp_async16(smem_u32(&As[nxt][(ar+64)*ASTR + ac]), Agn + (size_t)64*K);
            cp_async16(smem_u32(&Bs[nxt][br*BSTR + bc]),      Bgn);
            cp_async16(smem_u32(&Bs[nxt][(br+8)*BSTR + bc]),  Bgn + (size_t)8*N);
            cp_commit();
        }

        const float* Ab = As[cur];
        const float* Bb = Bs[cur];

        #pragma unroll
        for (int kk = 0; kk < 2; kk++) {
            int kl = kk*8 + kcol;
            uint32_t af[2][4];
            #pragma unroll
            for (int mt = 0; mt < 2; mt++) {
                int r = mrow + mt*16;
                af[mt][0] = f2tf(Ab[r*ASTR + kl]);
                af[mt][1] = f2tf(Ab[(r+8)*ASTR + kl]);
                af[mt][2] = f2tf(Ab[r*ASTR + kl + 4]);
                af[mt][3] = f2tf(Ab[(r+8)*ASTR + kl + 4]);
            }
            #pragma unroll
            for (int nt = 0; nt < 8; nt++) {
                uint32_t bf[2];
                int c = ncol + nt*8;
                bf[0] = f2tf(Bb[kl*BSTR + c]);
                bf[1] = f2tf(Bb[(kl+4)*BSTR + c]);
                mma_tf32(acc[0][nt], af[0], bf);
                mma_tf32(acc[1][nt], af[1], bf);
            }
        }
    }

    #pragma unroll
    for (int mt = 0; mt < 2; mt++) {
        #pragma unroll
        for (int i = 0; i < 2; i++) {
            size_t r = row0 + mrow + mt*16 + i*8;
            #pragma unroll
            for (int nt = 0; nt < 8; nt++) {
                int c = col0 + wn*64 + nt*8 + 2*(lane & 3);
                float v0 = acc[mt][nt][2*i + 0];
                float v1 = acc[mt][nt][2*i + 1];
                if (EPI & 1) { v0 += bias[c]; v1 += bias[c+1]; }
                if (EPI & 2) { v0 = gelu_exact(v0); v1 = gelu_exact(v1); }
                if (EPI & 4) {
                    float2 rr = *(const float2*)&res[r * N + c];
                    v0 += rr.x; v1 += rr.y;
                }
                *(float2*)&C[r * N + c] = make_float2(v0, v1);
            }
        }
    }
}

// ---------------------------------------------------------------------------
// TF32 tensor-core flash attention.
// Block: 256 threads (8 warps), q-tile 128, kv-tile 64, grid (Sq/128, B*H).
// Warp w owns q-rows [w*16, w*16+16): computes S = Q K^T via mma, does online
// softmax in registers (per-quad shfl reductions), round-trips P through smem
// (C-frag -> A-frag layout), accumulates O = P V via mma.
// Score scale (1/8) folded into Q tf32 conversion.
// Smem (uint32 tf32 words): Qs[128*68], Ps[128*68], Ks[64*68], Vs[64*68]
// ---------------------------------------------------------------------------
#define FAT_STR 68
#define FAT_SMEM ((2*128*FAT_STR + 2*64*FAT_STR) * 4)   // 104448 B

__global__ void __launch_bounds__(256, 2) flash_attn_tc(const float* __restrict__ qkv,
                                                        float* __restrict__ ctx)
{
    extern __shared__ uint32_t usm[];
    uint32_t* Qs = usm;                  // [128][68]
    uint32_t* Ps = Qs + 128*FAT_STR;     // [128][68]
    uint32_t* Ks = Ps + 128*FAT_STR;     // [64][68]
    uint32_t* Vs = Ks + 64*FAT_STR;      // [64][68]

    int bh = blockIdx.y;
    int b = bh / Hh, h = bh % Hh;
    int q0 = blockIdx.x * 128;
    int tid = threadIdx.x;
    int lane = tid & 31;
    int w = tid >> 5;
    int r4 = lane >> 2;    // 0..7
    int j4 = lane & 3;     // 0..3

    const float* qbase = qkv + (size_t)(b*Sq)*NQKV + h*DHd;
    const float* kbase = qbase + Hh*DHd;
    const float* vbase = qbase + 2*Hh*DHd;

    // stage Q (pre-scaled by 1/8) as tf32
    for (int i = tid; i < 128*16; i += 256) {
        int r = i >> 4, c = (i & 15) * 4;
        float4 q = *(const float4*)&qbase[(size_t)(q0 + r)*NQKV + c];
        Qs[r*FAT_STR + c + 0] = f2tf(q.x * 0.125f);
        Qs[r*FAT_STR + c + 1] = f2tf(q.y * 0.125f);
        Qs[r*FAT_STR + c + 2] = f2tf(q.z * 0.125f);
        Qs[r*FAT_STR + c + 3] = f2tf(q.w * 0.125f);
    }

    float o[8][4];
    #pragma unroll
    for (int nt = 0; nt < 8; nt++)
        #pragma unroll
        for (int q = 0; q < 4; q++) o[nt][q] = 0.0f;
    float mreg[2] = {-INFINITY, -INFINITY};
    float lreg[2] = {0.0f, 0.0f};

    int prow = w*16 + r4;   // this thread's first q-row (local)

    for (int kt = 0; kt < Sq/64; kt++) {
        __syncthreads();   // previous tile's Ks/Vs reads done (also covers Qs staging on kt=0)
        for (int i = tid; i < 64*16; i += 256) {
            int r = i >> 4, c = (i & 15) * 4;
            float4 kk = *(const float4*)&kbase[(size_t)(kt*64 + r)*NQKV + c];
            float4 vv = *(const float4*)&vbase[(size_t)(kt*64 + r)*NQKV + c];
            Ks[r*FAT_STR + c + 0] = f2tf(kk.x);
            Ks[r*FAT_STR + c + 1] = f2tf(kk.y);
            Ks[r*FAT_STR + c + 2] = f2tf(kk.z);
            Ks[r*FAT_STR + c + 3] = f2tf(kk.w);
            Vs[r*FAT_STR + c + 0] = f2tf(vv.x);
            Vs[r*FAT_STR + c + 1] = f2tf(vv.y);
            Vs[r*FAT_STR + c + 2] = f2tf(vv.z);
            Vs[r*FAT_STR + c + 3] = f2tf(vv.w);
        }
        __syncthreads();

        // S = Q K^T  (16 rows x 64 cols per warp)
        float s[8][4];
        #pragma unroll
        for (int nt = 0; nt < 8; nt++)
            #pragma unroll
            for (int q = 0; q < 4; q++) s[nt][q] = 0.0f;

        #pragma unroll
        for (int ks = 0; ks < 8; ks++) {
            int k = ks*8 + j4;
            uint32_t a[4];
            a[0] = Qs[prow*FAT_STR + k];
            a[1] = Qs[(prow+8)*FAT_STR + k];
            a[2] = Qs[prow*FAT_STR + k + 4];
            a[3] = Qs[(prow+8)*FAT_STR + k + 4];
            #pragma unroll
            for (int nt = 0; nt < 8; nt++) {
                uint32_t bf[2];
                bf[0] = Ks[(nt*8 + r4)*FAT_STR + k];
                bf[1] = Ks[(nt*8 + r4)*FAT_STR + k + 4];
                mma_tf32(s[nt], a, bf);
            }
        }

        // online softmax (rows prow, prow+8); quad (xor 1,2) reductions
        float mx0 = -INFINITY, mx1 = -INFINITY;
        #pragma unroll
        for (int nt = 0; nt < 8; nt++) {
            mx0 = fmaxf(mx0, fmaxf(s[nt][0], s[nt][1]));
            mx1 = fmaxf(mx1, fmaxf(s[nt][2], s[nt][3]));
        }
        mx0 = fmaxf(mx0, __shfl_xor_sync(0xffffffffu, mx0, 1));
        mx0 = fmaxf(mx0, __shfl_xor_sync(0xffffffffu, mx0, 2));
        mx1 = fmaxf(mx1, __shfl_xor_sync(0xffffffffu, mx1, 1));
        mx1 = fmaxf(mx1, __shfl_xor_sync(0xffffffffu, mx1, 2));

        float mn0 = fmaxf(mreg[0], mx0);
        float mn1 = fmaxf(mreg[1], mx1);
        float al0 = __expf(mreg[0] - mn0);
        float al1 = __expf(mreg[1] - mn1);

        float sum0 = 0.0f, sum1 = 0.0f;
        #pragma unroll
        for (int nt = 0; nt < 8; nt++) {
            s[nt][0] = __expf(s[nt][0] - mn0);
            s[nt][1] = __expf(s[nt][1] - mn0);
            s[nt][2] = __expf(s[nt][2] - mn1);
            s[nt][3] = __expf(s[nt][3] - mn1);
            sum0 += s[nt][0] + s[nt][1];
            sum1 += s[nt][2] + s[nt][3];
        }
        sum0 += __shfl_xor_sync(0xffffffffu, sum0, 1);
        sum0 += __shfl_xor_sync(0xffffffffu, sum0, 2);
        sum1 += __shfl_xor_sync(0xffffffffu, sum1, 1);
        sum1 += __shfl_xor_sync(0xffffffffu, sum1, 2);

        lreg[0] = lreg[0]*al0 + sum0;  mreg[0] = mn0;
        lreg[1] = lreg[1]*al1 + sum1;  mreg[1] = mn1;

        #pragma unroll
        for (int nt = 0; nt < 8; nt++) {
            o[nt][0] *= al0; o[nt][1] *= al0;
            o[nt][2] *= al1; o[nt][3] *= al1;
        }

        // P (tf32) -> Ps, own rows only
        #pragma unroll
        for (int nt = 0; nt < 8; nt++) {
            int c = nt*8 + 2*j4;
            Ps[prow*FAT_STR + c]       = f2tf(s[nt][0]);
            Ps[prow*FAT_STR + c + 1]   = f2tf(s[nt][1]);
            Ps[(prow+8)*FAT_STR + c]   = f2tf(s[nt][2]);
            Ps[(prow+8)*FAT_STR + c+1] = f2tf(s[nt][3]);
        }
        __syncwarp();   // STS -> LDS ordering within the warp

        // O += P V
        #pragma unroll
        for (int ks = 0; ks < 8; ks++) {
            int k = ks*8 + j4;
            uint32_t a[4];
            a[0] = Ps[prow*FAT_STR + k];
            a[1] = Ps[(prow+8)*FAT_STR + k];
            a[2] = Ps[prow*FAT_STR + k + 4];
            a[3] = Ps[(prow+8)*FAT_STR + k + 4];
            #pragma unroll
            for (int nt = 0; nt < 8; nt++) {
                uint32_t bf[2];
                bf[0] = Vs[(ks*8 + j4)*FAT_STR + nt*8 + r4];
                bf[1] = Vs[(ks*8 + j4 + 4)*FAT_STR + nt*8 + r4];
                mma_tf32(o[nt], a, bf);
            }
        }
    }

    // normalize & store ctx [b,s,h,e]
    float inv0 = 1.0f / lreg[0];
    float inv1 = 1.0f / lreg[1];
    int gr0 = q0 + prow;
    int gr1 = gr0 + 8;
    #pragma unroll
    for (int nt = 0; nt < 8; nt++) {
        int c = nt*8 + 2*j4;
        *(float2*)&ctx[((size_t)(b*Sq + gr0)*Hh + h)*DHd + c] =
            make_float2(o[nt][0]*inv0, o[nt][1]*inv0);
        *(float2*)&ctx[((size_t)(b*Sq + gr1)*Hh + h)*DHd + c] =
            make_float2(o[nt][2]*inv1, o[nt][3]*inv1);
    }
}

// ---------------------------------------------------------------------------
// Launch
// ---------------------------------------------------------------------------
extern "C" void kernel_launch(void* const* d_in, const int* in_sizes, int n_in,
                              void* d_out, int out_size)
{
    (void)in_sizes; (void)n_in; (void)out_size;
    const float* x     = (const float*)d_in[0];
    const float* ln1_w = (const float*)d_in[1];
    const float* ln1_b = (const float*)d_in[2];
    const float* ln2_w = (const float*)d_in[3];
    const float* ln2_b = (const float*)d_in[4];
    const float* Wq    = (const float*)d_in[5];
    const float* bq    = (const float*)d_in[6];
    const float* Wk    = (const float*)d_in[7];
    const float* bk    = (const float*)d_in[8];
    const float* Wv    = (const float*)d_in[9];
    const float* bv    = (const float*)d_in[10];
    const float* Wo    = (const float*)d_in[11];
    const float* bo    = (const float*)d_in[12];
    const float* fc1_w = (const float*)d_in[13];
    const float* fc1_b = (const float*)d_in[14];
    const float* fc2_w = (const float*)d_in[15];
    const float* fc2_b = (const float*)d_in[16];
    float* out = (float*)d_out;

    float *p_wqkv, *p_bqkv, *p_h1, *p_qkv, *p_ctx, *p_y1, *p_h2, *p_a1;
    cudaGetSymbolAddress((void**)&p_wqkv, g_wqkv);
    cudaGetSymbolAddress((void**)&p_bqkv, g_bqkv);
    cudaGetSymbolAddress((void**)&p_h1,   g_h1);
    cudaGetSymbolAddress((void**)&p_qkv,  g_qkv);
    cudaGetSymbolAddress((void**)&p_ctx,  g_ctx);
    cudaGetSymbolAddress((void**)&p_y1,   g_y1);
    cudaGetSymbolAddress((void**)&p_h2,   g_h2);
    cudaGetSymbolAddress((void**)&p_a1,   g_a1);

    static int fa_attr_set = 0;
    if (!fa_attr_set) {
        cudaFuncSetAttribute(flash_attn_tc,
                             cudaFuncAttributeMaxDynamicSharedMemorySize, (int)FAT_SMEM);
        fa_attr_set = 1;
    }

    // 1. repack QKV weights/bias
    repack_qkv_kernel<<<(Dm*NQKV + 255)/256, 256>>>(Wq, bq, Wk, bk, Wv, bv);

    // 2. ln1(x) -> h1
    ln_kernel<<<Mrows, 256>>>(x, ln1_w, ln1_b, p_h1);

    // 3. qkv = h1 @ Wqkv + bqkv   [8192, 2304]
    tgemm128<1><<<dim3(NQKV/128, Mrows/128), 256>>>(p_h1, p_wqkv, p_bqkv, nullptr, p_qkv,
                                                    Mrows, NQKV, Dm);

    // 4-6. fused tensor-core attention -> ctx [8192, 768]
    flash_attn_tc<<<dim3(Sq/128, Bsz*Hh), 256, FAT_SMEM>>>(p_qkv, p_ctx);

    // 7. y1 = x + ctx @ Wo + bo
    tgemm128<1|4><<<dim3(Dm/128, Mrows/128), 256>>>(p_ctx, Wo, bo, x, p_y1,
                                                    Mrows, Dm, Dm);

    // 8. h2 = ln2(y1)
    ln_kernel<<<Mrows, 256>>>(p_y1, ln2_w, ln2_b, p_h2);

    // 9. a1 = gelu(h2 @ fc1_w + fc1_b)
    tgemm128<1|2><<<dim3(Ff/128, Mrows/128), 256>>>(p_h2, fc1_w, fc1_b, nullptr, p_a1,
                                                    Mrows, Ff, Dm);

    // 10. out = y1 + a1 @ fc2_w + fc2_b
    tgemm128<1|4><<<dim3(Dm/128, Mrows/128), 256>>>(p_a1, fc2_w, fc2_b, p_y1, out,
                                                    Mrows, Dm, Ff);
}

// round 6
// speedup vs baseline: 3.1388x; 1.0965x over previous
#include <cuda_runtime.h>
#include <math.h>
#include <stdint.h>

// ---------------------------------------------------------------------------
// Problem dims
// ---------------------------------------------------------------------------
#define Bsz 8
#define Sq  1024
#define Dm  768
#define Hh  12
#define DHd 64
#define Ff  3072
#define Mrows (Bsz*Sq)        // 8192
#define NQKV  (3*Hh*DHd)      // 2304
#define LN_EPS 1e-5f

// ---------------------------------------------------------------------------
// Scratch (static device globals; no runtime allocation)
// ---------------------------------------------------------------------------
__device__ float g_wqkv[Dm*NQKV];     // repacked + tf32-rounded [D, 3*H*DH]
__device__ float g_bqkv[NQKV];
__device__ float g_wo_r[Dm*Dm];       // tf32-rounded Wo
__device__ float g_fc1_r[Dm*Ff];      // tf32-rounded fc1_w
__device__ float g_fc2_r[Ff*Dm];      // tf32-rounded fc2_w
__device__ float g_h1[Mrows*Dm];      // ln1(x), tf32-rounded
__device__ float g_qkv[Mrows*NQKV];   // [b,s, (q|k|v, h, e)]
__device__ float g_ctx[Mrows*Dm];     // [b,s,h,e], tf32-rounded
__device__ float g_y1[Mrows*Dm];      // x + attn out (full fp32)
__device__ float g_h2[Mrows*Dm];      // ln2(y1), tf32-rounded
__device__ float g_a1[Mrows*Ff];      // gelu(fc1), tf32-rounded

// ---------------------------------------------------------------------------
// PTX helpers
// ---------------------------------------------------------------------------
__device__ __forceinline__ uint32_t smem_u32(const void* p) {
    return (uint32_t)__cvta_generic_to_shared(p);
}
__device__ __forceinline__ void cp_async16(uint32_t saddr, const void* g) {
    asm volatile("cp.async.cg.shared.global [%0], [%1], 16;" :: "r"(saddr), "l"(g));
}
__device__ __forceinline__ void cp_commit() { asm volatile("cp.async.commit_group;"); }
__device__ __forceinline__ void cp_wait_all() { asm volatile("cp.async.wait_group 0;"); }

__device__ __forceinline__ uint32_t f2tf(float f) {
    uint32_t r; asm("cvt.rna.tf32.f32 %0, %1;" : "=r"(r) : "f"(f)); return r;
}
// rna-round a float to an exact tf32 value (still a valid fp32)
__device__ __forceinline__ float tf32r(float f) { return __uint_as_float(f2tf(f)); }

__device__ __forceinline__ void mma_tf32(float* c, const uint32_t* a, const uint32_t* b) {
    asm volatile("mma.sync.aligned.m16n8k8.row.col.f32.tf32.tf32.f32 "
        "{%0,%1,%2,%3}, {%4,%5,%6,%7}, {%8,%9}, {%0,%1,%2,%3};"
        : "+f"(c[0]), "+f"(c[1]), "+f"(c[2]), "+f"(c[3])
        : "r"(a[0]), "r"(a[1]), "r"(a[2]), "r"(a[3]), "r"(b[0]), "r"(b[1]));
}

__device__ __forceinline__ float gelu_exact(float v) {
    return 0.5f * v * (1.0f + erff(v * 0.70710678118654752440f));
}

// ---------------------------------------------------------------------------
// Round-copy a weight matrix to exact-tf32 fp32 values
// ---------------------------------------------------------------------------
__global__ void round_copy(const float* __restrict__ src, float* __restrict__ dst, int n)
{
    int i = blockIdx.x * blockDim.x + threadIdx.x;
    if (i < n) dst[i] = tf32r(src[i]);
}

// ---------------------------------------------------------------------------
// Repack per-head QKV weights into one [D, 2304] matrix (+ bias), tf32-rounded
// ---------------------------------------------------------------------------
__global__ void repack_qkv_kernel(const float* __restrict__ Wq, const float* __restrict__ bq,
                                  const float* __restrict__ Wk, const float* __restrict__ bk,
                                  const float* __restrict__ Wv, const float* __restrict__ bv)
{
    int idx = blockIdx.x * blockDim.x + threadIdx.x;
    if (idx < Dm * NQKV) {
        int d = idx / NQKV;
        int c = idx % NQKV;
        int proj = c / (Hh*DHd);
        int hc   = c % (Hh*DHd);
        int h = hc / DHd;
        int e = hc % DHd;
        const float* W = (proj == 0) ? Wq : (proj == 1) ? Wk : Wv;
        g_wqkv[idx] = tf32r(W[((size_t)h*Dm + d)*DHd + e]);
    }
    if (idx < NQKV) {
        int proj = idx / (Hh*DHd);
        int hc   = idx % (Hh*DHd);
        const float* bb = (proj == 0) ? bq : (proj == 1) ? bk : bv;
        g_bqkv[idx] = bb[hc];
    }
}

// ---------------------------------------------------------------------------
// LayerNorm over last dim (768). Warp per row, shfl-only, 8 rows per block.
// Output is tf32-rounded (it only ever feeds a GEMM A operand).
// ---------------------------------------------------------------------------
__global__ void __launch_bounds__(256) ln_kernel(const float* __restrict__ x,
                                                 const float* __restrict__ w,
                                                 const float* __restrict__ b,
                                                 float* __restrict__ out)
{
    int warp = threadIdx.x >> 5;
    int lane = threadIdx.x & 31;
    int row  = blockIdx.x * 8 + warp;
    const float* xr = x + (size_t)row * Dm;
    float* orow = out + (size_t)row * Dm;

    float4 v[6];
    #pragma unroll
    for (int i = 0; i < 6; i++)
        v[i] = *(const float4*)&xr[(lane + i*32) * 4];

    float s = 0.0f;
    #pragma unroll
    for (int i = 0; i < 6; i++) s += v[i].x + v[i].y + v[i].z + v[i].w;
    #pragma unroll
    for (int o = 16; o > 0; o >>= 1) s += __shfl_xor_sync(0xffffffffu, s, o);
    float mu = s * (1.0f / Dm);

    float vs = 0.0f;
    #pragma unroll
    for (int i = 0; i < 6; i++) {
        float a0 = v[i].x - mu, a1 = v[i].y - mu, a2 = v[i].z - mu, a3 = v[i].w - mu;
        v[i] = make_float4(a0, a1, a2, a3);
        vs += a0*a0 + a1*a1 + a2*a2 + a3*a3;
    }
    #pragma unroll
    for (int o = 16; o > 0; o >>= 1) vs += __shfl_xor_sync(0xffffffffu, vs, o);
    float inv = rsqrtf(vs * (1.0f / Dm) + LN_EPS);

    #pragma unroll
    for (int i = 0; i < 6; i++) {
        int c = (lane + i*32) * 4;
        float4 ww = *(const float4*)&w[c];
        float4 bb = *(const float4*)&b[c];
        float4 r;
        r.x = tf32r(v[i].x * inv * ww.x + bb.x);
        r.y = tf32r(v[i].y * inv * ww.y + bb.y);
        r.z = tf32r(v[i].z * inv * ww.z + bb.z);
        r.w = tf32r(v[i].w * inv * ww.w + bb.w);
        *(float4*)&orow[c] = r;
    }
}

// ---------------------------------------------------------------------------
// TF32 tensor-core GEMM: C = A[M,K] * B[K,N], row-major, 128x128x16 tiles.
// Inputs MUST already be exact tf32 values (pre-rounded); raw bits are fed
// to mma with no per-use cvt.
// Epilogue flags: 1=bias[n], 2=gelu(exact), 4=residual[m,n], 8=tf32-round out
// ---------------------------------------------------------------------------
#define BM 128
#define BN 128
#define BK 16
#define ASTR 20
#define BSTR 136

template<int EPI>
__global__ void __launch_bounds__(256) tgemm128(const float* __restrict__ A,
                                                const float* __restrict__ Bm,
                                                const float* __restrict__ bias,
                                                const float* __restrict__ res,
                                                float* __restrict__ C,
                                                int M, int N, int K)
{
    __shared__ float As[2][BM*ASTR];
    __shared__ float Bs[2][BK*BSTR];

    int tid  = threadIdx.x;
    int lane = tid & 31;
    int wid  = tid >> 5;
    int wm   = wid & 3;
    int wn   = wid >> 2;
    int row0 = blockIdx.y * BM;
    int col0 = blockIdx.x * BN;

    int ar = tid >> 2;
    int ac = (tid & 3) << 2;
    int br = tid >> 5;
    int bc = (tid & 31) << 2;

    const float* Ag = A  + (size_t)(row0 + ar) * K + ac;
    const float* Bg = Bm + (size_t)br * N + col0 + bc;

    float acc[2][8][4];
    #pragma unroll
    for (int mt = 0; mt < 2; mt++)
        #pragma unroll
        for (int nt = 0; nt < 8; nt++)
            #pragma unroll
            for (int q = 0; q < 4; q++) acc[mt][nt][q] = 0.0f;

    int nk = K / BK;

    {
        cp_async16(smem_u32(&As[0][ar*ASTR + ac]),        Ag);
        cp_async16(smem_u32(&As[0][(ar+64)*ASTR + ac]),   Ag + (size_t)64*K);
        cp_async16(smem_u32(&Bs[0][br*BSTR + bc]),        Bg);
        cp_async16(smem_u32(&Bs[0][(br+8)*BSTR + bc]),    Bg + (size_t)8*N);
        cp_commit();
    }

    int mrow = wm*32 + (lane >> 2);
    int kcol = lane & 3;
    int ncol = wn*64 + (lane >> 2);

    for (int kt = 0; kt < nk; kt++) {
        cp_wait_all();
        __syncthreads();
        int cur = kt & 1;

        if (kt + 1 < nk) {
            int nxt = cur ^ 1;
            const float* Agn = Ag + (size_t)(kt+1)*BK;
            const float* Bgn = Bg + (size_t)(kt+1)*BK*N;
            cp_async16(smem_u32(&As[nxt][ar*ASTR + ac]),      Agn);
            cp_async16(smem_u32(&As[nxt][(ar+64)*ASTR + ac]), Agn + (size_t)64*K);
            cp_async16(smem_u32(&Bs[nxt][br*BSTR + bc]),      Bgn);
            cp_async16(smem_u32(&Bs[nxt][(br+8)*BSTR + bc]),  Bgn + (size_t)8*N);
            cp_commit();
        }

        const uint32_t* Ab = (const uint32_t*)As[cur];
        const uint32_t* Bb = (const uint32_t*)Bs[cur];

        #pragma unroll
        for (int kk = 0; kk < 2; kk++) {
            int kl = kk*8 + kcol;
            uint32_t af[2][4];
            #pragma unroll
            for (int mt = 0; mt < 2; mt++) {
                int r = mrow + mt*16;
                af[mt][0] = Ab[r*ASTR + kl];
                af[mt][1] = Ab[(r+8)*ASTR + kl];
                af[mt][2] = Ab[r*ASTR + kl + 4];
                af[mt][3] = Ab[(r+8)*ASTR + kl + 4];
            }
            #pragma unroll
            for (int nt = 0; nt < 8; nt++) {
                uint32_t bf[2];
                int c = ncol + nt*8;
                bf[0] = Bb[kl*BSTR + c];
                bf[1] = Bb[(kl+4)*BSTR + c];
                mma_tf32(acc[0][nt], af[0], bf);
                mma_tf32(acc[1][nt], af[1], bf);
            }
        }
    }

    #pragma unroll
    for (int mt = 0; mt < 2; mt++) {
        #pragma unroll
        for (int i = 0; i < 2; i++) {
            size_t r = row0 + mrow + mt*16 + i*8;
            #pragma unroll
            for (int nt = 0; nt < 8; nt++) {
                int c = col0 + wn*64 + nt*8 + 2*(lane & 3);
                float v0 = acc[mt][nt][2*i + 0];
                float v1 = acc[mt][nt][2*i + 1];
                if (EPI & 1) { v0 += bias[c]; v1 += bias[c+1]; }
                if (EPI & 2) { v0 = gelu_exact(v0); v1 = gelu_exact(v1); }
                if (EPI & 4) {
                    float2 rr = *(const float2*)&res[r * N + c];
                    v0 += rr.x; v1 += rr.y;
                }
                if (EPI & 8) { v0 = tf32r(v0); v1 = tf32r(v1); }
                *(float2*)&C[r * N + c] = make_float2(v0, v1);
            }
        }
    }
}

// ---------------------------------------------------------------------------
// TF32 tensor-core flash attention (unchanged core; ctx store tf32-rounded).
// ---------------------------------------------------------------------------
#define FAT_STR 68
#define FAT_SMEM ((2*128*FAT_STR + 2*64*FAT_STR) * 4)   // 104448 B

__global__ void __launch_bounds__(256, 2) flash_attn_tc(const float* __restrict__ qkv,
                                                        float* __restrict__ ctx)
{
    extern __shared__ uint32_t usm[];
    uint32_t* Qs = usm;                  // [128][68]
    uint32_t* Ps = Qs + 128*FAT_STR;     // [128][68]
    uint32_t* Ks = Ps + 128*FAT_STR;     // [64][68]
    uint32_t* Vs = Ks + 64*FAT_STR;      // [64][68]

    int bh = blockIdx.y;
    int b = bh / Hh, h = bh % Hh;
    int q0 = blockIdx.x * 128;
    int tid = threadIdx.x;
    int lane = tid & 31;
    int w = tid >> 5;
    int r4 = lane >> 2;
    int j4 = lane & 3;

    const float* qbase = qkv + (size_t)(b*Sq)*NQKV + h*DHd;
    const float* kbase = qbase + Hh*DHd;
    const float* vbase = qbase + 2*Hh*DHd;

    for (int i = tid; i < 128*16; i += 256) {
        int r = i >> 4, c = (i & 15) * 4;
        float4 q = *(const float4*)&qbase[(size_t)(q0 + r)*NQKV + c];
        Qs[r*FAT_STR + c + 0] = f2tf(q.x * 0.125f);
        Qs[r*FAT_STR + c + 1] = f2tf(q.y * 0.125f);
        Qs[r*FAT_STR + c + 2] = f2tf(q.z * 0.125f);
        Qs[r*FAT_STR + c + 3] = f2tf(q.w * 0.125f);
    }

    float o[8][4];
    #pragma unroll
    for (int nt = 0; nt < 8; nt++)
        #pragma unroll
        for (int q = 0; q < 4; q++) o[nt][q] = 0.0f;
    float mreg[2] = {-INFINITY, -INFINITY};
    float lreg[2] = {0.0f, 0.0f};

    int prow = w*16 + r4;

    for (int kt = 0; kt < Sq/64; kt++) {
        __syncthreads();
        for (int i = tid; i < 64*16; i += 256) {
            int r = i >> 4, c = (i & 15) * 4;
            float4 kk = *(const float4*)&kbase[(size_t)(kt*64 + r)*NQKV + c];
            float4 vv = *(const float4*)&vbase[(size_t)(kt*64 + r)*NQKV + c];
            Ks[r*FAT_STR + c + 0] = f2tf(kk.x);
            Ks[r*FAT_STR + c + 1] = f2tf(kk.y);
            Ks[r*FAT_STR + c + 2] = f2tf(kk.z);
            Ks[r*FAT_STR + c + 3] = f2tf(kk.w);
            Vs[r*FAT_STR + c + 0] = f2tf(vv.x);
            Vs[r*FAT_STR + c + 1] = f2tf(vv.y);
            Vs[r*FAT_STR + c + 2] = f2tf(vv.z);
            Vs[r*FAT_STR + c + 3] = f2tf(vv.w);
        }
        __syncthreads();

        float s[8][4];
        #pragma unroll
        for (int nt = 0; nt < 8; nt++)
            #pragma unroll
            for (int q = 0; q < 4; q++) s[nt][q] = 0.0f;

        #pragma unroll
        for (int ks = 0; ks < 8; ks++) {
            int k = ks*8 + j4;
            uint32_t a[4];
            a[0] = Qs[prow*FAT_STR + k];
            a[1] = Qs[(prow+8)*FAT_STR + k];
            a[2] = Qs[prow*FAT_STR + k + 4];
            a[3] = Qs[(prow+8)*FAT_STR + k + 4];
            #pragma unroll
            for (int nt = 0; nt < 8; nt++) {
                uint32_t bf[2];
                bf[0] = Ks[(nt*8 + r4)*FAT_STR + k];
                bf[1] = Ks[(nt*8 + r4)*FAT_STR + k + 4];
                mma_tf32(s[nt], a, bf);
            }
        }

        float mx0 = -INFINITY, mx1 = -INFINITY;
        #pragma unroll
        for (int nt = 0; nt < 8; nt++) {
            mx0 = fmaxf(mx0, fmaxf(s[nt][0], s[nt][1]));
            mx1 = fmaxf(mx1, fmaxf(s[nt][2], s[nt][3]));
        }
        mx0 = fmaxf(mx0, __shfl_xor_sync(0xffffffffu, mx0, 1));
        mx0 = fmaxf(mx0, __shfl_xor_sync(0xffffffffu, mx0, 2));
        mx1 = fmaxf(mx1, __shfl_xor_sync(0xffffffffu, mx1, 1));
        mx1 = fmaxf(mx1, __shfl_xor_sync(0xffffffffu, mx1, 2));

        float mn0 = fmaxf(mreg[0], mx0);
        float mn1 = fmaxf(mreg[1], mx1);
        float al0 = __expf(mreg[0] - mn0);
        float al1 = __expf(mreg[1] - mn1);

        float sum0 = 0.0f, sum1 = 0.0f;
        #pragma unroll
        for (int nt = 0; nt < 8; nt++) {
            s[nt][0] = __expf(s[nt][0] - mn0);
            s[nt][1] = __expf(s[nt][1] - mn0);
            s[nt][2] = __expf(s[nt][2] - mn1);
            s[nt][3] = __expf(s[nt][3] - mn1);
            sum0 += s[nt][0] + s[nt][1];
            sum1 += s[nt][2] + s[nt][3];
        }
        sum0 += __shfl_xor_sync(0xffffffffu, sum0, 1);
        sum0 += __shfl_xor_sync(0xffffffffu, sum0, 2);
        sum1 += __shfl_xor_sync(0xffffffffu, sum1, 1);
        sum1 += __shfl_xor_sync(0xffffffffu, sum1, 2);

        lreg[0] = lreg[0]*al0 + sum0;  mreg[0] = mn0;
        lreg[1] = lreg[1]*al1 + sum1;  mreg[1] = mn1;

        #pragma unroll
        for (int nt = 0; nt < 8; nt++) {
            o[nt][0] *= al0; o[nt][1] *= al0;
            o[nt][2] *= al1; o[nt][3] *= al1;
        }

        #pragma unroll
        for (int nt = 0; nt < 8; nt++) {
            int c = nt*8 + 2*j4;
            Ps[prow*FAT_STR + c]       = f2tf(s[nt][0]);
            Ps[prow*FAT_STR + c + 1]   = f2tf(s[nt][1]);
            Ps[(prow+8)*FAT_STR + c]   = f2tf(s[nt][2]);
            Ps[(prow+8)*FAT_STR + c+1] = f2tf(s[nt][3]);
        }
        __syncwarp();

        #pragma unroll
        for (int ks = 0; ks < 8; ks++) {
            int k = ks*8 + j4;
            uint32_t a[4];
            a[0] = Ps[prow*FAT_STR + k];
            a[1] = Ps[(prow+8)*FAT_STR + k];
            a[2] = Ps[prow*FAT_STR + k + 4];
            a[3] = Ps[(prow+8)*FAT_STR + k + 4];
            #pragma unroll
            for (int nt = 0; nt < 8; nt++) {
                uint32_t bf[2];
                bf[0] = Vs[(ks*8 + j4)*FAT_STR + nt*8 + r4];
                bf[1] = Vs[(ks*8 + j4 + 4)*FAT_STR + nt*8 + r4];
                mma_tf32(o[nt], a, bf);
            }
        }
    }

    float inv0 = 1.0f / lreg[0];
    float inv1 = 1.0f / lreg[1];
    int gr0 = q0 + prow;
    int gr1 = gr0 + 8;
    #pragma unroll
    for (int nt = 0; nt < 8; nt++) {
        int c = nt*8 + 2*j4;
        *(float2*)&ctx[((size_t)(b*Sq + gr0)*Hh + h)*DHd + c] =
            make_float2(tf32r(o[nt][0]*inv0), tf32r(o[nt][1]*inv0));
        *(float2*)&ctx[((size_t)(b*Sq + gr1)*Hh + h)*DHd + c] =
            make_float2(tf32r(o[nt][2]*inv1), tf32r(o[nt][3]*inv1));
    }
}

// ---------------------------------------------------------------------------
// Launch
// ---------------------------------------------------------------------------
extern "C" void kernel_launch(void* const* d_in, const int* in_sizes, int n_in,
                              void* d_out, int out_size)
{
    (void)in_sizes; (void)n_in; (void)out_size;
    const float* x     = (const float*)d_in[0];
    const float* ln1_w = (const float*)d_in[1];
    const float* ln1_b = (const float*)d_in[2];
    const float* ln2_w = (const float*)d_in[3];
    const float* ln2_b = (const float*)d_in[4];
    const float* Wq    = (const float*)d_in[5];
    const float* bq    = (const float*)d_in[6];
    const float* Wk    = (const float*)d_in[7];
    const float* bk    = (const float*)d_in[8];
    const float* Wv    = (const float*)d_in[9];
    const float* bv    = (const float*)d_in[10];
    const float* Wo    = (const float*)d_in[11];
    const float* bo    = (const float*)d_in[12];
    const float* fc1_w = (const float*)d_in[13];
    const float* fc1_b = (const float*)d_in[14];
    const float* fc2_w = (const float*)d_in[15];
    const float* fc2_b = (const float*)d_in[16];
    float* out = (float*)d_out;

    float *p_wqkv, *p_bqkv, *p_wo, *p_fc1, *p_fc2;
    float *p_h1, *p_qkv, *p_ctx, *p_y1, *p_h2, *p_a1;
    cudaGetSymbolAddress((void**)&p_wqkv, g_wqkv);
    cudaGetSymbolAddress((void**)&p_bqkv, g_bqkv);
    cudaGetSymbolAddress((void**)&p_wo,   g_wo_r);
    cudaGetSymbolAddress((void**)&p_fc1,  g_fc1_r);
    cudaGetSymbolAddress((void**)&p_fc2,  g_fc2_r);
    cudaGetSymbolAddress((void**)&p_h1,   g_h1);
    cudaGetSymbolAddress((void**)&p_qkv,  g_qkv);
    cudaGetSymbolAddress((void**)&p_ctx,  g_ctx);
    cudaGetSymbolAddress((void**)&p_y1,   g_y1);
    cudaGetSymbolAddress((void**)&p_h2,   g_h2);
    cudaGetSymbolAddress((void**)&p_a1,   g_a1);

    static int fa_attr_set = 0;
    if (!fa_attr_set) {
        cudaFuncSetAttribute(flash_attn_tc,
                             cudaFuncAttributeMaxDynamicSharedMemorySize, (int)FAT_SMEM);
        fa_attr_set = 1;
    }

    // 0. pre-round weights to exact tf32
    round_copy<<<(Dm*Dm + 255)/256, 256>>>(Wo,    p_wo,  Dm*Dm);
    round_copy<<<(Dm*Ff + 255)/256, 256>>>(fc1_w, p_fc1, Dm*Ff);
    round_copy<<<(Ff*Dm + 255)/256, 256>>>(fc2_w, p_fc2, Ff*Dm);

    // 1. repack + round QKV weights/bias
    repack_qkv_kernel<<<(Dm*NQKV + 255)/256, 256>>>(Wq, bq, Wk, bk, Wv, bv);

    // 2. ln1(x) -> h1 (tf32-rounded)
    ln_kernel<<<Mrows/8, 256>>>(x, ln1_w, ln1_b, p_h1);

    // 3. qkv = h1 @ Wqkv + bqkv   [8192, 2304]
    tgemm128<1><<<dim3(NQKV/128, Mrows/128), 256>>>(p_h1, p_wqkv, p_bqkv, nullptr, p_qkv,
                                                    Mrows, NQKV, Dm);

    // 4-6. fused tensor-core attention -> ctx [8192, 768] (tf32-rounded)
    flash_attn_tc<<<dim3(Sq/128, Bsz*Hh), 256, FAT_SMEM>>>(p_qkv, p_ctx);

    // 7. y1 = x + ctx @ Wo + bo  (full fp32)
    tgemm128<1|4><<<dim3(Dm/128, Mrows/128), 256>>>(p_ctx, p_wo, bo, x, p_y1,
                                                    Mrows, Dm, Dm);

    // 8. h2 = ln2(y1) (tf32-rounded)
    ln_kernel<<<Mrows/8, 256>>>(p_y1, ln2_w, ln2_b, p_h2);

    // 9. a1 = gelu(h2 @ fc1_w + fc1_b) (tf32-rounded: feeds FC2)
    tgemm128<1|2|8><<<dim3(Ff/128, Mrows/128), 256>>>(p_h2, p_fc1, fc1_b, nullptr, p_a1,
                                                      Mrows, Ff, Dm);

    // 10. out = y1 + a1 @ fc2_w + fc2_b  (full fp32)
    tgemm128<1|4><<<dim3(Dm/128, Mrows/128), 256>>>(p_a1, p_fc2, fc2_b, p_y1, out,
                                                    Mrows, Dm, Ff);
}

// round 7
// speedup vs baseline: 4.6055x; 1.4672x over previous
#include <cuda_runtime.h>
#include <cuda_fp16.h>
#include <math.h>
#include <stdint.h>

// ---------------------------------------------------------------------------
// Problem dims
// ---------------------------------------------------------------------------
#define Bsz 8
#define Sq  1024
#define Dm  768
#define Hh  12
#define DHd 64
#define Ff  3072
#define Mrows (Bsz*Sq)        // 8192
#define NQKV  (3*Hh*DHd)      // 2304
#define LN_EPS 1e-5f

// ---------------------------------------------------------------------------
// Scratch (static device globals; no runtime allocation)
// ---------------------------------------------------------------------------
__device__ __half g_wqkv_h[(size_t)NQKV*Dm];   // col-major [N][K] half
__device__ float  g_bqkv[NQKV];
__device__ __half g_wo_h[Dm*Dm];               // col-major [N][K]
__device__ __half g_fc1_h[(size_t)Ff*Dm];      // col-major [N=3072][K=768]
__device__ __half g_fc2_h[(size_t)Dm*Ff];      // col-major [N=768][K=3072]
__device__ __half g_h1[(size_t)Mrows*Dm];      // ln1(x) half
__device__ float  g_qkv[(size_t)Mrows*NQKV];   // f32 (consumed by flash)
__device__ __half g_ctx[(size_t)Mrows*Dm];     // [b,s,h,e] half
__device__ float  g_y1[(size_t)Mrows*Dm];      // residual f32
__device__ __half g_h2[(size_t)Mrows*Dm];      // ln2(y1) half
__device__ __half g_a1[(size_t)Mrows*Ff];      // gelu(fc1) half

// ---------------------------------------------------------------------------
// PTX helpers
// ---------------------------------------------------------------------------
__device__ __forceinline__ uint32_t smem_u32(const void* p) {
    return (uint32_t)__cvta_generic_to_shared(p);
}
__device__ __forceinline__ void cp_async16(uint32_t saddr, const void* g) {
    asm volatile("cp.async.cg.shared.global [%0], [%1], 16;" :: "r"(saddr), "l"(g));
}
__device__ __forceinline__ void cp_commit() { asm volatile("cp.async.commit_group;"); }
__device__ __forceinline__ void cp_wait_all() { asm volatile("cp.async.wait_group 0;"); }

__device__ __forceinline__ uint32_t f2tf(float f) {
    uint32_t r; asm("cvt.rna.tf32.f32 %0, %1;" : "=r"(r) : "f"(f)); return r;
}
__device__ __forceinline__ void mma_tf32(float* c, const uint32_t* a, const uint32_t* b) {
    asm volatile("mma.sync.aligned.m16n8k8.row.col.f32.tf32.tf32.f32 "
        "{%0,%1,%2,%3}, {%4,%5,%6,%7}, {%8,%9}, {%0,%1,%2,%3};"
        : "+f"(c[0]), "+f"(c[1]), "+f"(c[2]), "+f"(c[3])
        : "r"(a[0]), "r"(a[1]), "r"(a[2]), "r"(a[3]), "r"(b[0]), "r"(b[1]));
}
__device__ __forceinline__ void mma_f16(float* c, const uint32_t* a, const uint32_t* b) {
    asm volatile("mma.sync.aligned.m16n8k16.row.col.f32.f16.f16.f32 "
        "{%0,%1,%2,%3}, {%4,%5,%6,%7}, {%8,%9}, {%0,%1,%2,%3};"
        : "+f"(c[0]), "+f"(c[1]), "+f"(c[2]), "+f"(c[3])
        : "r"(a[0]), "r"(a[1]), "r"(a[2]), "r"(a[3]), "r"(b[0]), "r"(b[1]));
}

__device__ __forceinline__ float gelu_exact(float v) {
    return 0.5f * v * (1.0f + erff(v * 0.70710678118654752440f));
}

// ---------------------------------------------------------------------------
// Tiled transpose + f32->f16 convert: src [K,N] row-major -> dst [N,K] half
// grid (N/32, K/32), block (32,8)
// ---------------------------------------------------------------------------
__global__ void conv_t(const float* __restrict__ src, __half* __restrict__ dst,
                       int K, int N)
{
    __shared__ float t[32][33];
    int n0 = blockIdx.x * 32, k0 = blockIdx.y * 32;
    int tx = threadIdx.x, ty = threadIdx.y;
    #pragma unroll
    for (int i = 0; i < 32; i += 8)
        t[ty + i][tx] = src[(size_t)(k0 + ty + i) * N + n0 + tx];
    __syncthreads();
    #pragma unroll
    for (int i = 0; i < 32; i += 8)
        dst[(size_t)(n0 + ty + i) * K + k0 + tx] = __float2half(t[tx][ty + i]);
}

// ---------------------------------------------------------------------------
// Repack per-head QKV weights -> col-major half [NQKV][Dm] (+ f32 bias)
// ---------------------------------------------------------------------------
__global__ void repack_qkv_kernel(const float* __restrict__ Wq, const float* __restrict__ bq,
                                  const float* __restrict__ Wk, const float* __restrict__ bk,
                                  const float* __restrict__ Wv, const float* __restrict__ bv)
{
    int idx = blockIdx.x * blockDim.x + threadIdx.x;
    if (idx < Dm * NQKV) {
        int c = idx / Dm;      // output column (n)
        int d = idx % Dm;      // k
        int proj = c / (Hh*DHd);
        int hc   = c % (Hh*DHd);
        int h = hc / DHd;
        int e = hc % DHd;
        const float* W = (proj == 0) ? Wq : (proj == 1) ? Wk : Wv;
        g_wqkv_h[(size_t)c*Dm + d] = __float2half(W[((size_t)h*Dm + d)*DHd + e]);
    }
    if (idx < NQKV) {
        int proj = idx / (Hh*DHd);
        int hc   = idx % (Hh*DHd);
        const float* bb = (proj == 0) ? bq : (proj == 1) ? bk : bv;
        g_bqkv[idx] = bb[hc];
    }
}

// ---------------------------------------------------------------------------
// LayerNorm (768). Warp per row, shfl-only; output half.
// ---------------------------------------------------------------------------
__global__ void __launch_bounds__(256) ln_kernel(const float* __restrict__ x,
                                                 const float* __restrict__ w,
                                                 const float* __restrict__ b,
                                                 __half* __restrict__ out)
{
    int warp = threadIdx.x >> 5;
    int lane = threadIdx.x & 31;
    int row  = blockIdx.x * 8 + warp;
    const float* xr = x + (size_t)row * Dm;
    __half* orow = out + (size_t)row * Dm;

    float4 v[6];
    #pragma unroll
    for (int i = 0; i < 6; i++)
        v[i] = *(const float4*)&xr[(lane + i*32) * 4];

    float s = 0.0f;
    #pragma unroll
    for (int i = 0; i < 6; i++) s += v[i].x + v[i].y + v[i].z + v[i].w;
    #pragma unroll
    for (int o = 16; o > 0; o >>= 1) s += __shfl_xor_sync(0xffffffffu, s, o);
    float mu = s * (1.0f / Dm);

    float vs = 0.0f;
    #pragma unroll
    for (int i = 0; i < 6; i++) {
        float a0 = v[i].x - mu, a1 = v[i].y - mu, a2 = v[i].z - mu, a3 = v[i].w - mu;
        v[i] = make_float4(a0, a1, a2, a3);
        vs += a0*a0 + a1*a1 + a2*a2 + a3*a3;
    }
    #pragma unroll
    for (int o = 16; o > 0; o >>= 1) vs += __shfl_xor_sync(0xffffffffu, vs, o);
    float inv = rsqrtf(vs * (1.0f / Dm) + LN_EPS);

    #pragma unroll
    for (int i = 0; i < 6; i++) {
        int c = (lane + i*32) * 4;
        float4 ww = *(const float4*)&w[c];
        float4 bb = *(const float4*)&b[c];
        __half2 p0 = __floats2half2_rn(v[i].x * inv * ww.x + bb.x,
                                       v[i].y * inv * ww.y + bb.y);
        __half2 p1 = __floats2half2_rn(v[i].z * inv * ww.z + bb.z,
                                       v[i].w * inv * ww.w + bb.w);
        *(__half2*)&orow[c]     = p0;
        *(__half2*)&orow[c + 2] = p1;
    }
}

// ---------------------------------------------------------------------------
// FP16 tensor-core GEMM: C = A[M,K](row,half) * B[N,K](col-major,half),
// 128x128x32 tiles, mma.m16n8k16, f32 accumulate.
// Epilogue flags: 1=bias[n] f32, 2=gelu, 4=residual f32, 16=half output
// Smem: As/Bs stride 40 halves (=20 uint32) -> conflict-free half2 frag reads.
// ---------------------------------------------------------------------------
#define HBM_ 128
#define HBN_ 128
#define HBK_ 32
#define HSTR 40        // halves per row (32 data + 8 pad); 20 uint32

template<int EPI>
__global__ void __launch_bounds__(256) hgemm128(const __half* __restrict__ A,
                                                const __half* __restrict__ Bc,
                                                const float* __restrict__ bias,
                                                const float* __restrict__ res,
                                                void* __restrict__ Cv,
                                                int M, int N, int K)
{
    __shared__ __half As[2][HBM_*HSTR];   // 2*10240 B
    __shared__ __half Bs[2][HBN_*HSTR];   // 2*10240 B

    int tid  = threadIdx.x;
    int lane = tid & 31;
    int wid  = tid >> 5;
    int wm   = wid & 3;
    int wn   = wid >> 2;
    int row0 = blockIdx.y * HBM_;
    int col0 = blockIdx.x * HBN_;

    int lr = tid >> 2;             // 0..63 (row for A, n for B)
    int lc = (tid & 3) << 3;       // half offset 0,8,16,24

    const __half* Ag = A  + (size_t)(row0 + lr) * K + lc;
    const __half* Bg = Bc + (size_t)(col0 + lr) * K + lc;

    float acc[2][8][4];
    #pragma unroll
    for (int mt = 0; mt < 2; mt++)
        #pragma unroll
        for (int nt = 0; nt < 8; nt++)
            #pragma unroll
            for (int q = 0; q < 4; q++) acc[mt][nt][q] = 0.0f;

    int nk = K / HBK_;

    {
        cp_async16(smem_u32(&As[0][lr*HSTR + lc]),        Ag);
        cp_async16(smem_u32(&As[0][(lr+64)*HSTR + lc]),   Ag + (size_t)64*K);
        cp_async16(smem_u32(&Bs[0][lr*HSTR + lc]),        Bg);
        cp_async16(smem_u32(&Bs[0][(lr+64)*HSTR + lc]),   Bg + (size_t)64*K);
        cp_commit();
    }

    int mrow = wm*32 + (lane >> 2);   // a-frag base row
    int j4   = lane & 3;
    int ncol = wn*64 + (lane >> 2);   // b-frag base col

    for (int kt = 0; kt < nk; kt++) {
        cp_wait_all();
        __syncthreads();
        int cur = kt & 1;

        if (kt + 1 < nk) {
            int nxt = cur ^ 1;
            const __half* Agn = Ag + (size_t)(kt+1)*HBK_;
            const __half* Bgn = Bg + (size_t)(kt+1)*HBK_;
            cp_async16(smem_u32(&As[nxt][lr*HSTR + lc]),      Agn);
            cp_async16(smem_u32(&As[nxt][(lr+64)*HSTR + lc]), Agn + (size_t)64*K);
            cp_async16(smem_u32(&Bs[nxt][lr*HSTR + lc]),      Bgn);
            cp_async16(smem_u32(&Bs[nxt][(lr+64)*HSTR + lc]), Bgn + (size_t)64*K);
            cp_commit();
        }

        const uint32_t* Ab = (const uint32_t*)As[cur];   // stride 20 u32/row
        const uint32_t* Bb = (const uint32_t*)Bs[cur];

        #pragma unroll
        for (int ks = 0; ks < 2; ks++) {           // two k16 steps per tile
            int kw = ks*8 + j4;                    // u32 index within row
            uint32_t af[2][4];
            #pragma unroll
            for (int mt = 0; mt < 2; mt++) {
                int r = mrow + mt*16;
                af[mt][0] = Ab[r*20 + kw];
                af[mt][1] = Ab[(r+8)*20 + kw];
                af[mt][2] = Ab[r*20 + kw + 4];
                af[mt][3] = Ab[(r+8)*20 + kw + 4];
            }
            #pragma unroll
            for (int nt = 0; nt < 8; nt++) {
                int c = ncol + nt*8;
                uint32_t bf[2];
                bf[0] = Bb[c*20 + kw];
                bf[1] = Bb[c*20 + kw + 4];
                mma_f16(acc[0][nt], af[0], bf);
                mma_f16(acc[1][nt], af[1], bf);
            }
        }
    }

    #pragma unroll
    for (int mt = 0; mt < 2; mt++) {
        #pragma unroll
        for (int i = 0; i < 2; i++) {
            size_t r = row0 + mrow + mt*16 + i*8;
            #pragma unroll
            for (int nt = 0; nt < 8; nt++) {
                int c = col0 + wn*64 + nt*8 + 2*(lane & 3);
                float v0 = acc[mt][nt][2*i + 0];
                float v1 = acc[mt][nt][2*i + 1];
                if (EPI & 1) { v0 += bias[c]; v1 += bias[c+1]; }
                if (EPI & 2) { v0 = gelu_exact(v0); v1 = gelu_exact(v1); }
                if (EPI & 4) {
                    float2 rr = *(const float2*)&res[r * N + c];
                    v0 += rr.x; v1 += rr.y;
                }
                if (EPI & 16) {
                    *(__half2*)&((__half*)Cv)[r * N + c] = __floats2half2_rn(v0, v1);
                } else {
                    *(float2*)&((float*)Cv)[r * N + c] = make_float2(v0, v1);
                }
            }
        }
    }
}

// ---------------------------------------------------------------------------
// TF32 tensor-core flash attention (unchanged core; ctx stored as half).
// ---------------------------------------------------------------------------
#define FAT_STR 68
#define FAT_SMEM ((2*128*FAT_STR + 2*64*FAT_STR) * 4)   // 104448 B

__global__ void __launch_bounds__(256, 2) flash_attn_tc(const float* __restrict__ qkv,
                                                        __half* __restrict__ ctx)
{
    extern __shared__ uint32_t usm[];
    uint32_t* Qs = usm;                  // [128][68]
    uint32_t* Ps = Qs + 128*FAT_STR;     // [128][68]
    uint32_t* Ks = Ps + 128*FAT_STR;     // [64][68]
    uint32_t* Vs = Ks + 64*FAT_STR;      // [64][68]

    int bh = blockIdx.y;
    int b = bh / Hh, h = bh % Hh;
    int q0 = blockIdx.x * 128;
    int tid = threadIdx.x;
    int lane = tid & 31;
    int w = tid >> 5;
    int r4 = lane >> 2;
    int j4 = lane & 3;

    const float* qbase = qkv + (size_t)(b*Sq)*NQKV + h*DHd;
    const float* kbase = qbase + Hh*DHd;
    const float* vbase = qbase + 2*Hh*DHd;

    for (int i = tid; i < 128*16; i += 256) {
        int r = i >> 4, c = (i & 15) * 4;
        float4 q = *(const float4*)&qbase[(size_t)(q0 + r)*NQKV + c];
        Qs[r*FAT_STR + c + 0] = f2tf(q.x * 0.125f);
        Qs[r*FAT_STR + c + 1] = f2tf(q.y * 0.125f);
        Qs[r*FAT_STR + c + 2] = f2tf(q.z * 0.125f);
        Qs[r*FAT_STR + c + 3] = f2tf(q.w * 0.125f);
    }

    float o[8][4];
    #pragma unroll
    for (int nt = 0; nt < 8; nt++)
        #pragma unroll
        for (int q = 0; q < 4; q++) o[nt][q] = 0.0f;
    float mreg[2] = {-INFINITY, -INFINITY};
    float lreg[2] = {0.0f, 0.0f};

    int prow = w*16 + r4;

    for (int kt = 0; kt < Sq/64; kt++) {
        __syncthreads();
        for (int i = tid; i < 64*16; i += 256) {
            int r = i >> 4, c = (i & 15) * 4;
            float4 kk = *(const float4*)&kbase[(size_t)(kt*64 + r)*NQKV + c];
            float4 vv = *(const float4*)&vbase[(size_t)(kt*64 + r)*NQKV + c];
            Ks[r*FAT_STR + c + 0] = f2tf(kk.x);
            Ks[r*FAT_STR + c + 1] = f2tf(kk.y);
            Ks[r*FAT_STR + c + 2] = f2tf(kk.z);
            Ks[r*FAT_STR + c + 3] = f2tf(kk.w);
            Vs[r*FAT_STR + c + 0] = f2tf(vv.x);
            Vs[r*FAT_STR + c + 1] = f2tf(vv.y);
            Vs[r*FAT_STR + c + 2] = f2tf(vv.z);
            Vs[r*FAT_STR + c + 3] = f2tf(vv.w);
        }
        __syncthreads();

        float s[8][4];
        #pragma unroll
        for (int nt = 0; nt < 8; nt++)
            #pragma unroll
            for (int q = 0; q < 4; q++) s[nt][q] = 0.0f;

        #pragma unroll
        for (int ks = 0; ks < 8; ks++) {
            int k = ks*8 + j4;
            uint32_t a[4];
            a[0] = Qs[prow*FAT_STR + k];
            a[1] = Qs[(prow+8)*FAT_STR + k];
            a[2] = Qs[prow*FAT_STR + k + 4];
            a[3] = Qs[(prow+8)*FAT_STR + k + 4];
            #pragma unroll
            for (int nt = 0; nt < 8; nt++) {
                uint32_t bf[2];
                bf[0] = Ks[(nt*8 + r4)*FAT_STR + k];
                bf[1] = Ks[(nt*8 + r4)*FAT_STR + k + 4];
                mma_tf32(s[nt], a, bf);
            }
        }

        float mx0 = -INFINITY, mx1 = -INFINITY;
        #pragma unroll
        for (int nt = 0; nt < 8; nt++) {
            mx0 = fmaxf(mx0, fmaxf(s[nt][0], s[nt][1]));
            mx1 = fmaxf(mx1, fmaxf(s[nt][2], s[nt][3]));
        }
        mx0 = fmaxf(mx0, __shfl_xor_sync(0xffffffffu, mx0, 1));
        mx0 = fmaxf(mx0, __shfl_xor_sync(0xffffffffu, mx0, 2));
        mx1 = fmaxf(mx1, __shfl_xor_sync(0xffffffffu, mx1, 1));
        mx1 = fmaxf(mx1, __shfl_xor_sync(0xffffffffu, mx1, 2));

        float mn0 = fmaxf(mreg[0], mx0);
        float mn1 = fmaxf(mreg[1], mx1);
        float al0 = __expf(mreg[0] - mn0);
        float al1 = __expf(mreg[1] - mn1);

        float sum0 = 0.0f, sum1 = 0.0f;
        #pragma unroll
        for (int nt = 0; nt < 8; nt++) {
            s[nt][0] = __expf(s[nt][0] - mn0);
            s[nt][1] = __expf(s[nt][1] - mn0);
            s[nt][2] = __expf(s[nt][2] - mn1);
            s[nt][3] = __expf(s[nt][3] - mn1);
            sum0 += s[nt][0] + s[nt][1];
            sum1 += s[nt][2] + s[nt][3];
        }
        sum0 += __shfl_xor_sync(0xffffffffu, sum0, 1);
        sum0 += __shfl_xor_sync(0xffffffffu, sum0, 2);
        sum1 += __shfl_xor_sync(0xffffffffu, sum1, 1);
        sum1 += __shfl_xor_sync(0xffffffffu, sum1, 2);

        lreg[0] = lreg[0]*al0 + sum0;  mreg[0] = mn0;
        lreg[1] = lreg[1]*al1 + sum1;  mreg[1] = mn1;

        #pragma unroll
        for (int nt = 0; nt < 8; nt++) {
            o[nt][0] *= al0; o[nt][1] *= al0;
            o[nt][2] *= al1; o[nt][3] *= al1;
        }

        #pragma unroll
        for (int nt = 0; nt < 8; nt++) {
            int c = nt*8 + 2*j4;
            Ps[prow*FAT_STR + c]       = f2tf(s[nt][0]);
            Ps[prow*FAT_STR + c + 1]   = f2tf(s[nt][1]);
            Ps[(prow+8)*FAT_STR + c]   = f2tf(s[nt][2]);
            Ps[(prow+8)*FAT_STR + c+1] = f2tf(s[nt][3]);
        }
        __syncwarp();

        #pragma unroll
        for (int ks = 0; ks < 8; ks++) {
            int k = ks*8 + j4;
            uint32_t a[4];
            a[0] = Ps[prow*FAT_STR + k];
            a[1] = Ps[(prow+8)*FAT_STR + k];
            a[2] = Ps[prow*FAT_STR + k + 4];
            a[3] = Ps[(prow+8)*FAT_STR + k + 4];
            #pragma unroll
            for (int nt = 0; nt < 8; nt++) {
                uint32_t bf[2];
                bf[0] = Vs[(ks*8 + j4)*FAT_STR + nt*8 + r4];
                bf[1] = Vs[(ks*8 + j4 + 4)*FAT_STR + nt*8 + r4];
                mma_tf32(o[nt], a, bf);
            }
        }
    }

    float inv0 = 1.0f / lreg[0];
    float inv1 = 1.0f / lreg[1];
    int gr0 = q0 + prow;
    int gr1 = gr0 + 8;
    #pragma unroll
    for (int nt = 0; nt < 8; nt++) {
        int c = nt*8 + 2*j4;
        *(__half2*)&ctx[((size_t)(b*Sq + gr0)*Hh + h)*DHd + c] =
            __floats2half2_rn(o[nt][0]*inv0, o[nt][1]*inv0);
        *(__half2*)&ctx[((size_t)(b*Sq + gr1)*Hh + h)*DHd + c] =
            __floats2half2_rn(o[nt][2]*inv1, o[nt][3]*inv1);
    }
}

// ---------------------------------------------------------------------------
// Launch
// ---------------------------------------------------------------------------
extern "C" void kernel_launch(void* const* d_in, const int* in_sizes, int n_in,
                              void* d_out, int out_size)
{
    (void)in_sizes; (void)n_in; (void)out_size;
    const float* x     = (const float*)d_in[0];
    const float* ln1_w = (const float*)d_in[1];
    const float* ln1_b = (const float*)d_in[2];
    const float* ln2_w = (const float*)d_in[3];
    const float* ln2_b = (const float*)d_in[4];
    const float* Wq    = (const float*)d_in[5];
    const float* bq    = (const float*)d_in[6];
    const float* Wk    = (const float*)d_in[7];
    const float* bk    = (const float*)d_in[8];
    const float* Wv    = (const float*)d_in[9];
    const float* bv    = (const float*)d_in[10];
    const float* Wo    = (const float*)d_in[11];
    const float* bo    = (const float*)d_in[12];
    const float* fc1_w = (const float*)d_in[13];
    const float* fc1_b = (const float*)d_in[14];
    const float* fc2_w = (const float*)d_in[15];
    const float* fc2_b = (const float*)d_in[16];
    float* out = (float*)d_out;

    __half *p_wqkv, *p_wo, *p_fc1, *p_fc2, *p_h1, *p_ctx, *p_h2, *p_a1;
    float *p_bqkv, *p_qkv, *p_y1;
    cudaGetSymbolAddress((void**)&p_wqkv, g_wqkv_h);
    cudaGetSymbolAddress((void**)&p_bqkv, g_bqkv);
    cudaGetSymbolAddress((void**)&p_wo,   g_wo_h);
    cudaGetSymbolAddress((void**)&p_fc1,  g_fc1_h);
    cudaGetSymbolAddress((void**)&p_fc2,  g_fc2_h);
    cudaGetSymbolAddress((void**)&p_h1,   g_h1);
    cudaGetSymbolAddress((void**)&p_qkv,  g_qkv);
    cudaGetSymbolAddress((void**)&p_ctx,  g_ctx);
    cudaGetSymbolAddress((void**)&p_y1,   g_y1);
    cudaGetSymbolAddress((void**)&p_h2,   g_h2);
    cudaGetSymbolAddress((void**)&p_a1,   g_a1);

    static int fa_attr_set = 0;
    if (!fa_attr_set) {
        cudaFuncSetAttribute(flash_attn_tc,
                             cudaFuncAttributeMaxDynamicSharedMemorySize, (int)FAT_SMEM);
        fa_attr_set = 1;
    }

    // 0. weight conversion: transpose to col-major half
    conv_t<<<dim3(Dm/32, Dm/32), dim3(32,8)>>>(Wo,    p_wo,  Dm, Dm);
    conv_t<<<dim3(Ff/32, Dm/32), dim3(32,8)>>>(fc1_w, p_fc1, Dm, Ff);
    conv_t<<<dim3(Dm/32, Ff/32), dim3(32,8)>>>(fc2_w, p_fc2, Ff, Dm);

    // 1. repack QKV weights (col-major half) + bias
    repack_qkv_kernel<<<(Dm*NQKV + 255)/256, 256>>>(Wq, bq, Wk, bk, Wv, bv);

    // 2. ln1(x) -> h1 (half)
    ln_kernel<<<Mrows/8, 256>>>(x, ln1_w, ln1_b, p_h1);

    // 3. qkv = h1 @ Wqkv + bqkv   [8192, 2304] f32
    hgemm128<1><<<dim3(NQKV/128, Mrows/128), 256>>>(p_h1, p_wqkv, p_bqkv, nullptr,
                                                    (void*)p_qkv, Mrows, NQKV, Dm);

    // 4-6. fused tensor-core attention -> ctx [8192, 768] half
    flash_attn_tc<<<dim3(Sq/128, Bsz*Hh), 256, FAT_SMEM>>>(p_qkv, p_ctx);

    // 7. y1 = x + ctx @ Wo + bo  (f32)
    hgemm128<1|4><<<dim3(Dm/128, Mrows/128), 256>>>(p_ctx, p_wo, bo, x,
                                                    (void*)p_y1, Mrows, Dm, Dm);

    // 8. h2 = ln2(y1) (half)
    ln_kernel<<<Mrows/8, 256>>>(p_y1, ln2_w, ln2_b, p_h2);

    // 9. a1 = gelu(h2 @ fc1_w + fc1_b) (half)
    hgemm128<1|2|16><<<dim3(Ff/128, Mrows/128), 256>>>(p_h2, p_fc1, fc1_b, nullptr,
                                                       (void*)p_a1, Mrows, Ff, Dm);

    // 10. out = y1 + a1 @ fc2_w + fc2_b  (f32)
    hgemm128<1|4><<<dim3(Dm/128, Mrows/128), 256>>>(p_a1, p_fc2, fc2_b, p_y1,
                                                    (void*)out, Mrows, Dm, Ff);
}

// round 9
// speedup vs baseline: 5.6771x; 1.2327x over previous
#include <cuda_runtime.h>
#include <cuda_fp16.h>
#include <math.h>
#include <stdint.h>

// ---------------------------------------------------------------------------
// Problem dims
// ---------------------------------------------------------------------------
#define Bsz 8
#define Sq  1024
#define Dm  768
#define Hh  12
#define DHd 64
#define Ff  3072
#define Mrows (Bsz*Sq)        // 8192
#define NQKV  (3*Hh*DHd)      // 2304
#define LN_EPS 1e-5f

// ---------------------------------------------------------------------------
// Scratch (static device globals; no runtime allocation)
// ---------------------------------------------------------------------------
__device__ __half g_wqkv_h[(size_t)NQKV*Dm];   // col-major [N][K]; Wq part pre-scaled by 1/8
__device__ float  g_bqkv[NQKV];                // bq part pre-scaled by 1/8
__device__ __half g_wo_h[Dm*Dm];               // col-major [N][K]
__device__ __half g_fc1_h[(size_t)Ff*Dm];      // col-major
__device__ __half g_fc2_h[(size_t)Dm*Ff];      // col-major
__device__ __half g_h1[(size_t)Mrows*Dm];      // ln1(x) half
__device__ __half g_qkv[(size_t)Mrows*NQKV];   // half (q pre-scaled by 1/8)
__device__ __half g_ctx[(size_t)Mrows*Dm];     // [b,s,h,e] half
__device__ float  g_y1[(size_t)Mrows*Dm];      // residual f32
__device__ __half g_h2[(size_t)Mrows*Dm];      // ln2(y1) half
__device__ __half g_a1[(size_t)Mrows*Ff];      // gelu(fc1) half

// ---------------------------------------------------------------------------
// PTX helpers
// ---------------------------------------------------------------------------
__device__ __forceinline__ uint32_t smem_u32(const void* p) {
    return (uint32_t)__cvta_generic_to_shared(p);
}
__device__ __forceinline__ void cp_async16(uint32_t saddr, const void* g) {
    asm volatile("cp.async.cg.shared.global [%0], [%1], 16;" :: "r"(saddr), "l"(g));
}
__device__ __forceinline__ void cp_commit() { asm volatile("cp.async.commit_group;"); }
__device__ __forceinline__ void cp_wait_all() { asm volatile("cp.async.wait_group 0;"); }

__device__ __forceinline__ void mma_f16(float* c, const uint32_t* a, const uint32_t* b) {
    asm volatile("mma.sync.aligned.m16n8k16.row.col.f32.f16.f16.f32 "
        "{%0,%1,%2,%3}, {%4,%5,%6,%7}, {%8,%9}, {%0,%1,%2,%3};"
        : "+f"(c[0]), "+f"(c[1]), "+f"(c[2]), "+f"(c[3])
        : "r"(a[0]), "r"(a[1]), "r"(a[2]), "r"(a[3]), "r"(b[0]), "r"(b[1]));
}

__device__ __forceinline__ float gelu_exact(float v) {
    return 0.5f * v * (1.0f + erff(v * 0.70710678118654752440f));
}
__device__ __forceinline__ uint32_t pack_h2(float lo, float hi) {
    __half2 h = __floats2half2_rn(lo, hi);
    return *(uint32_t*)&h;
}

// ---------------------------------------------------------------------------
// Tiled transpose + f32->f16: src [K,N] row-major -> dst [N,K] half
// ---------------------------------------------------------------------------
__global__ void conv_t(const float* __restrict__ src, __half* __restrict__ dst,
                       int K, int N)
{
    __shared__ float t[32][33];
    int n0 = blockIdx.x * 32, k0 = blockIdx.y * 32;
    int tx = threadIdx.x, ty = threadIdx.y;
    #pragma unroll
    for (int i = 0; i < 32; i += 8)
        t[ty + i][tx] = src[(size_t)(k0 + ty + i) * N + n0 + tx];
    __syncthreads();
    #pragma unroll
    for (int i = 0; i < 32; i += 8)
        dst[(size_t)(n0 + ty + i) * K + k0 + tx] = __float2half(t[tx][ty + i]);
}

// ---------------------------------------------------------------------------
// Repack per-head QKV weights -> col-major half [NQKV][Dm] (+ f32 bias).
// Q projection (and bias) pre-scaled by 1/8 (exact power of two).
// ---------------------------------------------------------------------------
__global__ void repack_qkv_kernel(const float* __restrict__ Wq, const float* __restrict__ bq,
                                  const float* __restrict__ Wk, const float* __restrict__ bk,
                                  const float* __restrict__ Wv, const float* __restrict__ bv)
{
    int idx = blockIdx.x * blockDim.x + threadIdx.x;
    if (idx < Dm * NQKV) {
        int c = idx / Dm;      // output column (n)
        int d = idx % Dm;      // k
        int proj = c / (Hh*DHd);
        int hc   = c % (Hh*DHd);
        int h = hc / DHd;
        int e = hc % DHd;
        const float* W = (proj == 0) ? Wq : (proj == 1) ? Wk : Wv;
        float v = W[((size_t)h*Dm + d)*DHd + e];
        if (proj == 0) v *= 0.125f;
        g_wqkv_h[(size_t)c*Dm + d] = __float2half(v);
    }
    if (idx < NQKV) {
        int proj = idx / (Hh*DHd);
        int hc   = idx % (Hh*DHd);
        const float* bb = (proj == 0) ? bq : (proj == 1) ? bk : bv;
        g_bqkv[idx] = (proj == 0) ? bb[hc] * 0.125f : bb[hc];
    }
}

// ---------------------------------------------------------------------------
// LayerNorm (768). Warp per row, shfl-only; output half.
// ---------------------------------------------------------------------------
__global__ void __launch_bounds__(256) ln_kernel(const float* __restrict__ x,
                                                 const float* __restrict__ w,
                                                 const float* __restrict__ b,
                                                 __half* __restrict__ out)
{
    int warp = threadIdx.x >> 5;
    int lane = threadIdx.x & 31;
    int row  = blockIdx.x * 8 + warp;
    const float* xr = x + (size_t)row * Dm;
    __half* orow = out + (size_t)row * Dm;

    float4 v[6];
    #pragma unroll
    for (int i = 0; i < 6; i++)
        v[i] = *(const float4*)&xr[(lane + i*32) * 4];

    float s = 0.0f;
    #pragma unroll
    for (int i = 0; i < 6; i++) s += v[i].x + v[i].y + v[i].z + v[i].w;
    #pragma unroll
    for (int o = 16; o > 0; o >>= 1) s += __shfl_xor_sync(0xffffffffu, s, o);
    float mu = s * (1.0f / Dm);

    float vs = 0.0f;
    #pragma unroll
    for (int i = 0; i < 6; i++) {
        float a0 = v[i].x - mu, a1 = v[i].y - mu, a2 = v[i].z - mu, a3 = v[i].w - mu;
        v[i] = make_float4(a0, a1, a2, a3);
        vs += a0*a0 + a1*a1 + a2*a2 + a3*a3;
    }
    #pragma unroll
    for (int o = 16; o > 0; o >>= 1) vs += __shfl_xor_sync(0xffffffffu, vs, o);
    float inv = rsqrtf(vs * (1.0f / Dm) + LN_EPS);

    #pragma unroll
    for (int i = 0; i < 6; i++) {
        int c = (lane + i*32) * 4;
        float4 ww = *(const float4*)&w[c];
        float4 bb = *(const float4*)&b[c];
        *(__half2*)&orow[c]     = __floats2half2_rn(v[i].x * inv * ww.x + bb.x,
                                                    v[i].y * inv * ww.y + bb.y);
        *(__half2*)&orow[c + 2] = __floats2half2_rn(v[i].z * inv * ww.z + bb.z,
                                                    v[i].w * inv * ww.w + bb.w);
    }
}

// ---------------------------------------------------------------------------
// FP16 tensor-core GEMM (validated): C = A[M,K](row,half) * B[N,K](col,half)
// 128x128x32 tiles, mma.m16n8k16, f32 accumulate.
// Epilogue flags: 1=bias f32, 2=gelu, 4=residual f32, 16=half output
// ---------------------------------------------------------------------------
#define HSTR 40        // halves per smem row (20 uint32)

template<int EPI>
__global__ void __launch_bounds__(256) hgemm128(const __half* __restrict__ A,
                                                const __half* __restrict__ Bc,
                                                const float* __restrict__ bias,
                                                const float* __restrict__ res,
                                                void* __restrict__ Cv,
                                                int M, int N, int K)
{
    __shared__ __half As[2][128*HSTR];
    __shared__ __half Bs[2][128*HSTR];

    int tid  = threadIdx.x;
    int lane = tid & 31;
    int wid  = tid >> 5;
    int wm   = wid & 3;
    int wn   = wid >> 2;
    int row0 = blockIdx.y * 128;
    int col0 = blockIdx.x * 128;

    int lr = tid >> 2;
    int lc = (tid & 3) << 3;

    const __half* Ag = A  + (size_t)(row0 + lr) * K + lc;
    const __half* Bg = Bc + (size_t)(col0 + lr) * K + lc;

    float acc[2][8][4];
    #pragma unroll
    for (int mt = 0; mt < 2; mt++)
        #pragma unroll
        for (int nt = 0; nt < 8; nt++)
            #pragma unroll
            for (int q = 0; q < 4; q++) acc[mt][nt][q] = 0.0f;

    int nk = K / 32;

    {
        cp_async16(smem_u32(&As[0][lr*HSTR + lc]),        Ag);
        cp_async16(smem_u32(&As[0][(lr+64)*HSTR + lc]),   Ag + (size_t)64*K);
        cp_async16(smem_u32(&Bs[0][lr*HSTR + lc]),        Bg);
        cp_async16(smem_u32(&Bs[0][(lr+64)*HSTR + lc]),   Bg + (size_t)64*K);
        cp_commit();
    }

    int mrow = wm*32 + (lane >> 2);
    int j4   = lane & 3;
    int ncol = wn*64 + (lane >> 2);

    for (int kt = 0; kt < nk; kt++) {
        cp_wait_all();
        __syncthreads();
        int cur = kt & 1;

        if (kt + 1 < nk) {
            int nxt = cur ^ 1;
            const __half* Agn = Ag + (size_t)(kt+1)*32;
            const __half* Bgn = Bg + (size_t)(kt+1)*32;
            cp_async16(smem_u32(&As[nxt][lr*HSTR + lc]),      Agn);
            cp_async16(smem_u32(&As[nxt][(lr+64)*HSTR + lc]), Agn + (size_t)64*K);
            cp_async16(smem_u32(&Bs[nxt][lr*HSTR + lc]),      Bgn);
            cp_async16(smem_u32(&Bs[nxt][(lr+64)*HSTR + lc]), Bgn + (size_t)64*K);
            cp_commit();
        }

        const uint32_t* Ab = (const uint32_t*)As[cur];
        const uint32_t* Bb = (const uint32_t*)Bs[cur];

        #pragma unroll
        for (int ks = 0; ks < 2; ks++) {
            int kw = ks*8 + j4;
            uint32_t af[2][4];
            #pragma unroll
            for (int mt = 0; mt < 2; mt++) {
                int r = mrow + mt*16;
                af[mt][0] = Ab[r*20 + kw];
                af[mt][1] = Ab[(r+8)*20 + kw];
                af[mt][2] = Ab[r*20 + kw + 4];
                af[mt][3] = Ab[(r+8)*20 + kw + 4];
            }
            #pragma unroll
            for (int nt = 0; nt < 8; nt++) {
                int c = ncol + nt*8;
                uint32_t bf[2];
                bf[0] = Bb[c*20 + kw];
                bf[1] = Bb[c*20 + kw + 4];
                mma_f16(acc[0][nt], af[0], bf);
                mma_f16(acc[1][nt], af[1], bf);
            }
        }
    }

    #pragma unroll
    for (int mt = 0; mt < 2; mt++) {
        #pragma unroll
        for (int i = 0; i < 2; i++) {
            size_t r = row0 + mrow + mt*16 + i*8;
            #pragma unroll
            for (int nt = 0; nt < 8; nt++) {
                int c = col0 + wn*64 + nt*8 + 2*(lane & 3);
                float v0 = acc[mt][nt][2*i + 0];
                float v1 = acc[mt][nt][2*i + 1];
                if (EPI & 1) { v0 += bias[c]; v1 += bias[c+1]; }
                if (EPI & 2) { v0 = gelu_exact(v0); v1 = gelu_exact(v1); }
                if (EPI & 4) {
                    float2 rr = *(const float2*)&res[r * N + c];
                    v0 += rr.x; v1 += rr.y;
                }
                if (EPI & 16) {
                    *(__half2*)&((__half*)Cv)[r * N + c] = __floats2half2_rn(v0, v1);
                } else {
                    *(float2*)&((float*)Cv)[r * N + c] = make_float2(v0, v1);
                }
            }
        }
    }
}

// ---------------------------------------------------------------------------
// FP16 tensor-core flash attention. q-tile 128, kv-tile 64, 8 warps.
// Q (pre-scaled 1/8 upstream) and K staged via cp.async in native layout;
// V transposed on load into token-pair-packed half2 words; P packed to half2
// in C-fragment layout. All mma are m16n8k16 f16 with f32 accumulate.
// Smem u32 stride 36 per row (32 data + 4 pad) — conflict-free everywhere.
// ---------------------------------------------------------------------------
#define FSTR 36
#define FAH_SMEM ((128*FSTR + 128*FSTR + 64*FSTR + 64*FSTR) * 4)   // 55296 B

__global__ void __launch_bounds__(256, 2) flash_attn_h16(const __half* __restrict__ qkv,
                                                         __half* __restrict__ ctx)
{
    extern __shared__ uint32_t usm[];
    uint32_t* Qs = usm;                 // [128][36] u32 (= 64 halves + pad)
    uint32_t* Ps = Qs + 128*FSTR;       // [128][36]
    uint32_t* Ks = Ps + 128*FSTR;       // [64][36]
    uint32_t* Vs = Ks + 64*FSTR;        // [64 e][36] token-pair words

    int bh = blockIdx.y;
    int b = bh / Hh, h = bh % Hh;
    int q0 = blockIdx.x * 128;
    int tid = threadIdx.x;
    int lane = tid & 31;
    int w = tid >> 5;
    int r4 = lane >> 2;
    int j4 = lane & 3;

    const __half* qbase = qkv + (size_t)(b*Sq)*NQKV + h*DHd;
    const __half* kbase = qbase + Hh*DHd;
    const __half* vbase = qbase + 2*Hh*DHd;

    // stage Q tile: 128 rows x 64 halves = 8 x 16B per row
    #pragma unroll
    for (int i = tid; i < 128*8; i += 256) {
        int r = i >> 3, seg = i & 7;
        cp_async16(smem_u32(&Qs[r*FSTR + seg*4]),
                   qbase + (size_t)(q0 + r)*NQKV + seg*8);
    }
    cp_commit();

    float o[8][4];
    #pragma unroll
    for (int nt = 0; nt < 8; nt++)
        #pragma unroll
        for (int q = 0; q < 4; q++) o[nt][q] = 0.0f;
    float mreg[2] = {-INFINITY, -INFINITY};
    float lreg[2] = {0.0f, 0.0f};

    int prow = w*16 + r4;

    for (int kt = 0; kt < Sq/64; kt++) {
        __syncthreads();   // prior tile's Ks/Vs reads done

        // K tile via cp.async (native [token][e] = col-major B)
        #pragma unroll
        for (int i = tid; i < 64*8; i += 256) {
            int r = i >> 3, seg = i & 7;
            cp_async16(smem_u32(&Ks[r*FSTR + seg*4]),
                       kbase + (size_t)(kt*64 + r)*NQKV + seg*8);
        }
        cp_commit();

        // V tile transposed: word (e, tp) = half2(V[2tp][e], V[2tp+1][e])
        {
            int tp = tid & 31;          // token pair 0..31
            int eg = tid >> 5;          // 0..7 -> e base eg*8
            const __half* v0p = vbase + (size_t)(kt*64 + 2*tp)*NQKV + eg*8;
            uint4 x0 = *(const uint4*)v0p;
            uint4 x1 = *(const uint4*)(v0p + NQKV);
            const unsigned short* h0 = (const unsigned short*)&x0;
            const unsigned short* h1 = (const unsigned short*)&x1;
            #pragma unroll
            for (int j = 0; j < 8; j++)
                Vs[(eg*8 + j)*FSTR + tp] = (uint32_t)h0[j] | ((uint32_t)h1[j] << 16);
        }
        cp_wait_all();     // K (and Q on first iter) landed
        __syncthreads();

        // S = Q K^T : 4 k16 steps over e=64
        float s[8][4];
        #pragma unroll
        for (int nt = 0; nt < 8; nt++)
            #pragma unroll
            for (int q = 0; q < 4; q++) s[nt][q] = 0.0f;

        #pragma unroll
        for (int ks = 0; ks < 4; ks++) {
            int kw = ks*8 + j4;
            uint32_t a[4];
            a[0] = Qs[prow*FSTR + kw];
            a[1] = Qs[(prow+8)*FSTR + kw];
            a[2] = Qs[prow*FSTR + kw + 4];
            a[3] = Qs[(prow+8)*FSTR + kw + 4];
            #pragma unroll
            for (int nt = 0; nt < 8; nt++) {
                int c = nt*8 + r4;
                uint32_t bf[2];
                bf[0] = Ks[c*FSTR + kw];
                bf[1] = Ks[c*FSTR + kw + 4];
                mma_f16(s[nt], a, bf);
            }
        }

        // online softmax (rows prow, prow+8), quad reductions
        float mx0 = -INFINITY, mx1 = -INFINITY;
        #pragma unroll
        for (int nt = 0; nt < 8; nt++) {
            mx0 = fmaxf(mx0, fmaxf(s[nt][0], s[nt][1]));
            mx1 = fmaxf(mx1, fmaxf(s[nt][2], s[nt][3]));
        }
        mx0 = fmaxf(mx0, __shfl_xor_sync(0xffffffffu, mx0, 1));
        mx0 = fmaxf(mx0, __shfl_xor_sync(0xffffffffu, mx0, 2));
        mx1 = fmaxf(mx1, __shfl_xor_sync(0xffffffffu, mx1, 1));
        mx1 = fmaxf(mx1, __shfl_xor_sync(0xffffffffu, mx1, 2));

        float mn0 = fmaxf(mreg[0], mx0);
        float mn1 = fmaxf(mreg[1], mx1);
        float al0 = __expf(mreg[0] - mn0);
        float al1 = __expf(mreg[1] - mn1);

        float sum0 = 0.0f, sum1 = 0.0f;
        #pragma unroll
        for (int nt = 0; nt < 8; nt++) {
            s[nt][0] = __expf(s[nt][0] - mn0);
            s[nt][1] = __expf(s[nt][1] - mn0);
            s[nt][2] = __expf(s[nt][2] - mn1);
            s[nt][3] = __expf(s[nt][3] - mn1);
            sum0 += s[nt][0] + s[nt][1];
            sum1 += s[nt][2] + s[nt][3];
        }
        sum0 += __shfl_xor_sync(0xffffffffu, sum0, 1);
        sum0 += __shfl_xor_sync(0xffffffffu, sum0, 2);
        sum1 += __shfl_xor_sync(0xffffffffu, sum1, 1);
        sum1 += __shfl_xor_sync(0xffffffffu, sum1, 2);

        lreg[0] = lreg[0]*al0 + sum0;  mreg[0] = mn0;
        lreg[1] = lreg[1]*al1 + sum1;  mreg[1] = mn1;

        #pragma unroll
        for (int nt = 0; nt < 8; nt++) {
            o[nt][0] *= al0; o[nt][1] *= al0;
            o[nt][2] *= al1; o[nt][3] *= al1;
        }

        // P -> half2 words in A-frag-compatible layout (own rows only)
        #pragma unroll
        for (int nt = 0; nt < 8; nt++) {
            Ps[prow*FSTR + nt*4 + j4]     = pack_h2(s[nt][0], s[nt][1]);
            Ps[(prow+8)*FSTR + nt*4 + j4] = pack_h2(s[nt][2], s[nt][3]);
        }
        __syncwarp();

        // O += P V : 4 k16 steps over 64 tokens
        #pragma unroll
        for (int ks = 0; ks < 4; ks++) {
            int kw = ks*8 + j4;
            uint32_t a[4];
            a[0] = Ps[prow*FSTR + kw];
            a[1] = Ps[(prow+8)*FSTR + kw];
            a[2] = Ps[prow*FSTR + kw + 4];
            a[3] = Ps[(prow+8)*FSTR + kw + 4];
            #pragma unroll
            for (int nt = 0; nt < 8; nt++) {
                int c = nt*8 + r4;           // output col = e
                uint32_t bf[2];
                bf[0] = Vs[c*FSTR + kw];
                bf[1] = Vs[c*FSTR + kw + 4];
                mma_f16(o[nt], a, bf);
            }
        }
    }

    float inv0 = 1.0f / lreg[0];
    float inv1 = 1.0f / lreg[1];
    int gr0 = q0 + prow;
    int gr1 = gr0 + 8;
    #pragma unroll
    for (int nt = 0; nt < 8; nt++) {
        int c = nt*8 + 2*j4;
        *(__half2*)&ctx[((size_t)(b*Sq + gr0)*Hh + h)*DHd + c] =
            __floats2half2_rn(o[nt][0]*inv0, o[nt][1]*inv0);
        *(__half2*)&ctx[((size_t)(b*Sq + gr1)*Hh + h)*DHd + c] =
            __floats2half2_rn(o[nt][2]*inv1, o[nt][3]*inv1);
    }
}

// ---------------------------------------------------------------------------
// Launch
// ---------------------------------------------------------------------------
extern "C" void kernel_launch(void* const* d_in, const int* in_sizes, int n_in,
                              void* d_out, int out_size)
{
    (void)in_sizes; (void)n_in; (void)out_size;
    const float* x     = (const float*)d_in[0];
    const float* ln1_w = (const float*)d_in[1];
    const float* ln1_b = (const float*)d_in[2];
    const float* ln2_w = (const float*)d_in[3];
    const float* ln2_b = (const float*)d_in[4];
    const float* Wq    = (const float*)d_in[5];
    const float* bq    = (const float*)d_in[6];
    const float* Wk    = (const float*)d_in[7];
    const float* bk    = (const float*)d_in[8];
    const float* Wv    = (const float*)d_in[9];
    const float* bv    = (const float*)d_in[10];
    const float* Wo    = (const float*)d_in[11];
    const float* bo    = (const float*)d_in[12];
    const float* fc1_w = (const float*)d_in[13];
    const float* fc1_b = (const float*)d_in[14];
    const float* fc2_w = (const float*)d_in[15];
    const float* fc2_b = (const float*)d_in[16];
    float* out = (float*)d_out;

    __half *p_wqkv, *p_wo, *p_fc1, *p_fc2, *p_h1, *p_qkv, *p_ctx, *p_h2, *p_a1;
    float *p_bqkv, *p_y1;
    cudaGetSymbolAddress((void**)&p_wqkv, g_wqkv_h);
    cudaGetSymbolAddress((void**)&p_bqkv, g_bqkv);
    cudaGetSymbolAddress((void**)&p_wo,   g_wo_h);
    cudaGetSymbolAddress((void**)&p_fc1,  g_fc1_h);
    cudaGetSymbolAddress((void**)&p_fc2,  g_fc2_h);
    cudaGetSymbolAddress((void**)&p_h1,   g_h1);
    cudaGetSymbolAddress((void**)&p_qkv,  g_qkv);
    cudaGetSymbolAddress((void**)&p_ctx,  g_ctx);
    cudaGetSymbolAddress((void**)&p_y1,   g_y1);
    cudaGetSymbolAddress((void**)&p_h2,   g_h2);
    cudaGetSymbolAddress((void**)&p_a1,   g_a1);

    static int fa_attr_set = 0;
    if (!fa_attr_set) {
        cudaFuncSetAttribute(flash_attn_h16,
                             cudaFuncAttributeMaxDynamicSharedMemorySize, (int)FAH_SMEM);
        fa_attr_set = 1;
    }

    // 0. weight conversion: transpose to col-major half
    conv_t<<<dim3(Dm/32, Dm/32), dim3(32,8)>>>(Wo,    p_wo,  Dm, Dm);
    conv_t<<<dim3(Ff/32, Dm/32), dim3(32,8)>>>(fc1_w, p_fc1, Dm, Ff);
    conv_t<<<dim3(Dm/32, Ff/32), dim3(32,8)>>>(fc2_w, p_fc2, Ff, Dm);

    // 1. repack QKV weights (col-major half, Wq/bq pre-scaled 1/8) + bias
    repack_qkv_kernel<<<(Dm*NQKV + 255)/256, 256>>>(Wq, bq, Wk, bk, Wv, bv);

    // 2. ln1(x) -> h1 (half)
    ln_kernel<<<Mrows/8, 256>>>(x, ln1_w, ln1_b, p_h1);

    // 3. qkv = h1 @ Wqkv + bqkv   [8192, 2304] half
    hgemm128<1|16><<<dim3(NQKV/128, Mrows/128), 256>>>(p_h1, p_wqkv, p_bqkv, nullptr,
                                                       (void*)p_qkv, Mrows, NQKV, Dm);

    // 4-6. fp16 tensor-core attention -> ctx [8192, 768] half
    flash_attn_h16<<<dim3(Sq/128, Bsz*Hh), 256, FAH_SMEM>>>(p_qkv, p_ctx);

    // 7. y1 = x + ctx @ Wo + bo  (f32)
    hgemm128<1|4><<<dim3(Dm/128, Mrows/128), 256>>>(p_ctx, p_wo, bo, x,
                                                    (void*)p_y1, Mrows, Dm, Dm);

    // 8. h2 = ln2(y1) (half)
    ln_kernel<<<Mrows/8, 256>>>(p_y1, ln2_w, ln2_b, p_h2);

    // 9. a1 = gelu(h2 @ fc1_w + fc1_b) (half)
    hgemm128<1|2|16><<<dim3(Ff/128, Mrows/128), 256>>>(p_h2, p_fc1, fc1_b, nullptr,
                                                       (void*)p_a1, Mrows, Ff, Dm);

    // 10. out = y1 + a1 @ fc2_w + fc2_b  (f32)
    hgemm128<1|4><<<dim3(Dm/128, Mrows/128), 256>>>(p_a1, p_fc2, fc2_b, p_y1,
                                                    (void*)out, Mrows, Dm, Ff);
}

// round 11
// speedup vs baseline: 6.0827x; 1.0714x over previous
#include <cuda_runtime.h>
#include <cuda_fp16.h>
#include <math.h>
#include <stdint.h>

// ---------------------------------------------------------------------------
// Problem dims
// ---------------------------------------------------------------------------
#define Bsz 8
#define Sq  1024
#define Dm  768
#define Hh  12
#define DHd 64
#define Ff  3072
#define Mrows (Bsz*Sq)        // 8192
#define NQKV  (3*Hh*DHd)      // 2304
#define LN_EPS 1e-5f

// ---------------------------------------------------------------------------
// Scratch (static device globals; no runtime allocation)
// ---------------------------------------------------------------------------
__device__ __half g_wqkv_h[(size_t)NQKV*Dm];   // col-major [N][K]; Wq part pre-scaled by 1/8
__device__ float  g_bqkv[NQKV];                // bq part pre-scaled by 1/8
__device__ __half g_wo_h[Dm*Dm];               // col-major [N][K]
__device__ __half g_fc1_h[(size_t)Ff*Dm];      // col-major
__device__ __half g_fc2_h[(size_t)Dm*Ff];      // col-major
__device__ __half g_h1[(size_t)Mrows*Dm];      // ln1(x) half
__device__ __half g_qkv[(size_t)Mrows*NQKV];   // half (q pre-scaled by 1/8)
__device__ __half g_ctx[(size_t)Mrows*Dm];     // [b,s,h,e] half
__device__ float  g_y1[(size_t)Mrows*Dm];      // residual f32
__device__ __half g_h2[(size_t)Mrows*Dm];      // ln2(y1) half
__device__ __half g_a1[(size_t)Mrows*Ff];      // gelu(fc1) half

// ---------------------------------------------------------------------------
// PTX helpers
// ---------------------------------------------------------------------------
__device__ __forceinline__ uint32_t smem_u32(const void* p) {
    return (uint32_t)__cvta_generic_to_shared(p);
}
__device__ __forceinline__ void cp_async16(uint32_t saddr, const void* g) {
    asm volatile("cp.async.cg.shared.global [%0], [%1], 16;" :: "r"(saddr), "l"(g));
}
__device__ __forceinline__ void cp_commit() { asm volatile("cp.async.commit_group;"); }
__device__ __forceinline__ void cp_wait_all() { asm volatile("cp.async.wait_group 0;"); }

__device__ __forceinline__ void mma_f16(float* c, const uint32_t* a, const uint32_t* b) {
    asm volatile("mma.sync.aligned.m16n8k16.row.col.f32.f16.f16.f32 "
        "{%0,%1,%2,%3}, {%4,%5,%6,%7}, {%8,%9}, {%0,%1,%2,%3};"
        : "+f"(c[0]), "+f"(c[1]), "+f"(c[2]), "+f"(c[3])
        : "r"(a[0]), "r"(a[1]), "r"(a[2]), "r"(a[3]), "r"(b[0]), "r"(b[1]));
}

__device__ __forceinline__ void ldsm_x4(uint32_t& r0, uint32_t& r1, uint32_t& r2,
                                        uint32_t& r3, uint32_t addr) {
    asm volatile("ldmatrix.sync.aligned.m8n8.x4.shared.b16 {%0,%1,%2,%3}, [%4];"
        : "=r"(r0), "=r"(r1), "=r"(r2), "=r"(r3) : "r"(addr));
}

__device__ __forceinline__ float gelu_exact(float v) {
    return 0.5f * v * (1.0f + erff(v * 0.70710678118654752440f));
}
__device__ __forceinline__ uint32_t pack_h2(float lo, float hi) {
    __half2 h = __floats2half2_rn(lo, hi);
    return *(uint32_t*)&h;
}

// ---------------------------------------------------------------------------
// Tiled transpose + f32->f16: src [K,N] row-major -> dst [N,K] half
// ---------------------------------------------------------------------------
__global__ void conv_t(const float* __restrict__ src, __half* __restrict__ dst,
                       int K, int N)
{
    __shared__ float t[32][33];
    int n0 = blockIdx.x * 32, k0 = blockIdx.y * 32;
    int tx = threadIdx.x, ty = threadIdx.y;
    #pragma unroll
    for (int i = 0; i < 32; i += 8)
        t[ty + i][tx] = src[(size_t)(k0 + ty + i) * N + n0 + tx];
    __syncthreads();
    #pragma unroll
    for (int i = 0; i < 32; i += 8)
        dst[(size_t)(n0 + ty + i) * K + k0 + tx] = __float2half(t[tx][ty + i]);
}

// ---------------------------------------------------------------------------
// Repack per-head QKV weights -> col-major half [NQKV][Dm] (+ f32 bias).
// Q projection (and bias) pre-scaled by 1/8 (exact power of two).
// ---------------------------------------------------------------------------
__global__ void repack_qkv_kernel(const float* __restrict__ Wq, const float* __restrict__ bq,
                                  const float* __restrict__ Wk, const float* __restrict__ bk,
                                  const float* __restrict__ Wv, const float* __restrict__ bv)
{
    int idx = blockIdx.x * blockDim.x + threadIdx.x;
    if (idx < Dm * NQKV) {
        int c = idx / Dm;
        int d = idx % Dm;
        int proj = c / (Hh*DHd);
        int hc   = c % (Hh*DHd);
        int h = hc / DHd;
        int e = hc % DHd;
        const float* W = (proj == 0) ? Wq : (proj == 1) ? Wk : Wv;
        float v = W[((size_t)h*Dm + d)*DHd + e];
        if (proj == 0) v *= 0.125f;
        g_wqkv_h[(size_t)c*Dm + d] = __float2half(v);
    }
    if (idx < NQKV) {
        int proj = idx / (Hh*DHd);
        int hc   = idx % (Hh*DHd);
        const float* bb = (proj == 0) ? bq : (proj == 1) ? bk : bv;
        g_bqkv[idx] = (proj == 0) ? bb[hc] * 0.125f : bb[hc];
    }
}

// ---------------------------------------------------------------------------
// LayerNorm (768). Warp per row, shfl-only; output half.
// ---------------------------------------------------------------------------
__global__ void __launch_bounds__(256) ln_kernel(const float* __restrict__ x,
                                                 const float* __restrict__ w,
                                                 const float* __restrict__ b,
                                                 __half* __restrict__ out)
{
    int warp = threadIdx.x >> 5;
    int lane = threadIdx.x & 31;
    int row  = blockIdx.x * 8 + warp;
    const float* xr = x + (size_t)row * Dm;
    __half* orow = out + (size_t)row * Dm;

    float4 v[6];
    #pragma unroll
    for (int i = 0; i < 6; i++)
        v[i] = *(const float4*)&xr[(lane + i*32) * 4];

    float s = 0.0f;
    #pragma unroll
    for (int i = 0; i < 6; i++) s += v[i].x + v[i].y + v[i].z + v[i].w;
    #pragma unroll
    for (int o = 16; o > 0; o >>= 1) s += __shfl_xor_sync(0xffffffffu, s, o);
    float mu = s * (1.0f / Dm);

    float vs = 0.0f;
    #pragma unroll
    for (int i = 0; i < 6; i++) {
        float a0 = v[i].x - mu, a1 = v[i].y - mu, a2 = v[i].z - mu, a3 = v[i].w - mu;
        v[i] = make_float4(a0, a1, a2, a3);
        vs += a0*a0 + a1*a1 + a2*a2 + a3*a3;
    }
    #pragma unroll
    for (int o = 16; o > 0; o >>= 1) vs += __shfl_xor_sync(0xffffffffu, vs, o);
    float inv = rsqrtf(vs * (1.0f / Dm) + LN_EPS);

    #pragma unroll
    for (int i = 0; i < 6; i++) {
        int c = (lane + i*32) * 4;
        float4 ww = *(const float4*)&w[c];
        float4 bb = *(const float4*)&b[c];
        *(__half2*)&orow[c]     = __floats2half2_rn(v[i].x * inv * ww.x + bb.x,
                                                    v[i].y * inv * ww.y + bb.y);
        *(__half2*)&orow[c + 2] = __floats2half2_rn(v[i].z * inv * ww.z + bb.z,
                                                    v[i].w * inv * ww.w + bb.w);
    }
}

// ---------------------------------------------------------------------------
// FP16 tensor-core GEMM: C = A[M,K](row,half) * B[N,K](col,half)
// 128x128x32 tiles, mma.m16n8k16, f32 accumulate.
// Fragment loads via ldmatrix.m8n8.x4 (12 loads per k-tile vs 48 LDS).
// Epilogue flags: 1=bias f32, 2=gelu, 4=residual f32, 16=half output
// ---------------------------------------------------------------------------
#define HSTR 40        // halves per smem row (80 B)

template<int EPI>
__global__ void __launch_bounds__(256, 2) hgemm128(const __half* __restrict__ A,
                                                   const __half* __restrict__ Bc,
                                                   const float* __restrict__ bias,
                                                   const float* __restrict__ res,
                                                   void* __restrict__ Cv,
                                                   int M, int N, int K)
{
    __shared__ __half As[2][128*HSTR];
    __shared__ __half Bs[2][128*HSTR];

    int tid  = threadIdx.x;
    int lane = tid & 31;
    int wid  = tid >> 5;
    int wm   = wid & 3;
    int wn   = wid >> 2;
    int row0 = blockIdx.y * 128;
    int col0 = blockIdx.x * 128;

    int lr = tid >> 2;
    int lc = (tid & 3) << 3;

    const __half* Ag = A  + (size_t)(row0 + lr) * K + lc;
    const __half* Bg = Bc + (size_t)(col0 + lr) * K + lc;

    float acc[2][8][4];
    #pragma unroll
    for (int mt = 0; mt < 2; mt++)
        #pragma unroll
        for (int nt = 0; nt < 8; nt++)
            #pragma unroll
            for (int q = 0; q < 4; q++) acc[mt][nt][q] = 0.0f;

    int nk = K / 32;

    {
        cp_async16(smem_u32(&As[0][lr*HSTR + lc]),        Ag);
        cp_async16(smem_u32(&As[0][(lr+64)*HSTR + lc]),   Ag + (size_t)64*K);
        cp_async16(smem_u32(&Bs[0][lr*HSTR + lc]),        Bg);
        cp_async16(smem_u32(&Bs[0][(lr+64)*HSTR + lc]),   Bg + (size_t)64*K);
        cp_commit();
    }

    // ldmatrix lane statics (byte offsets into the 80B-stride tiles)
    // A x4: matrix m = lane>>3 -> row_off (m&1)*8, k_off (m>>1)*8 halves
    int row_a  = wm*32 + (lane & 7) + ((lane >> 3) & 1) * 8;
    int koff_a = ((lane >> 4) & 1) * 8;
    // B x4 (nt pair p): matrix m = lane>>3 -> nt_off (m>>1)*8 rows, k_off (m&1)*8
    int row_b  = wn*64 + (lane & 7) + ((lane >> 4) & 1) * 8;
    int koff_b = ((lane >> 3) & 1) * 8;

    int mrow = wm*32 + (lane >> 2);   // epilogue row mapping (unchanged)

    for (int kt = 0; kt < nk; kt++) {
        cp_wait_all();
        __syncthreads();
        int cur = kt & 1;

        if (kt + 1 < nk) {
            int nxt = cur ^ 1;
            const __half* Agn = Ag + (size_t)(kt+1)*32;
            const __half* Bgn = Bg + (size_t)(kt+1)*32;
            cp_async16(smem_u32(&As[nxt][lr*HSTR + lc]),      Agn);
            cp_async16(smem_u32(&As[nxt][(lr+64)*HSTR + lc]), Agn + (size_t)64*K);
            cp_async16(smem_u32(&Bs[nxt][lr*HSTR + lc]),      Bgn);
            cp_async16(smem_u32(&Bs[nxt][(lr+64)*HSTR + lc]), Bgn + (size_t)64*K);
            cp_commit();
        }

        uint32_t aB = smem_u32(As[cur]);
        uint32_t bB = smem_u32(Bs[cur]);

        #pragma unroll
        for (int ks = 0; ks < 2; ks++) {
            uint32_t af[2][4];
            #pragma unroll
            for (int mt = 0; mt < 2; mt++)
                ldsm_x4(af[mt][0], af[mt][1], af[mt][2], af[mt][3],
                        aB + (uint32_t)(((row_a + mt*16)*HSTR + ks*16 + koff_a) * 2));
            #pragma unroll
            for (int p = 0; p < 4; p++) {
                uint32_t b0, b1, b2, b3;
                ldsm_x4(b0, b1, b2, b3,
                        bB + (uint32_t)(((row_b + p*16)*HSTR + ks*16 + koff_b) * 2));
                uint32_t bf0[2] = {b0, b1};
                uint32_t bf1[2] = {b2, b3};
                mma_f16(acc[0][2*p],   af[0], bf0);
                mma_f16(acc[1][2*p],   af[1], bf0);
                mma_f16(acc[0][2*p+1], af[0], bf1);
                mma_f16(acc[1][2*p+1], af[1], bf1);
            }
        }
    }

    #pragma unroll
    for (int mt = 0; mt < 2; mt++) {
        #pragma unroll
        for (int i = 0; i < 2; i++) {
            size_t r = row0 + mrow + mt*16 + i*8;
            #pragma unroll
            for (int nt = 0; nt < 8; nt++) {
                int c = col0 + wn*64 + nt*8 + 2*(lane & 3);
                float v0 = acc[mt][nt][2*i + 0];
                float v1 = acc[mt][nt][2*i + 1];
                if (EPI & 1) { v0 += bias[c]; v1 += bias[c+1]; }
                if (EPI & 2) { v0 = gelu_exact(v0); v1 = gelu_exact(v1); }
                if (EPI & 4) {
                    float2 rr = *(const float2*)&res[r * N + c];
                    v0 += rr.x; v1 += rr.y;
                }
                if (EPI & 16) {
                    *(__half2*)&((__half*)Cv)[r * N + c] = __floats2half2_rn(v0, v1);
                } else {
                    *(float2*)&((float*)Cv)[r * N + c] = make_float2(v0, v1);
                }
            }
        }
    }
}

// ---------------------------------------------------------------------------
// FP16 tensor-core flash attention (validated at 739us; unchanged).
// ---------------------------------------------------------------------------
#define FSTR 36
#define FAH_SMEM ((128*FSTR + 128*FSTR + 64*FSTR + 64*FSTR) * 4)   // 55296 B

__global__ void __launch_bounds__(256, 2) flash_attn_h16(const __half* __restrict__ qkv,
                                                         __half* __restrict__ ctx)
{
    extern __shared__ uint32_t usm[];
    uint32_t* Qs = usm;
    uint32_t* Ps = Qs + 128*FSTR;
    uint32_t* Ks = Ps + 128*FSTR;
    uint32_t* Vs = Ks + 64*FSTR;

    int bh = blockIdx.y;
    int b = bh / Hh, h = bh % Hh;
    int q0 = blockIdx.x * 128;
    int tid = threadIdx.x;
    int lane = tid & 31;
    int w = tid >> 5;
    int r4 = lane >> 2;
    int j4 = lane & 3;

    const __half* qbase = qkv + (size_t)(b*Sq)*NQKV + h*DHd;
    const __half* kbase = qbase + Hh*DHd;
    const __half* vbase = qbase + 2*Hh*DHd;

    #pragma unroll
    for (int i = tid; i < 128*8; i += 256) {
        int r = i >> 3, seg = i & 7;
        cp_async16(smem_u32(&Qs[r*FSTR + seg*4]),
                   qbase + (size_t)(q0 + r)*NQKV + seg*8);
    }
    cp_commit();

    float o[8][4];
    #pragma unroll
    for (int nt = 0; nt < 8; nt++)
        #pragma unroll
        for (int q = 0; q < 4; q++) o[nt][q] = 0.0f;
    float mreg[2] = {-INFINITY, -INFINITY};
    float lreg[2] = {0.0f, 0.0f};

    int prow = w*16 + r4;

    for (int kt = 0; kt < Sq/64; kt++) {
        __syncthreads();

        #pragma unroll
        for (int i = tid; i < 64*8; i += 256) {
            int r = i >> 3, seg = i & 7;
            cp_async16(smem_u32(&Ks[r*FSTR + seg*4]),
                       kbase + (size_t)(kt*64 + r)*NQKV + seg*8);
        }
        cp_commit();

        {
            int tp = tid & 31;
            int eg = tid >> 5;
            const __half* v0p = vbase + (size_t)(kt*64 + 2*tp)*NQKV + eg*8;
            uint4 x0 = *(const uint4*)v0p;
            uint4 x1 = *(const uint4*)(v0p + NQKV);
            const unsigned short* h0 = (const unsigned short*)&x0;
            const unsigned short* h1 = (const unsigned short*)&x1;
            #pragma unroll
            for (int j = 0; j < 8; j++)
                Vs[(eg*8 + j)*FSTR + tp] = (uint32_t)h0[j] | ((uint32_t)h1[j] << 16);
        }
        cp_wait_all();
        __syncthreads();

        float s[8][4];
        #pragma unroll
        for (int nt = 0; nt < 8; nt++)
            #pragma unroll
            for (int q = 0; q < 4; q++) s[nt][q] = 0.0f;

        #pragma unroll
        for (int ks = 0; ks < 4; ks++) {
            int kw = ks*8 + j4;
            uint32_t a[4];
            a[0] = Qs[prow*FSTR + kw];
            a[1] = Qs[(prow+8)*FSTR + kw];
            a[2] = Qs[prow*FSTR + kw + 4];
            a[3] = Qs[(prow+8)*FSTR + kw + 4];
            #pragma unroll
            for (int nt = 0; nt < 8; nt++) {
                int c = nt*8 + r4;
                uint32_t bf[2];
                bf[0] = Ks[c*FSTR + kw];
                bf[1] = Ks[c*FSTR + kw + 4];
                mma_f16(s[nt], a, bf);
            }
        }

        float mx0 = -INFINITY, mx1 = -INFINITY;
        #pragma unroll
        for (int nt = 0; nt < 8; nt++) {
            mx0 = fmaxf(mx0, fmaxf(s[nt][0], s[nt][1]));
            mx1 = fmaxf(mx1, fmaxf(s[nt][2], s[nt][3]));
        }
        mx0 = fmaxf(mx0, __shfl_xor_sync(0xffffffffu, mx0, 1));
        mx0 = fmaxf(mx0, __shfl_xor_sync(0xffffffffu, mx0, 2));
        mx1 = fmaxf(mx1, __shfl_xor_sync(0xffffffffu, mx1, 1));
        mx1 = fmaxf(mx1, __shfl_xor_sync(0xffffffffu, mx1, 2));

        float mn0 = fmaxf(mreg[0], mx0);
        float mn1 = fmaxf(mreg[1], mx1);
        float al0 = __expf(mreg[0] - mn0);
        float al1 = __expf(mreg[1] - mn1);

        float sum0 = 0.0f, sum1 = 0.0f;
        #pragma unroll
        for (int nt = 0; nt < 8; nt++) {
            s[nt][0] = __expf(s[nt][0] - mn0);
            s[nt][1] = __expf(s[nt][1] - mn0);
            s[nt][2] = __expf(s[nt][2] - mn1);
            s[nt][3] = __expf(s[nt][3] - mn1);
            sum0 += s[nt][0] + s[nt][1];
            sum1 += s[nt][2] + s[nt][3];
        }
        sum0 += __shfl_xor_sync(0xffffffffu, sum0, 1);
        sum0 += __shfl_xor_sync(0xffffffffu, sum0, 2);
        sum1 += __shfl_xor_sync(0xffffffffu, sum1, 1);
        sum1 += __shfl_xor_sync(0xffffffffu, sum1, 2);

        lreg[0] = lreg[0]*al0 + sum0;  mreg[0] = mn0;
        lreg[1] = lreg[1]*al1 + sum1;  mreg[1] = mn1;

        #pragma unroll
        for (int nt = 0; nt < 8; nt++) {
            o[nt][0] *= al0; o[nt][1] *= al0;
            o[nt][2] *= al1; o[nt][3] *= al1;
        }

        #pragma unroll
        for (int nt = 0; nt < 8; nt++) {
            Ps[prow*FSTR + nt*4 + j4]     = pack_h2(s[nt][0], s[nt][1]);
            Ps[(prow+8)*FSTR + nt*4 + j4] = pack_h2(s[nt][2], s[nt][3]);
        }
        __syncwarp();

        #pragma unroll
        for (int ks = 0; ks < 4; ks++) {
            int kw = ks*8 + j4;
            uint32_t a[4];
            a[0] = Ps[prow*FSTR + kw];
            a[1] = Ps[(prow+8)*FSTR + kw];
            a[2] = Ps[prow*FSTR + kw + 4];
            a[3] = Ps[(prow+8)*FSTR + kw + 4];
            #pragma unroll
            for (int nt = 0; nt < 8; nt++) {
                int c = nt*8 + r4;
                uint32_t bf[2];
                bf[0] = Vs[c*FSTR + kw];
                bf[1] = Vs[c*FSTR + kw + 4];
                mma_f16(o[nt], a, bf);
            }
        }
    }

    float inv0 = 1.0f / lreg[0];
    float inv1 = 1.0f / lreg[1];
    int gr0 = q0 + prow;
    int gr1 = gr0 + 8;
    #pragma unroll
    for (int nt = 0; nt < 8; nt++) {
        int c = nt*8 + 2*j4;
        *(__half2*)&ctx[((size_t)(b*Sq + gr0)*Hh + h)*DHd + c] =
            __floats2half2_rn(o[nt][0]*inv0, o[nt][1]*inv0);
        *(__half2*)&ctx[((size_t)(b*Sq + gr1)*Hh + h)*DHd + c] =
            __floats2half2_rn(o[nt][2]*inv1, o[nt][3]*inv1);
    }
}

// ---------------------------------------------------------------------------
// Launch
// ---------------------------------------------------------------------------
extern "C" void kernel_launch(void* const* d_in, const int* in_sizes, int n_in,
                              void* d_out, int out_size)
{
    (void)in_sizes; (void)n_in; (void)out_size;
    const float* x     = (const float*)d_in[0];
    const float* ln1_w = (const float*)d_in[1];
    const float* ln1_b = (const float*)d_in[2];
    const float* ln2_w = (const float*)d_in[3];
    const float* ln2_b = (const float*)d_in[4];
    const float* Wq    = (const float*)d_in[5];
    const float* bq    = (const float*)d_in[6];
    const float* Wk    = (const float*)d_in[7];
    const float* bk    = (const float*)d_in[8];
    const float* Wv    = (const float*)d_in[9];
    const float* bv    = (const float*)d_in[10];
    const float* Wo    = (const float*)d_in[11];
    const float* bo    = (const float*)d_in[12];
    const float* fc1_w = (const float*)d_in[13];
    const float* fc1_b = (const float*)d_in[14];
    const float* fc2_w = (const float*)d_in[15];
    const float* fc2_b = (const float*)d_in[16];
    float* out = (float*)d_out;

    __half *p_wqkv, *p_wo, *p_fc1, *p_fc2, *p_h1, *p_qkv, *p_ctx, *p_h2, *p_a1;
    float *p_bqkv, *p_y1;
    cudaGetSymbolAddress((void**)&p_wqkv, g_wqkv_h);
    cudaGetSymbolAddress((void**)&p_bqkv, g_bqkv);
    cudaGetSymbolAddress((void**)&p_wo,   g_wo_h);
    cudaGetSymbolAddress((void**)&p_fc1,  g_fc1_h);
    cudaGetSymbolAddress((void**)&p_fc2,  g_fc2_h);
    cudaGetSymbolAddress((void**)&p_h1,   g_h1);
    cudaGetSymbolAddress((void**)&p_qkv,  g_qkv);
    cudaGetSymbolAddress((void**)&p_ctx,  g_ctx);
    cudaGetSymbolAddress((void**)&p_y1,   g_y1);
    cudaGetSymbolAddress((void**)&p_h2,   g_h2);
    cudaGetSymbolAddress((void**)&p_a1,   g_a1);

    static int fa_attr_set = 0;
    if (!fa_attr_set) {
        cudaFuncSetAttribute(flash_attn_h16,
                             cudaFuncAttributeMaxDynamicSharedMemorySize, (int)FAH_SMEM);
        fa_attr_set = 1;
    }

    // 0. weight conversion: transpose to col-major half
    conv_t<<<dim3(Dm/32, Dm/32), dim3(32,8)>>>(Wo,    p_wo,  Dm, Dm);
    conv_t<<<dim3(Ff/32, Dm/32), dim3(32,8)>>>(fc1_w, p_fc1, Dm, Ff);
    conv_t<<<dim3(Dm/32, Ff/32), dim3(32,8)>>>(fc2_w, p_fc2, Ff, Dm);

    // 1. repack QKV weights (col-major half, Wq/bq pre-scaled 1/8) + bias
    repack_qkv_kernel<<<(Dm*NQKV + 255)/256, 256>>>(Wq, bq, Wk, bk, Wv, bv);

    // 2. ln1(x) -> h1 (half)
    ln_kernel<<<Mrows/8, 256>>>(x, ln1_w, ln1_b, p_h1);

    // 3. qkv = h1 @ Wqkv + bqkv   [8192, 2304] half
    hgemm128<1|16><<<dim3(NQKV/128, Mrows/128), 256>>>(p_h1, p_wqkv, p_bqkv, nullptr,
                                                       (void*)p_qkv, Mrows, NQKV, Dm);

    // 4-6. fp16 tensor-core attention -> ctx [8192, 768] half
    flash_attn_h16<<<dim3(Sq/128, Bsz*Hh), 256, FAH_SMEM>>>(p_qkv, p_ctx);

    // 7. y1 = x + ctx @ Wo + bo  (f32)
    hgemm128<1|4><<<dim3(Dm/128, Mrows/128), 256>>>(p_ctx, p_wo, bo, x,
                                                    (void*)p_y1, Mrows, Dm, Dm);

    // 8. h2 = ln2(y1) (half)
    ln_kernel<<<Mrows/8, 256>>>(p_y1, ln2_w, ln2_b, p_h2);

    // 9. a1 = gelu(h2 @ fc1_w + fc1_b) (half)
    hgemm128<1|2|16><<<dim3(Ff/128, Mrows/128), 256>>>(p_h2, p_fc1, fc1_b, nullptr,
                                                       (void*)p_a1, Mrows, Ff, Dm);

    // 10. out = y1 + a1 @ fc2_w + fc2_b  (f32)
    hgemm128<1|4><<<dim3(Dm/128, Mrows/128), 256>>>(p_a1, p_fc2, fc2_b, p_y1,
                                                    (void*)out, Mrows, Dm, Ff);
}

// round 12
// speedup vs baseline: 6.1528x; 1.0115x over previous
#include <cuda_runtime.h>
#include <cuda_fp16.h>
#include <math.h>
#include <stdint.h>

// ---------------------------------------------------------------------------
// Problem dims
// ---------------------------------------------------------------------------
#define Bsz 8
#define Sq  1024
#define Dm  768
#define Hh  12
#define DHd 64
#define Ff  3072
#define Mrows (Bsz*Sq)        // 8192
#define NQKV  (3*Hh*DHd)      // 2304
#define LN_EPS 1e-5f

// ---------------------------------------------------------------------------
// Scratch (static device globals; no runtime allocation)
// ---------------------------------------------------------------------------
__device__ __half g_wqkv_h[(size_t)NQKV*Dm];   // col-major [N][K]; Wq part pre-scaled by 1/8
__device__ float  g_bqkv[NQKV];                // bq part pre-scaled by 1/8
__device__ __half g_wo_h[Dm*Dm];               // col-major [N][K]
__device__ __half g_fc1_h[(size_t)Ff*Dm];      // col-major
__device__ __half g_fc2_h[(size_t)Dm*Ff];      // col-major
__device__ __half g_h1[(size_t)Mrows*Dm];      // ln1(x) half
__device__ __half g_qkv[(size_t)Mrows*NQKV];   // half (q pre-scaled by 1/8)
__device__ __half g_ctx[(size_t)Mrows*Dm];     // [b,s,h,e] half
__device__ float  g_y1[(size_t)Mrows*Dm];      // residual f32
__device__ __half g_h2[(size_t)Mrows*Dm];      // ln2(y1) half
__device__ __half g_a1[(size_t)Mrows*Ff];      // gelu(fc1) half

// ---------------------------------------------------------------------------
// PTX helpers
// ---------------------------------------------------------------------------
__device__ __forceinline__ uint32_t smem_u32(const void* p) {
    return (uint32_t)__cvta_generic_to_shared(p);
}
__device__ __forceinline__ void cp_async16(uint32_t saddr, const void* g) {
    asm volatile("cp.async.cg.shared.global [%0], [%1], 16;" :: "r"(saddr), "l"(g));
}
__device__ __forceinline__ void cp_commit() { asm volatile("cp.async.commit_group;"); }
__device__ __forceinline__ void cp_wait_all() { asm volatile("cp.async.wait_group 0;"); }
__device__ __forceinline__ void cp_wait_1() { asm volatile("cp.async.wait_group 1;"); }

__device__ __forceinline__ void mma_f16(float* c, const uint32_t* a, const uint32_t* b) {
    asm volatile("mma.sync.aligned.m16n8k16.row.col.f32.f16.f16.f32 "
        "{%0,%1,%2,%3}, {%4,%5,%6,%7}, {%8,%9}, {%0,%1,%2,%3};"
        : "+f"(c[0]), "+f"(c[1]), "+f"(c[2]), "+f"(c[3])
        : "r"(a[0]), "r"(a[1]), "r"(a[2]), "r"(a[3]), "r"(b[0]), "r"(b[1]));
}

__device__ __forceinline__ void ldsm_x4(uint32_t& r0, uint32_t& r1, uint32_t& r2,
                                        uint32_t& r3, uint32_t addr) {
    asm volatile("ldmatrix.sync.aligned.m8n8.x4.shared.b16 {%0,%1,%2,%3}, [%4];"
        : "=r"(r0), "=r"(r1), "=r"(r2), "=r"(r3) : "r"(addr));
}

__device__ __forceinline__ float gelu_exact(float v) {
    return 0.5f * v * (1.0f + erff(v * 0.70710678118654752440f));
}
__device__ __forceinline__ uint32_t pack_h2(float lo, float hi) {
    __half2 h = __floats2half2_rn(lo, hi);
    return *(uint32_t*)&h;
}

// ---------------------------------------------------------------------------
// Tiled transpose + f32->f16: src [K,N] row-major -> dst [N,K] half
// ---------------------------------------------------------------------------
__global__ void conv_t(const float* __restrict__ src, __half* __restrict__ dst,
                       int K, int N)
{
    __shared__ float t[32][33];
    int n0 = blockIdx.x * 32, k0 = blockIdx.y * 32;
    int tx = threadIdx.x, ty = threadIdx.y;
    #pragma unroll
    for (int i = 0; i < 32; i += 8)
        t[ty + i][tx] = src[(size_t)(k0 + ty + i) * N + n0 + tx];
    __syncthreads();
    #pragma unroll
    for (int i = 0; i < 32; i += 8)
        dst[(size_t)(n0 + ty + i) * K + k0 + tx] = __float2half(t[tx][ty + i]);
}

// ---------------------------------------------------------------------------
// Repack per-head QKV weights -> col-major half [NQKV][Dm] (+ f32 bias).
// Q projection (and bias) pre-scaled by 1/8 (exact power of two).
// ---------------------------------------------------------------------------
__global__ void repack_qkv_kernel(const float* __restrict__ Wq, const float* __restrict__ bq,
                                  const float* __restrict__ Wk, const float* __restrict__ bk,
                                  const float* __restrict__ Wv, const float* __restrict__ bv)
{
    int idx = blockIdx.x * blockDim.x + threadIdx.x;
    if (idx < Dm * NQKV) {
        int c = idx / Dm;
        int d = idx % Dm;
        int proj = c / (Hh*DHd);
        int hc   = c % (Hh*DHd);
        int h = hc / DHd;
        int e = hc % DHd;
        const float* W = (proj == 0) ? Wq : (proj == 1) ? Wk : Wv;
        float v = W[((size_t)h*Dm + d)*DHd + e];
        if (proj == 0) v *= 0.125f;
        g_wqkv_h[(size_t)c*Dm + d] = __float2half(v);
    }
    if (idx < NQKV) {
        int proj = idx / (Hh*DHd);
        int hc   = idx % (Hh*DHd);
        const float* bb = (proj == 0) ? bq : (proj == 1) ? bk : bv;
        g_bqkv[idx] = (proj == 0) ? bb[hc] * 0.125f : bb[hc];
    }
}

// ---------------------------------------------------------------------------
// LayerNorm (768). Warp per row, shfl-only; output half.
// ---------------------------------------------------------------------------
__global__ void __launch_bounds__(256) ln_kernel(const float* __restrict__ x,
                                                 const float* __restrict__ w,
                                                 const float* __restrict__ b,
                                                 __half* __restrict__ out)
{
    int warp = threadIdx.x >> 5;
    int lane = threadIdx.x & 31;
    int row  = blockIdx.x * 8 + warp;
    const float* xr = x + (size_t)row * Dm;
    __half* orow = out + (size_t)row * Dm;

    float4 v[6];
    #pragma unroll
    for (int i = 0; i < 6; i++)
        v[i] = *(const float4*)&xr[(lane + i*32) * 4];

    float s = 0.0f;
    #pragma unroll
    for (int i = 0; i < 6; i++) s += v[i].x + v[i].y + v[i].z + v[i].w;
    #pragma unroll
    for (int o = 16; o > 0; o >>= 1) s += __shfl_xor_sync(0xffffffffu, s, o);
    float mu = s * (1.0f / Dm);

    float vs = 0.0f;
    #pragma unroll
    for (int i = 0; i < 6; i++) {
        float a0 = v[i].x - mu, a1 = v[i].y - mu, a2 = v[i].z - mu, a3 = v[i].w - mu;
        v[i] = make_float4(a0, a1, a2, a3);
        vs += a0*a0 + a1*a1 + a2*a2 + a3*a3;
    }
    #pragma unroll
    for (int o = 16; o > 0; o >>= 1) vs += __shfl_xor_sync(0xffffffffu, vs, o);
    float inv = rsqrtf(vs * (1.0f / Dm) + LN_EPS);

    #pragma unroll
    for (int i = 0; i < 6; i++) {
        int c = (lane + i*32) * 4;
        float4 ww = *(const float4*)&w[c];
        float4 bb = *(const float4*)&b[c];
        *(__half2*)&orow[c]     = __floats2half2_rn(v[i].x * inv * ww.x + bb.x,
                                                    v[i].y * inv * ww.y + bb.y);
        *(__half2*)&orow[c + 2] = __floats2half2_rn(v[i].z * inv * ww.z + bb.z,
                                                    v[i].w * inv * ww.w + bb.w);
    }
}

// ---------------------------------------------------------------------------
// FP16 tensor-core GEMM (validated at 690us): C = A[M,K](row) * B[N,K](col)
// 128x128x32 tiles, mma.m16n8k16, ldmatrix fragment loads.
// Epilogue flags: 1=bias f32, 2=gelu, 4=residual f32, 16=half output
// ---------------------------------------------------------------------------
#define HSTR 40        // halves per smem row (80 B)

template<int EPI>
__global__ void __launch_bounds__(256, 2) hgemm128(const __half* __restrict__ A,
                                                   const __half* __restrict__ Bc,
                                                   const float* __restrict__ bias,
                                                   const float* __restrict__ res,
                                                   void* __restrict__ Cv,
                                                   int M, int N, int K)
{
    __shared__ __half As[2][128*HSTR];
    __shared__ __half Bs[2][128*HSTR];

    int tid  = threadIdx.x;
    int lane = tid & 31;
    int wid  = tid >> 5;
    int wm   = wid & 3;
    int wn   = wid >> 2;
    int row0 = blockIdx.y * 128;
    int col0 = blockIdx.x * 128;

    int lr = tid >> 2;
    int lc = (tid & 3) << 3;

    const __half* Ag = A  + (size_t)(row0 + lr) * K + lc;
    const __half* Bg = Bc + (size_t)(col0 + lr) * K + lc;

    float acc[2][8][4];
    #pragma unroll
    for (int mt = 0; mt < 2; mt++)
        #pragma unroll
        for (int nt = 0; nt < 8; nt++)
            #pragma unroll
            for (int q = 0; q < 4; q++) acc[mt][nt][q] = 0.0f;

    int nk = K / 32;

    {
        cp_async16(smem_u32(&As[0][lr*HSTR + lc]),        Ag);
        cp_async16(smem_u32(&As[0][(lr+64)*HSTR + lc]),   Ag + (size_t)64*K);
        cp_async16(smem_u32(&Bs[0][lr*HSTR + lc]),        Bg);
        cp_async16(smem_u32(&Bs[0][(lr+64)*HSTR + lc]),   Bg + (size_t)64*K);
        cp_commit();
    }

    int row_a  = wm*32 + (lane & 7) + ((lane >> 3) & 1) * 8;
    int koff_a = ((lane >> 4) & 1) * 8;
    int row_b  = wn*64 + (lane & 7) + ((lane >> 4) & 1) * 8;
    int koff_b = ((lane >> 3) & 1) * 8;

    int mrow = wm*32 + (lane >> 2);

    for (int kt = 0; kt < nk; kt++) {
        cp_wait_all();
        __syncthreads();
        int cur = kt & 1;

        if (kt + 1 < nk) {
            int nxt = cur ^ 1;
            const __half* Agn = Ag + (size_t)(kt+1)*32;
            const __half* Bgn = Bg + (size_t)(kt+1)*32;
            cp_async16(smem_u32(&As[nxt][lr*HSTR + lc]),      Agn);
            cp_async16(smem_u32(&As[nxt][(lr+64)*HSTR + lc]), Agn + (size_t)64*K);
            cp_async16(smem_u32(&Bs[nxt][lr*HSTR + lc]),      Bgn);
            cp_async16(smem_u32(&Bs[nxt][(lr+64)*HSTR + lc]), Bgn + (size_t)64*K);
            cp_commit();
        }

        uint32_t aB = smem_u32(As[cur]);
        uint32_t bB = smem_u32(Bs[cur]);

        #pragma unroll
        for (int ks = 0; ks < 2; ks++) {
            uint32_t af[2][4];
            #pragma unroll
            for (int mt = 0; mt < 2; mt++)
                ldsm_x4(af[mt][0], af[mt][1], af[mt][2], af[mt][3],
                        aB + (uint32_t)(((row_a + mt*16)*HSTR + ks*16 + koff_a) * 2));
            #pragma unroll
            for (int p = 0; p < 4; p++) {
                uint32_t b0, b1, b2, b3;
                ldsm_x4(b0, b1, b2, b3,
                        bB + (uint32_t)(((row_b + p*16)*HSTR + ks*16 + koff_b) * 2));
                uint32_t bf0[2] = {b0, b1};
                uint32_t bf1[2] = {b2, b3};
                mma_f16(acc[0][2*p],   af[0], bf0);
                mma_f16(acc[1][2*p],   af[1], bf0);
                mma_f16(acc[0][2*p+1], af[0], bf1);
                mma_f16(acc[1][2*p+1], af[1], bf1);
            }
        }
    }

    #pragma unroll
    for (int mt = 0; mt < 2; mt++) {
        #pragma unroll
        for (int i = 0; i < 2; i++) {
            size_t r = row0 + mrow + mt*16 + i*8;
            #pragma unroll
            for (int nt = 0; nt < 8; nt++) {
                int c = col0 + wn*64 + nt*8 + 2*(lane & 3);
                float v0 = acc[mt][nt][2*i + 0];
                float v1 = acc[mt][nt][2*i + 1];
                if (EPI & 1) { v0 += bias[c]; v1 += bias[c+1]; }
                if (EPI & 2) { v0 = gelu_exact(v0); v1 = gelu_exact(v1); }
                if (EPI & 4) {
                    float2 rr = *(const float2*)&res[r * N + c];
                    v0 += rr.x; v1 += rr.y;
                }
                if (EPI & 16) {
                    *(__half2*)&((__half*)Cv)[r * N + c] = __floats2half2_rn(v0, v1);
                } else {
                    *(float2*)&((float*)Cv)[r * N + c] = make_float2(v0, v1);
                }
            }
        }
    }
}

// ---------------------------------------------------------------------------
// FP16 flash attention with double-buffered K/V and ldmatrix fragment loads.
// q-tile 128, kv-tile 64, 8 warps; warp w owns q-rows [16w, 16w+16).
// Smem u32 stride FSTR=36/row (conflict-free for ldsm: 36 mod 32 = 4).
// ---------------------------------------------------------------------------
#define FSTR 36
#define NTILES (Sq/64)
#define FAH_SMEM ((128*FSTR + 128*FSTR + 2*64*FSTR + 2*64*FSTR) * 4)   // 73728 B

__global__ void __launch_bounds__(256, 2) flash_attn_h16(const __half* __restrict__ qkv,
                                                         __half* __restrict__ ctx)
{
    extern __shared__ uint32_t usm[];
    uint32_t* Qs = usm;                       // [128][36]
    uint32_t* Ps = Qs + 128*FSTR;             // [128][36]
    uint32_t* Ks[2] = { Ps + 128*FSTR, Ps + 128*FSTR + 64*FSTR };
    uint32_t* Vs[2] = { Ks[1] + 64*FSTR, Ks[1] + 2*64*FSTR };

    int bh = blockIdx.y;
    int b = bh / Hh, h = bh % Hh;
    int q0 = blockIdx.x * 128;
    int tid = threadIdx.x;
    int lane = tid & 31;
    int w = tid >> 5;
    int r4 = lane >> 2;
    int j4 = lane & 3;

    const __half* qbase = qkv + (size_t)(b*Sq)*NQKV + h*DHd;
    const __half* kbase = qbase + Hh*DHd;
    const __half* vbase = qbase + 2*Hh*DHd;

    // ldmatrix lane statics (byte offsets; rows are FSTR*4 = 144 B apart)
    int rowsel = (lane & 7);
    uint32_t qa_base = smem_u32(Qs)
        + (uint32_t)(((w*16 + rowsel + ((lane >> 3) & 1)*8) * FSTR) * 4)
        + (uint32_t)(((lane >> 4) & 1) * 16);
    uint32_t pa_base = qa_base + (uint32_t)(128*FSTR*4);   // Ps directly after Qs
    uint32_t kb_off  = (uint32_t)(((rowsel + ((lane >> 4) & 1)*8) * FSTR) * 4)
        + (uint32_t)(((lane >> 3) & 1) * 16);

    // prologue: stage Q + K0 (one cp.async group), V0 via LDG->STS transpose
    #pragma unroll
    for (int i = tid; i < 128*8; i += 256) {
        int r = i >> 3, seg = i & 7;
        cp_async16(smem_u32(&Qs[r*FSTR + seg*4]),
                   qbase + (size_t)(q0 + r)*NQKV + seg*8);
    }
    #pragma unroll
    for (int i = tid; i < 64*8; i += 256) {
        int r = i >> 3, seg = i & 7;
        cp_async16(smem_u32(&Ks[0][r*FSTR + seg*4]),
                   kbase + (size_t)r*NQKV + seg*8);
    }
    cp_commit();
    {
        int tp = tid & 31, eg = tid >> 5;
        const __half* v0p = vbase + (size_t)(2*tp)*NQKV + eg*8;
        uint4 x0 = *(const uint4*)v0p;
        uint4 x1 = *(const uint4*)(v0p + NQKV);
        const unsigned short* h0 = (const unsigned short*)&x0;
        const unsigned short* h1 = (const unsigned short*)&x1;
        #pragma unroll
        for (int j = 0; j < 8; j++)
            Vs[0][(eg*8 + j)*FSTR + tp] = (uint32_t)h0[j] | ((uint32_t)h1[j] << 16);
    }

    float o[8][4];
    #pragma unroll
    for (int nt = 0; nt < 8; nt++)
        #pragma unroll
        for (int q = 0; q < 4; q++) o[nt][q] = 0.0f;
    float mreg[2] = {-INFINITY, -INFINITY};
    float lreg[2] = {0.0f, 0.0f};

    int prow = w*16 + r4;

    for (int kt = 0; kt < NTILES; kt++) {
        int cur = kt & 1, nxt = cur ^ 1;
        __syncthreads();   // buf[nxt] free (all reads done); prior V STS visible

        if (kt + 1 < NTILES) {
            // prefetch K(kt+1)
            #pragma unroll
            for (int i = tid; i < 64*8; i += 256) {
                int r = i >> 3, seg = i & 7;
                cp_async16(smem_u32(&Ks[nxt][r*FSTR + seg*4]),
                           kbase + (size_t)((kt+1)*64 + r)*NQKV + seg*8);
            }
            cp_commit();
            // prefetch V(kt+1) via LDG->STS transpose
            {
                int tp = tid & 31, eg = tid >> 5;
                const __half* v0p = vbase + (size_t)((kt+1)*64 + 2*tp)*NQKV + eg*8;
                uint4 x0 = *(const uint4*)v0p;
                uint4 x1 = *(const uint4*)(v0p + NQKV);
                const unsigned short* h0 = (const unsigned short*)&x0;
                const unsigned short* h1 = (const unsigned short*)&x1;
                #pragma unroll
                for (int j = 0; j < 8; j++)
                    Vs[nxt][(eg*8 + j)*FSTR + tp] = (uint32_t)h0[j] | ((uint32_t)h1[j] << 16);
            }
            cp_wait_1();    // K(kt) landed; K(kt+1) may be in flight
        } else {
            cp_wait_all();
        }
        __syncthreads();   // K(kt) visible to all

        uint32_t kB = smem_u32(Ks[cur]) + kb_off;
        uint32_t vB = smem_u32(Vs[cur]) + kb_off;

        // S = Q K^T : 4 k16 steps, ldmatrix fragments
        float s[8][4];
        #pragma unroll
        for (int nt = 0; nt < 8; nt++)
            #pragma unroll
            for (int q = 0; q < 4; q++) s[nt][q] = 0.0f;

        #pragma unroll
        for (int ks = 0; ks < 4; ks++) {
            uint32_t a[4];
            ldsm_x4(a[0], a[1], a[2], a[3], qa_base + ks*32);
            #pragma unroll
            for (int p = 0; p < 4; p++) {
                uint32_t b0, b1, b2, b3;
                ldsm_x4(b0, b1, b2, b3, kB + (uint32_t)(p*16*FSTR*4) + ks*32);
                uint32_t bf0[2] = {b0, b1};
                uint32_t bf1[2] = {b2, b3};
                mma_f16(s[2*p],   a, bf0);
                mma_f16(s[2*p+1], a, bf1);
            }
        }

        // online softmax (rows prow, prow+8), quad reductions
        float mx0 = -INFINITY, mx1 = -INFINITY;
        #pragma unroll
        for (int nt = 0; nt < 8; nt++) {
            mx0 = fmaxf(mx0, fmaxf(s[nt][0], s[nt][1]));
            mx1 = fmaxf(mx1, fmaxf(s[nt][2], s[nt][3]));
        }
        mx0 = fmaxf(mx0, __shfl_xor_sync(0xffffffffu, mx0, 1));
        mx0 = fmaxf(mx0, __shfl_xor_sync(0xffffffffu, mx0, 2));
        mx1 = fmaxf(mx1, __shfl_xor_sync(0xffffffffu, mx1, 1));
        mx1 = fmaxf(mx1, __shfl_xor_sync(0xffffffffu, mx1, 2));

        float mn0 = fmaxf(mreg[0], mx0);
        float mn1 = fmaxf(mreg[1], mx1);
        float al0 = __expf(mreg[0] - mn0);
        float al1 = __expf(mreg[1] - mn1);

        float sum0 = 0.0f, sum1 = 0.0f;
        #pragma unroll
        for (int nt = 0; nt < 8; nt++) {
            s[nt][0] = __expf(s[nt][0] - mn0);
            s[nt][1] = __expf(s[nt][1] - mn0);
            s[nt][2] = __expf(s[nt][2] - mn1);
            s[nt][3] = __expf(s[nt][3] - mn1);
            sum0 += s[nt][0] + s[nt][1];
            sum1 += s[nt][2] + s[nt][3];
        }
        sum0 += __shfl_xor_sync(0xffffffffu, sum0, 1);
        sum0 += __shfl_xor_sync(0xffffffffu, sum0, 2);
        sum1 += __shfl_xor_sync(0xffffffffu, sum1, 1);
        sum1 += __shfl_xor_sync(0xffffffffu, sum1, 2);

        lreg[0] = lreg[0]*al0 + sum0;  mreg[0] = mn0;
        lreg[1] = lreg[1]*al1 + sum1;  mreg[1] = mn1;

        #pragma unroll
        for (int nt = 0; nt < 8; nt++) {
            o[nt][0] *= al0; o[nt][1] *= al0;
            o[nt][2] *= al1; o[nt][3] *= al1;
        }

        // P -> half2 in A-frag layout (own rows only)
        #pragma unroll
        for (int nt = 0; nt < 8; nt++) {
            Ps[prow*FSTR + nt*4 + j4]     = pack_h2(s[nt][0], s[nt][1]);
            Ps[(prow+8)*FSTR + nt*4 + j4] = pack_h2(s[nt][2], s[nt][3]);
        }
        __syncwarp();

        // O += P V : ldmatrix fragments
        #pragma unroll
        for (int ks = 0; ks < 4; ks++) {
            uint32_t a[4];
            ldsm_x4(a[0], a[1], a[2], a[3], pa_base + ks*32);
            #pragma unroll
            for (int p = 0; p < 4; p++) {
                uint32_t b0, b1, b2, b3;
                ldsm_x4(b0, b1, b2, b3, vB + (uint32_t)(p*16*FSTR*4) + ks*32);
                uint32_t bf0[2] = {b0, b1};
                uint32_t bf1[2] = {b2, b3};
                mma_f16(o[2*p],   a, bf0);
                mma_f16(o[2*p+1], a, bf1);
            }
        }
    }

    float inv0 = 1.0f / lreg[0];
    float inv1 = 1.0f / lreg[1];
    int gr0 = q0 + prow;
    int gr1 = gr0 + 8;
    #pragma unroll
    for (int nt = 0; nt < 8; nt++) {
        int c = nt*8 + 2*j4;
        *(__half2*)&ctx[((size_t)(b*Sq + gr0)*Hh + h)*DHd + c] =
            __floats2half2_rn(o[nt][0]*inv0, o[nt][1]*inv0);
        *(__half2*)&ctx[((size_t)(b*Sq + gr1)*Hh + h)*DHd + c] =
            __floats2half2_rn(o[nt][2]*inv1, o[nt][3]*inv1);
    }
}

// ---------------------------------------------------------------------------
// Launch
// ---------------------------------------------------------------------------
extern "C" void kernel_launch(void* const* d_in, const int* in_sizes, int n_in,
                              void* d_out, int out_size)
{
    (void)in_sizes; (void)n_in; (void)out_size;
    const float* x     = (const float*)d_in[0];
    const float* ln1_w = (const float*)d_in[1];
    const float* ln1_b = (const float*)d_in[2];
    const float* ln2_w = (const float*)d_in[3];
    const float* ln2_b = (const float*)d_in[4];
    const float* Wq    = (const float*)d_in[5];
    const float* bq    = (const float*)d_in[6];
    const float* Wk    = (const float*)d_in[7];
    const float* bk    = (const float*)d_in[8];
    const float* Wv    = (const float*)d_in[9];
    const float* bv    = (const float*)d_in[10];
    const float* Wo    = (const float*)d_in[11];
    const float* bo    = (const float*)d_in[12];
    const float* fc1_w = (const float*)d_in[13];
    const float* fc1_b = (const float*)d_in[14];
    const float* fc2_w = (const float*)d_in[15];
    const float* fc2_b = (const float*)d_in[16];
    float* out = (float*)d_out;

    __half *p_wqkv, *p_wo, *p_fc1, *p_fc2, *p_h1, *p_qkv, *p_ctx, *p_h2, *p_a1;
    float *p_bqkv, *p_y1;
    cudaGetSymbolAddress((void**)&p_wqkv, g_wqkv_h);
    cudaGetSymbolAddress((void**)&p_bqkv, g_bqkv);
    cudaGetSymbolAddress((void**)&p_wo,   g_wo_h);
    cudaGetSymbolAddress((void**)&p_fc1,  g_fc1_h);
    cudaGetSymbolAddress((void**)&p_fc2,  g_fc2_h);
    cudaGetSymbolAddress((void**)&p_h1,   g_h1);
    cudaGetSymbolAddress((void**)&p_qkv,  g_qkv);
    cudaGetSymbolAddress((void**)&p_ctx,  g_ctx);
    cudaGetSymbolAddress((void**)&p_y1,   g_y1);
    cudaGetSymbolAddress((void**)&p_h2,   g_h2);
    cudaGetSymbolAddress((void**)&p_a1,   g_a1);

    static int fa_attr_set = 0;
    if (!fa_attr_set) {
        cudaFuncSetAttribute(flash_attn_h16,
                             cudaFuncAttributeMaxDynamicSharedMemorySize, (int)FAH_SMEM);
        fa_attr_set = 1;
    }

    // 0. weight conversion: transpose to col-major half
    conv_t<<<dim3(Dm/32, Dm/32), dim3(32,8)>>>(Wo,    p_wo,  Dm, Dm);
    conv_t<<<dim3(Ff/32, Dm/32), dim3(32,8)>>>(fc1_w, p_fc1, Dm, Ff);
    conv_t<<<dim3(Dm/32, Ff/32), dim3(32,8)>>>(fc2_w, p_fc2, Ff, Dm);

    // 1. repack QKV weights (col-major half, Wq/bq pre-scaled 1/8) + bias
    repack_qkv_kernel<<<(Dm*NQKV + 255)/256, 256>>>(Wq, bq, Wk, bk, Wv, bv);

    // 2. ln1(x) -> h1 (half)
    ln_kernel<<<Mrows/8, 256>>>(x, ln1_w, ln1_b, p_h1);

    // 3. qkv = h1 @ Wqkv + bqkv   [8192, 2304] half
    hgemm128<1|16><<<dim3(NQKV/128, Mrows/128), 256>>>(p_h1, p_wqkv, p_bqkv, nullptr,
                                                       (void*)p_qkv, Mrows, NQKV, Dm);

    // 4-6. fp16 tensor-core attention -> ctx [8192, 768] half
    flash_attn_h16<<<dim3(Sq/128, Bsz*Hh), 256, FAH_SMEM>>>(p_qkv, p_ctx);

    // 7. y1 = x + ctx @ Wo + bo  (f32)
    hgemm128<1|4><<<dim3(Dm/128, Mrows/128), 256>>>(p_ctx, p_wo, bo, x,
                                                    (void*)p_y1, Mrows, Dm, Dm);

    // 8. h2 = ln2(y1) (half)
    ln_kernel<<<Mrows/8, 256>>>(p_y1, ln2_w, ln2_b, p_h2);

    // 9. a1 = gelu(h2 @ fc1_w + fc1_b) (half)
    hgemm128<1|2|16><<<dim3(Ff/128, Mrows/128), 256>>>(p_h2, p_fc1, fc1_b, nullptr,
                                                       (void*)p_a1, Mrows, Ff, Dm);

    // 10. out = y1 + a1 @ fc2_w + fc2_b  (f32)
    hgemm128<1|4><<<dim3(Dm/128, Mrows/128), 256>>>(p_a1, p_fc2, fc2_b, p_y1,
                                                    (void*)out, Mrows, Dm, Ff);
}

// round 14
// speedup vs baseline: 6.2202x; 1.0110x over previous
#include <cuda_runtime.h>
#include <cuda_fp16.h>
#include <math.h>
#include <stdint.h>

// ---------------------------------------------------------------------------
// Problem dims
// ---------------------------------------------------------------------------
#define Bsz 8
#define Sq  1024
#define Dm  768
#define Hh  12
#define DHd 64
#define Ff  3072
#define Mrows (Bsz*Sq)        // 8192
#define NQKV  (3*Hh*DHd)      // 2304
#define LN_EPS 1e-5f

// ---------------------------------------------------------------------------
// Scratch (static device globals; no runtime allocation)
// ---------------------------------------------------------------------------
__device__ __half g_wqkv_h[(size_t)NQKV*Dm];   // col-major [N][K]; Wq part pre-scaled by 1/8
__device__ float  g_bqkv[NQKV];                // bq part pre-scaled by 1/8
__device__ __half g_wo_h[Dm*Dm];               // col-major [N][K]
__device__ __half g_fc1_h[(size_t)Ff*Dm];      // col-major
__device__ __half g_fc2_h[(size_t)Dm*Ff];      // col-major
__device__ __half g_h1[(size_t)Mrows*Dm];      // ln1(x) half
__device__ __half g_qkv[(size_t)Mrows*NQKV];   // half (q pre-scaled by 1/8)
__device__ __half g_ctx[(size_t)Mrows*Dm];     // [b,s,h,e] half
__device__ float  g_y1[(size_t)Mrows*Dm];      // residual f32
__device__ __half g_h2[(size_t)Mrows*Dm];      // ln2(y1) half
__device__ __half g_a1[(size_t)Mrows*Ff];      // gelu(fc1) half

// ---------------------------------------------------------------------------
// PTX helpers
// ---------------------------------------------------------------------------
__device__ __forceinline__ uint32_t smem_u32(const void* p) {
    return (uint32_t)__cvta_generic_to_shared(p);
}
__device__ __forceinline__ void cp_async16(uint32_t saddr, const void* g) {
    asm volatile("cp.async.cg.shared.global [%0], [%1], 16;" :: "r"(saddr), "l"(g));
}
__device__ __forceinline__ void cp_commit() { asm volatile("cp.async.commit_group;"); }
__device__ __forceinline__ void cp_wait_all() { asm volatile("cp.async.wait_group 0;"); }

__device__ __forceinline__ void mma_f16(float* c, const uint32_t* a, const uint32_t* b) {
    asm volatile("mma.sync.aligned.m16n8k16.row.col.f32.f16.f16.f32 "
        "{%0,%1,%2,%3}, {%4,%5,%6,%7}, {%8,%9}, {%0,%1,%2,%3};"
        : "+f"(c[0]), "+f"(c[1]), "+f"(c[2]), "+f"(c[3])
        : "r"(a[0]), "r"(a[1]), "r"(a[2]), "r"(a[3]), "r"(b[0]), "r"(b[1]));
}

__device__ __forceinline__ void ldsm_x4(uint32_t& r0, uint32_t& r1, uint32_t& r2,
                                        uint32_t& r3, uint32_t addr) {
    asm volatile("ldmatrix.sync.aligned.m8n8.x4.shared.b16 {%0,%1,%2,%3}, [%4];"
        : "=r"(r0), "=r"(r1), "=r"(r2), "=r"(r3) : "r"(addr));
}

__device__ __forceinline__ float gelu_exact(float v) {
    return 0.5f * v * (1.0f + erff(v * 0.70710678118654752440f));
}
__device__ __forceinline__ uint32_t pack_h2(float lo, float hi) {
    __half2 h = __floats2half2_rn(lo, hi);
    return *(uint32_t*)&h;
}

// ---------------------------------------------------------------------------
// Tiled transpose + f32->f16: src [K,N] row-major -> dst [N,K] half
// ---------------------------------------------------------------------------
__global__ void conv_t(const float* __restrict__ src, __half* __restrict__ dst,
                       int K, int N)
{
    __shared__ float t[32][33];
    int n0 = blockIdx.x * 32, k0 = blockIdx.y * 32;
    int tx = threadIdx.x, ty = threadIdx.y;
    #pragma unroll
    for (int i = 0; i < 32; i += 8)
        t[ty + i][tx] = src[(size_t)(k0 + ty + i) * N + n0 + tx];
    __syncthreads();
    #pragma unroll
    for (int i = 0; i < 32; i += 8)
        dst[(size_t)(n0 + ty + i) * K + k0 + tx] = __float2half(t[tx][ty + i]);
}

// ---------------------------------------------------------------------------
// Repack per-head QKV weights -> col-major half [NQKV][Dm] (+ f32 bias).
// Q projection (and bias) pre-scaled by 1/8 (exact power of two).
// ---------------------------------------------------------------------------
__global__ void repack_qkv_kernel(const float* __restrict__ Wq, const float* __restrict__ bq,
                                  const float* __restrict__ Wk, const float* __restrict__ bk,
                                  const float* __restrict__ Wv, const float* __restrict__ bv)
{
    int idx = blockIdx.x * blockDim.x + threadIdx.x;
    if (idx < Dm * NQKV) {
        int c = idx / Dm;
        int d = idx % Dm;
        int proj = c / (Hh*DHd);
        int hc   = c % (Hh*DHd);
        int h = hc / DHd;
        int e = hc % DHd;
        const float* W = (proj == 0) ? Wq : (proj == 1) ? Wk : Wv;
        float v = W[((size_t)h*Dm + d)*DHd + e];
        if (proj == 0) v *= 0.125f;
        g_wqkv_h[(size_t)c*Dm + d] = __float2half(v);
    }
    if (idx < NQKV) {
        int proj = idx / (Hh*DHd);
        int hc   = idx % (Hh*DHd);
        const float* bb = (proj == 0) ? bq : (proj == 1) ? bk : bv;
        g_bqkv[idx] = (proj == 0) ? bb[hc] * 0.125f : bb[hc];
    }
}

// ---------------------------------------------------------------------------
// LayerNorm (768). Warp per row, shfl-only; output half.
// ---------------------------------------------------------------------------
__global__ void __launch_bounds__(256) ln_kernel(const float* __restrict__ x,
                                                 const float* __restrict__ w,
                                                 const float* __restrict__ b,
                                                 __half* __restrict__ out)
{
    int warp = threadIdx.x >> 5;
    int lane = threadIdx.x & 31;
    int row  = blockIdx.x * 8 + warp;
    const float* xr = x + (size_t)row * Dm;
    __half* orow = out + (size_t)row * Dm;

    float4 v[6];
    #pragma unroll
    for (int i = 0; i < 6; i++)
        v[i] = *(const float4*)&xr[(lane + i*32) * 4];

    float s = 0.0f;
    #pragma unroll
    for (int i = 0; i < 6; i++) s += v[i].x + v[i].y + v[i].z + v[i].w;
    #pragma unroll
    for (int o = 16; o > 0; o >>= 1) s += __shfl_xor_sync(0xffffffffu, s, o);
    float mu = s * (1.0f / Dm);

    float vs = 0.0f;
    #pragma unroll
    for (int i = 0; i < 6; i++) {
        float a0 = v[i].x - mu, a1 = v[i].y - mu, a2 = v[i].z - mu, a3 = v[i].w - mu;
        v[i] = make_float4(a0, a1, a2, a3);
        vs += a0*a0 + a1*a1 + a2*a2 + a3*a3;
    }
    #pragma unroll
    for (int o = 16; o > 0; o >>= 1) vs += __shfl_xor_sync(0xffffffffu, vs, o);
    float inv = rsqrtf(vs * (1.0f / Dm) + LN_EPS);

    #pragma unroll
    for (int i = 0; i < 6; i++) {
        int c = (lane + i*32) * 4;
        float4 ww = *(const float4*)&w[c];
        float4 bb = *(const float4*)&b[c];
        *(__half2*)&orow[c]     = __floats2half2_rn(v[i].x * inv * ww.x + bb.x,
                                                    v[i].y * inv * ww.y + bb.y);
        *(__half2*)&orow[c + 2] = __floats2half2_rn(v[i].z * inv * ww.z + bb.z,
                                                    v[i].w * inv * ww.w + bb.w);
    }
}

// ---------------------------------------------------------------------------
// FP16 tensor-core GEMM (validated at 682us): C = A[M,K](row) * B[N,K](col)
// 128x128x32 tiles, mma.m16n8k16, ldmatrix fragment loads.
// Epilogue flags: 1=bias f32, 2=gelu, 4=residual f32, 16=half output
// ---------------------------------------------------------------------------
#define HSTR 40        // halves per smem row (80 B)

template<int EPI>
__global__ void __launch_bounds__(256, 2) hgemm128(const __half* __restrict__ A,
                                                   const __half* __restrict__ Bc,
                                                   const float* __restrict__ bias,
                                                   const float* __restrict__ res,
                                                   void* __restrict__ Cv,
                                                   int M, int N, int K)
{
    __shared__ __half As[2][128*HSTR];
    __shared__ __half Bs[2][128*HSTR];

    int tid  = threadIdx.x;
    int lane = tid & 31;
    int wid  = tid >> 5;
    int wm   = wid & 3;
    int wn   = wid >> 2;
    int row0 = blockIdx.y * 128;
    int col0 = blockIdx.x * 128;

    int lr = tid >> 2;
    int lc = (tid & 3) << 3;

    const __half* Ag = A  + (size_t)(row0 + lr) * K + lc;
    const __half* Bg = Bc + (size_t)(col0 + lr) * K + lc;

    float acc[2][8][4];
    #pragma unroll
    for (int mt = 0; mt < 2; mt++)
        #pragma unroll
        for (int nt = 0; nt < 8; nt++)
            #pragma unroll
            for (int q = 0; q < 4; q++) acc[mt][nt][q] = 0.0f;

    int nk = K / 32;

    {
        cp_async16(smem_u32(&As[0][lr*HSTR + lc]),        Ag);
        cp_async16(smem_u32(&As[0][(lr+64)*HSTR + lc]),   Ag + (size_t)64*K);
        cp_async16(smem_u32(&Bs[0][lr*HSTR + lc]),        Bg);
        cp_async16(smem_u32(&Bs[0][(lr+64)*HSTR + lc]),   Bg + (size_t)64*K);
        cp_commit();
    }

    int row_a  = wm*32 + (lane & 7) + ((lane >> 3) & 1) * 8;
    int koff_a = ((lane >> 4) & 1) * 8;
    int row_b  = wn*64 + (lane & 7) + ((lane >> 4) & 1) * 8;
    int koff_b = ((lane >> 3) & 1) * 8;

    int mrow = wm*32 + (lane >> 2);

    for (int kt = 0; kt < nk; kt++) {
        cp_wait_all();
        __syncthreads();
        int cur = kt & 1;

        if (kt + 1 < nk) {
            int nxt = cur ^ 1;
            const __half* Agn = Ag + (size_t)(kt+1)*32;
            const __half* Bgn = Bg + (size_t)(kt+1)*32;
            cp_async16(smem_u32(&As[nxt][lr*HSTR + lc]),      Agn);
            cp_async16(smem_u32(&As[nxt][(lr+64)*HSTR + lc]), Agn + (size_t)64*K);
            cp_async16(smem_u32(&Bs[nxt][lr*HSTR + lc]),      Bgn);
            cp_async16(smem_u32(&Bs[nxt][(lr+64)*HSTR + lc]), Bgn + (size_t)64*K);
            cp_commit();
        }

        uint32_t aB = smem_u32(As[cur]);
        uint32_t bB = smem_u32(Bs[cur]);

        #pragma unroll
        for (int ks = 0; ks < 2; ks++) {
            uint32_t af[2][4];
            #pragma unroll
            for (int mt = 0; mt < 2; mt++)
                ldsm_x4(af[mt][0], af[mt][1], af[mt][2], af[mt][3],
                        aB + (uint32_t)(((row_a + mt*16)*HSTR + ks*16 + koff_a) * 2));
            #pragma unroll
            for (int p = 0; p < 4; p++) {
                uint32_t b0, b1, b2, b3;
                ldsm_x4(b0, b1, b2, b3,
                        bB + (uint32_t)(((row_b + p*16)*HSTR + ks*16 + koff_b) * 2));
                uint32_t bf0[2] = {b0, b1};
                uint32_t bf1[2] = {b2, b3};
                mma_f16(acc[0][2*p],   af[0], bf0);
                mma_f16(acc[1][2*p],   af[1], bf0);
                mma_f16(acc[0][2*p+1], af[0], bf1);
                mma_f16(acc[1][2*p+1], af[1], bf1);
            }
        }
    }

    #pragma unroll
    for (int mt = 0; mt < 2; mt++) {
        #pragma unroll
        for (int i = 0; i < 2; i++) {
            size_t r = row0 + mrow + mt*16 + i*8;
            #pragma unroll
            for (int nt = 0; nt < 8; nt++) {
                int c = col0 + wn*64 + nt*8 + 2*(lane & 3);
                float v0 = acc[mt][nt][2*i + 0];
                float v1 = acc[mt][nt][2*i + 1];
                if (EPI & 1) { v0 += bias[c]; v1 += bias[c+1]; }
                if (EPI & 2) { v0 = gelu_exact(v0); v1 = gelu_exact(v1); }
                if (EPI & 4) {
                    float2 rr = *(const float2*)&res[r * N + c];
                    v0 += rr.x; v1 += rr.y;
                }
                if (EPI & 16) {
                    *(__half2*)&((__half*)Cv)[r * N + c] = __floats2half2_rn(v0, v1);
                } else {
                    *(float2*)&((float*)Cv)[r * N + c] = make_float2(v0, v1);
                }
            }
        }
    }
}

// ---------------------------------------------------------------------------
// FP16 flash attention: double-buffered K/V, ldmatrix fragments,
// ONE __syncthreads per kv-iteration (top barrier covers buffer reuse).
// ---------------------------------------------------------------------------
#define FSTR 36
#define NTILES (Sq/64)
#define FAH_SMEM ((128*FSTR + 128*FSTR + 2*64*FSTR + 2*64*FSTR) * 4)   // 73728 B

__global__ void __launch_bounds__(256, 2) flash_attn_h16(const __half* __restrict__ qkv,
                                                         __half* __restrict__ ctx)
{
    extern __shared__ uint32_t usm[];
    uint32_t* Qs = usm;                       // [128][36]
    uint32_t* Ps = Qs + 128*FSTR;             // [128][36]
    uint32_t* Ks[2] = { Ps + 128*FSTR, Ps + 128*FSTR + 64*FSTR };
    uint32_t* Vs[2] = { Ks[1] + 64*FSTR, Ks[1] + 2*64*FSTR };

    int bh = blockIdx.y;
    int b = bh / Hh, h = bh % Hh;
    int q0 = blockIdx.x * 128;
    int tid = threadIdx.x;
    int lane = tid & 31;
    int w = tid >> 5;
    int r4 = lane >> 2;
    int j4 = lane & 3;

    const __half* qbase = qkv + (size_t)(b*Sq)*NQKV + h*DHd;
    const __half* kbase = qbase + Hh*DHd;
    const __half* vbase = qbase + 2*Hh*DHd;

    int rowsel = (lane & 7);
    uint32_t qa_base = smem_u32(Qs)
        + (uint32_t)(((w*16 + rowsel + ((lane >> 3) & 1)*8) * FSTR) * 4)
        + (uint32_t)(((lane >> 4) & 1) * 16);
    uint32_t pa_base = qa_base + (uint32_t)(128*FSTR*4);
    uint32_t kb_off  = (uint32_t)(((rowsel + ((lane >> 4) & 1)*8) * FSTR) * 4)
        + (uint32_t)(((lane >> 3) & 1) * 16);

    // prologue: stage Q + K0 (one group), V0 via LDG->STS transpose
    #pragma unroll
    for (int i = tid; i < 128*8; i += 256) {
        int r = i >> 3, seg = i & 7;
        cp_async16(smem_u32(&Qs[r*FSTR + seg*4]),
                   qbase + (size_t)(q0 + r)*NQKV + seg*8);
    }
    #pragma unroll
    for (int i = tid; i < 64*8; i += 256) {
        int r = i >> 3, seg = i & 7;
        cp_async16(smem_u32(&Ks[0][r*FSTR + seg*4]),
                   kbase + (size_t)r*NQKV + seg*8);
    }
    cp_commit();
    {
        int tp = tid & 31, eg = tid >> 5;
        const __half* v0p = vbase + (size_t)(2*tp)*NQKV + eg*8;
        uint4 x0 = *(const uint4*)v0p;
        uint4 x1 = *(const uint4*)(v0p + NQKV);
        const unsigned short* h0 = (const unsigned short*)&x0;
        const unsigned short* h1 = (const unsigned short*)&x1;
        #pragma unroll
        for (int j = 0; j < 8; j++)
            Vs[0][(eg*8 + j)*FSTR + tp] = (uint32_t)h0[j] | ((uint32_t)h1[j] << 16);
    }

    float o[8][4];
    #pragma unroll
    for (int nt = 0; nt < 8; nt++)
        #pragma unroll
        for (int q = 0; q < 4; q++) o[nt][q] = 0.0f;
    float mreg[2] = {-INFINITY, -INFINITY};
    float lreg[2] = {0.0f, 0.0f};

    int prow = w*16 + r4;

    for (int kt = 0; kt < NTILES; kt++) {
        int cur = kt & 1, nxt = cur ^ 1;
        // K(kt) landed (committed one iteration ago or in prologue)
        cp_wait_all();
        // Single barrier: proves all warps finished iter kt-1 (so buf[nxt] free
        // for prefetch below) AND makes K(kt)/V(kt) stores visible to all.
        __syncthreads();

        if (kt + 1 < NTILES) {
            #pragma unroll
            for (int i = tid; i < 64*8; i += 256) {
                int r = i >> 3, seg = i & 7;
                cp_async16(smem_u32(&Ks[nxt][r*FSTR + seg*4]),
                           kbase + (size_t)((kt+1)*64 + r)*NQKV + seg*8);
            }
            cp_commit();
            {
                int tp = tid & 31, eg = tid >> 5;
                const __half* v0p = vbase + (size_t)((kt+1)*64 + 2*tp)*NQKV + eg*8;
                uint4 x0 = *(const uint4*)v0p;
                uint4 x1 = *(const uint4*)(v0p + NQKV);
                const unsigned short* h0 = (const unsigned short*)&x0;
                const unsigned short* h1 = (const unsigned short*)&x1;
                #pragma unroll
                for (int j = 0; j < 8; j++)
                    Vs[nxt][(eg*8 + j)*FSTR + tp] = (uint32_t)h0[j] | ((uint32_t)h1[j] << 16);
            }
        }

        uint32_t kB = smem_u32(Ks[cur]) + kb_off;
        uint32_t vB = smem_u32(Vs[cur]) + kb_off;

        // S = Q K^T
        float s[8][4];
        #pragma unroll
        for (int nt = 0; nt < 8; nt++)
            #pragma unroll
            for (int q = 0; q < 4; q++) s[nt][q] = 0.0f;

        #pragma unroll
        for (int ks = 0; ks < 4; ks++) {
            uint32_t a[4];
            ldsm_x4(a[0], a[1], a[2], a[3], qa_base + ks*32);
            #pragma unroll
            for (int p = 0; p < 4; p++) {
                uint32_t b0, b1, b2, b3;
                ldsm_x4(b0, b1, b2, b3, kB + (uint32_t)(p*16*FSTR*4) + ks*32);
                uint32_t bf0[2] = {b0, b1};
                uint32_t bf1[2] = {b2, b3};
                mma_f16(s[2*p],   a, bf0);
                mma_f16(s[2*p+1], a, bf1);
            }
        }

        // online softmax (rows prow, prow+8), quad reductions
        float mx0 = -INFINITY, mx1 = -INFINITY;
        #pragma unroll
        for (int nt = 0; nt < 8; nt++) {
            mx0 = fmaxf(mx0, fmaxf(s[nt][0], s[nt][1]));
            mx1 = fmaxf(mx1, fmaxf(s[nt][2], s[nt][3]));
        }
        mx0 = fmaxf(mx0, __shfl_xor_sync(0xffffffffu, mx0, 1));
        mx0 = fmaxf(mx0, __shfl_xor_sync(0xffffffffu, mx0, 2));
        mx1 = fmaxf(mx1, __shfl_xor_sync(0xffffffffu, mx1, 1));
        mx1 = fmaxf(mx1, __shfl_xor_sync(0xffffffffu, mx1, 2));

        float mn0 = fmaxf(mreg[0], mx0);
        float mn1 = fmaxf(mreg[1], mx1);
        float al0 = __expf(mreg[0] - mn0);
        float al1 = __expf(mreg[1] - mn1);

        float sum0 = 0.0f, sum1 = 0.0f;
        #pragma unroll
        for (int nt = 0; nt < 8; nt++) {
            s[nt][0] = __expf(s[nt][0] - mn0);
            s[nt][1] = __expf(s[nt][1] - mn0);
            s[nt][2] = __expf(s[nt][2] - mn1);
            s[nt][3] = __expf(s[nt][3] - mn1);
            sum0 += s[nt][0] + s[nt][1];
            sum1 += s[nt][2] + s[nt][3];
        }
        sum0 += __shfl_xor_sync(0xffffffffu, sum0, 1);
        sum0 += __shfl_xor_sync(0xffffffffu, sum0, 2);
        sum1 += __shfl_xor_sync(0xffffffffu, sum1, 1);
        sum1 += __shfl_xor_sync(0xffffffffu, sum1, 2);

        lreg[0] = lreg[0]*al0 + sum0;  mreg[0] = mn0;
        lreg[1] = lreg[1]*al1 + sum1;  mreg[1] = mn1;

        #pragma unroll
        for (int nt = 0; nt < 8; nt++) {
            o[nt][0] *= al0; o[nt][1] *= al0;
            o[nt][2] *= al1; o[nt][3] *= al1;
        }

        // P -> half2 in A-frag layout (own rows only)
        #pragma unroll
        for (int nt = 0; nt < 8; nt++) {
            Ps[prow*FSTR + nt*4 + j4]     = pack_h2(s[nt][0], s[nt][1]);
            Ps[(prow+8)*FSTR + nt*4 + j4] = pack_h2(s[nt][2], s[nt][3]);
        }
        __syncwarp();

        // O += P V
        #pragma unroll
        for (int ks = 0; ks < 4; ks++) {
            uint32_t a[4];
            ldsm_x4(a[0], a[1], a[2], a[3], pa_base + ks*32);
            #pragma unroll
            for (int p = 0; p < 4; p++) {
                uint32_t b0, b1, b2, b3;
                ldsm_x4(b0, b1, b2, b3, vB + (uint32_t)(p*16*FSTR*4) + ks*32);
                uint32_t bf0[2] = {b0, b1};
                uint32_t bf1[2] = {b2, b3};
                mma_f16(o[2*p],   a, bf0);
                mma_f16(o[2*p+1], a, bf1);
            }
        }
    }

    float inv0 = 1.0f / lreg[0];
    float inv1 = 1.0f / lreg[1];
    int gr0 = q0 + prow;
    int gr1 = gr0 + 8;
    #pragma unroll
    for (int nt = 0; nt < 8; nt++) {
        int c = nt*8 + 2*j4;
        *(__half2*)&ctx[((size_t)(b*Sq + gr0)*Hh + h)*DHd + c] =
            __floats2half2_rn(o[nt][0]*inv0, o[nt][1]*inv0);
        *(__half2*)&ctx[((size_t)(b*Sq + gr1)*Hh + h)*DHd + c] =
            __floats2half2_rn(o[nt][2]*inv1, o[nt][3]*inv1);
    }
}

// ---------------------------------------------------------------------------
// Launch — prep kernels forked onto a second stream (graph fork/join)
// ---------------------------------------------------------------------------
extern "C" void kernel_launch(void* const* d_in, const int* in_sizes, int n_in,
                              void* d_out, int out_size)
{
    (void)in_sizes; (void)n_in; (void)out_size;
    const float* x     = (const float*)d_in[0];
    const float* ln1_w = (const float*)d_in[1];
    const float* ln1_b = (const float*)d_in[2];
    const float* ln2_w = (const float*)d_in[3];
    const float* ln2_b = (const float*)d_in[4];
    const float* Wq    = (const float*)d_in[5];
    const float* bq    = (const float*)d_in[6];
    const float* Wk    = (const float*)d_in[7];
    const float* bk    = (const float*)d_in[8];
    const float* Wv    = (const float*)d_in[9];
    const float* bv    = (const float*)d_in[10];
    const float* Wo    = (const float*)d_in[11];
    const float* bo    = (const float*)d_in[12];
    const float* fc1_w = (const float*)d_in[13];
    const float* fc1_b = (const float*)d_in[14];
    const float* fc2_w = (const float*)d_in[15];
    const float* fc2_b = (const float*)d_in[16];
    float* out = (float*)d_out;

    __half *p_wqkv, *p_wo, *p_fc1, *p_fc2, *p_h1, *p_qkv, *p_ctx, *p_h2, *p_a1;
    float *p_bqkv, *p_y1;
    cudaGetSymbolAddress((void**)&p_wqkv, g_wqkv_h);
    cudaGetSymbolAddress((void**)&p_bqkv, g_bqkv);
    cudaGetSymbolAddress((void**)&p_wo,   g_wo_h);
    cudaGetSymbolAddress((void**)&p_fc1,  g_fc1_h);
    cudaGetSymbolAddress((void**)&p_fc2,  g_fc2_h);
    cudaGetSymbolAddress((void**)&p_h1,   g_h1);
    cudaGetSymbolAddress((void**)&p_qkv,  g_qkv);
    cudaGetSymbolAddress((void**)&p_ctx,  g_ctx);
    cudaGetSymbolAddress((void**)&p_y1,   g_y1);
    cudaGetSymbolAddress((void**)&p_h2,   g_h2);
    cudaGetSymbolAddress((void**)&p_a1,   g_a1);

    static cudaStream_t s2 = nullptr;
    static cudaEvent_t ev_fork = nullptr, ev_repack = nullptr, ev_conv = nullptr;
    static int fa_attr_set = 0;
    if (!fa_attr_set) {
        cudaFuncSetAttribute(flash_attn_h16,
                             cudaFuncAttributeMaxDynamicSharedMemorySize, (int)FAH_SMEM);
        cudaStreamCreateWithFlags(&s2, cudaStreamNonBlocking);
        cudaEventCreateWithFlags(&ev_fork,   cudaEventDisableTiming);
        cudaEventCreateWithFlags(&ev_repack, cudaEventDisableTiming);
        cudaEventCreateWithFlags(&ev_conv,   cudaEventDisableTiming);
        fa_attr_set = 1;
    }

    // fork side stream from the (capture) default stream
    cudaEventRecord(ev_fork, 0);
    cudaStreamWaitEvent(s2, ev_fork, 0);

    // side stream: repack (needed by step 3), then weight transposes (needed by 7/9/10)
    repack_qkv_kernel<<<(Dm*NQKV + 255)/256, 256, 0, s2>>>(Wq, bq, Wk, bk, Wv, bv);
    cudaEventRecord(ev_repack, s2);
    conv_t<<<dim3(Dm/32, Dm/32), dim3(32,8), 0, s2>>>(Wo,    p_wo,  Dm, Dm);
    conv_t<<<dim3(Ff/32, Dm/32), dim3(32,8), 0, s2>>>(fc1_w, p_fc1, Dm, Ff);
    conv_t<<<dim3(Dm/32, Ff/32), dim3(32,8), 0, s2>>>(fc2_w, p_fc2, Ff, Dm);
    cudaEventRecord(ev_conv, s2);

    // main stream: ln1 overlaps repack
    ln_kernel<<<Mrows/8, 256>>>(x, ln1_w, ln1_b, p_h1);

    // join 1: repack done before QKV GEMM
    cudaStreamWaitEvent(0, ev_repack, 0);

    // 3. qkv = h1 @ Wqkv + bqkv   [8192, 2304] half
    hgemm128<1|16><<<dim3(NQKV/128, Mrows/128), 256>>>(p_h1, p_wqkv, p_bqkv, nullptr,
                                                       (void*)p_qkv, Mrows, NQKV, Dm);

    // 4-6. fp16 tensor-core attention -> ctx [8192, 768] half
    flash_attn_h16<<<dim3(Sq/128, Bsz*Hh), 256, FAH_SMEM>>>(p_qkv, p_ctx);

    // join 2: weight transposes done before Wo GEMM (covers fc1/fc2 too)
    cudaStreamWaitEvent(0, ev_conv, 0);

    // 7. y1 = x + ctx @ Wo + bo  (f32)
    hgemm128<1|4><<<dim3(Dm/128, Mrows/128), 256>>>(p_ctx, p_wo, bo, x,
                                                    (void*)p_y1, Mrows, Dm, Dm);

    // 8. h2 = ln2(y1) (half)
    ln_kernel<<<Mrows/8, 256>>>(p_y1, ln2_w, ln2_b, p_h2);

    // 9. a1 = gelu(h2 @ fc1_w + fc1_b) (half)
    hgemm128<1|2|16><<<dim3(Ff/128, Mrows/128), 256>>>(p_h2, p_fc1, fc1_b, nullptr,
                                                       (void*)p_a1, Mrows, Ff, Dm);

    // 10. out = y1 + a1 @ fc2_w + fc2_b  (f32)
    hgemm128<1|4><<<dim3(Dm/128, Mrows/128), 256>>>(p_a1, p_fc2, fc2_b, p_y1,
                                                    (void*)out, Mrows, Dm, Ff);
}

// round 17
// speedup vs baseline: 6.2603x; 1.0064x over previous
#include <cuda_runtime.h>
#include <cuda_fp16.h>
#include <math.h>
#include <stdint.h>

// ---------------------------------------------------------------------------
// Problem dims
// ---------------------------------------------------------------------------
#define Bsz 8
#define Sq  1024
#define Dm  768
#define Hh  12
#define DHd 64
#define Ff  3072
#define Mrows (Bsz*Sq)        // 8192
#define NQKV  (3*Hh*DHd)      // 2304
#define LN_EPS 1e-5f

// ---------------------------------------------------------------------------
// Scratch (static device globals; no runtime allocation)
// ---------------------------------------------------------------------------
__device__ __half g_wqkv_h[(size_t)NQKV*Dm];   // col-major [N][K]; Wq part pre-scaled by 1/8
__device__ float  g_bqkv[NQKV];                // bq part pre-scaled by 1/8
__device__ __half g_wo_h[Dm*Dm];               // col-major [N][K]
__device__ __half g_fc1_h[(size_t)Ff*Dm];      // col-major
__device__ __half g_fc2_h[(size_t)Dm*Ff];      // col-major
__device__ __half g_h1[(size_t)Mrows*Dm];      // ln1(x) half
__device__ __half g_qkv[(size_t)Mrows*NQKV];   // half (q pre-scaled by 1/8)
__device__ __half g_ctx[(size_t)Mrows*Dm];     // [b,s,h,e] half
__device__ float  g_y1[(size_t)Mrows*Dm];      // residual f32
__device__ __half g_h2[(size_t)Mrows*Dm];      // ln2(y1) half
__device__ __half g_a1[(size_t)Mrows*Ff];      // gelu(fc1) half

// ---------------------------------------------------------------------------
// PTX helpers
// ---------------------------------------------------------------------------
__device__ __forceinline__ uint32_t smem_u32(const void* p) {
    return (uint32_t)__cvta_generic_to_shared(p);
}
__device__ __forceinline__ void cp_async16(uint32_t saddr, const void* g) {
    asm volatile("cp.async.cg.shared.global [%0], [%1], 16;" :: "r"(saddr), "l"(g));
}
__device__ __forceinline__ void cp_commit() { asm volatile("cp.async.commit_group;"); }
__device__ __forceinline__ void cp_wait_all() { asm volatile("cp.async.wait_group 0;"); }

__device__ __forceinline__ void mma_f16(float* c, const uint32_t* a, const uint32_t* b) {
    asm volatile("mma.sync.aligned.m16n8k16.row.col.f32.f16.f16.f32 "
        "{%0,%1,%2,%3}, {%4,%5,%6,%7}, {%8,%9}, {%0,%1,%2,%3};"
        : "+f"(c[0]), "+f"(c[1]), "+f"(c[2]), "+f"(c[3])
        : "r"(a[0]), "r"(a[1]), "r"(a[2]), "r"(a[3]), "r"(b[0]), "r"(b[1]));
}

__device__ __forceinline__ void ldsm_x4(uint32_t& r0, uint32_t& r1, uint32_t& r2,
                                        uint32_t& r3, uint32_t addr) {
    asm volatile("ldmatrix.sync.aligned.m8n8.x4.shared.b16 {%0,%1,%2,%3}, [%4];"
        : "=r"(r0), "=r"(r1), "=r"(r2), "=r"(r3) : "r"(addr));
}

__device__ __forceinline__ float gelu_exact(float v) {
    return 0.5f * v * (1.0f + erff(v * 0.70710678118654752440f));
}
__device__ __forceinline__ uint32_t pack_h2(float lo, float hi) {
    __half2 h = __floats2half2_rn(lo, hi);
    return *(uint32_t*)&h;
}

// ---------------------------------------------------------------------------
// Tiled transpose + f32->f16: src [K,N] row-major -> dst [N,K] half
// ---------------------------------------------------------------------------
__global__ void conv_t(const float* __restrict__ src, __half* __restrict__ dst,
                       int K, int N)
{
    __shared__ float t[32][33];
    int n0 = blockIdx.x * 32, k0 = blockIdx.y * 32;
    int tx = threadIdx.x, ty = threadIdx.y;
    #pragma unroll
    for (int i = 0; i < 32; i += 8)
        t[ty + i][tx] = src[(size_t)(k0 + ty + i) * N + n0 + tx];
    __syncthreads();
    #pragma unroll
    for (int i = 0; i < 32; i += 8)
        dst[(size_t)(n0 + ty + i) * K + k0 + tx] = __float2half(t[tx][ty + i]);
}

// ---------------------------------------------------------------------------
// Repack per-head QKV weights -> col-major half [NQKV][Dm] (+ f32 bias).
// Q projection (and bias) pre-scaled by 1/8 (exact power of two).
// ---------------------------------------------------------------------------
__global__ void repack_qkv_kernel(const float* __restrict__ Wq, const float* __restrict__ bq,
                                  const float* __restrict__ Wk, const float* __restrict__ bk,
                                  const float* __restrict__ Wv, const float* __restrict__ bv)
{
    int idx = blockIdx.x * blockDim.x + threadIdx.x;
    if (idx < Dm * NQKV) {
        int c = idx / Dm;
        int d = idx % Dm;
        int proj = c / (Hh*DHd);
        int hc   = c % (Hh*DHd);
        int h = hc / DHd;
        int e = hc % DHd;
        const float* W = (proj == 0) ? Wq : (proj == 1) ? Wk : Wv;
        float v = W[((size_t)h*Dm + d)*DHd + e];
        if (proj == 0) v *= 0.125f;
        g_wqkv_h[(size_t)c*Dm + d] = __float2half(v);
    }
    if (idx < NQKV) {
        int proj = idx / (Hh*DHd);
        int hc   = idx % (Hh*DHd);
        const float* bb = (proj == 0) ? bq : (proj == 1) ? bk : bv;
        g_bqkv[idx] = (proj == 0) ? bb[hc] * 0.125f : bb[hc];
    }
}

// ---------------------------------------------------------------------------
// LayerNorm (768). Warp per row, shfl-only; output half.
// ---------------------------------------------------------------------------
__global__ void __launch_bounds__(256) ln_kernel(const float* __restrict__ x,
                                                 const float* __restrict__ w,
                                                 const float* __restrict__ b,
                                                 __half* __restrict__ out)
{
    int warp = threadIdx.x >> 5;
    int lane = threadIdx.x & 31;
    int row  = blockIdx.x * 8 + warp;
    const float* xr = x + (size_t)row * Dm;
    __half* orow = out + (size_t)row * Dm;

    float4 v[6];
    #pragma unroll
    for (int i = 0; i < 6; i++)
        v[i] = *(const float4*)&xr[(lane + i*32) * 4];

    float s = 0.0f;
    #pragma unroll
    for (int i = 0; i < 6; i++) s += v[i].x + v[i].y + v[i].z + v[i].w;
    #pragma unroll
    for (int o = 16; o > 0; o >>= 1) s += __shfl_xor_sync(0xffffffffu, s, o);
    float mu = s * (1.0f / Dm);

    float vs = 0.0f;
    #pragma unroll
    for (int i = 0; i < 6; i++) {
        float a0 = v[i].x - mu, a1 = v[i].y - mu, a2 = v[i].z - mu, a3 = v[i].w - mu;
        v[i] = make_float4(a0, a1, a2, a3);
        vs += a0*a0 + a1*a1 + a2*a2 + a3*a3;
    }
    #pragma unroll
    for (int o = 16; o > 0; o >>= 1) vs += __shfl_xor_sync(0xffffffffu, vs, o);
    float inv = rsqrtf(vs * (1.0f / Dm) + LN_EPS);

    #pragma unroll
    for (int i = 0; i < 6; i++) {
        int c = (lane + i*32) * 4;
        float4 ww = *(const float4*)&w[c];
        float4 bb = *(const float4*)&b[c];
        *(__half2*)&orow[c]     = __floats2half2_rn(v[i].x * inv * ww.x + bb.x,
                                                    v[i].y * inv * ww.y + bb.y);
        *(__half2*)&orow[c + 2] = __floats2half2_rn(v[i].z * inv * ww.z + bb.z,
                                                    v[i].w * inv * ww.w + bb.w);
    }
}

// ---------------------------------------------------------------------------
// FP16 tensor-core GEMM (validated): C = A[M,K](row) * B[N,K](col)
// 128x128x32 tiles, mma.m16n8k16, ldmatrix fragment loads.
// Epilogue flags: 1=bias f32, 2=gelu, 4=residual f32, 16=half output
// ---------------------------------------------------------------------------
#define HSTR 40        // halves per smem row (80 B)

template<int EPI>
__global__ void __launch_bounds__(256, 2) hgemm128(const __half* __restrict__ A,
                                                   const __half* __restrict__ Bc,
                                                   const float* __restrict__ bias,
                                                   const float* __restrict__ res,
                                                   void* __restrict__ Cv,
                                                   int M, int N, int K)
{
    __shared__ __half As[2][128*HSTR];
    __shared__ __half Bs[2][128*HSTR];

    int tid  = threadIdx.x;
    int lane = tid & 31;
    int wid  = tid >> 5;
    int wm   = wid & 3;
    int wn   = wid >> 2;
    int row0 = blockIdx.y * 128;
    int col0 = blockIdx.x * 128;

    int lr = tid >> 2;
    int lc = (tid & 3) << 3;

    const __half* Ag = A  + (size_t)(row0 + lr) * K + lc;
    const __half* Bg = Bc + (size_t)(col0 + lr) * K + lc;

    float acc[2][8][4];
    #pragma unroll
    for (int mt = 0; mt < 2; mt++)
        #pragma unroll
        for (int nt = 0; nt < 8; nt++)
            #pragma unroll
            for (int q = 0; q < 4; q++) acc[mt][nt][q] = 0.0f;

    int nk = K / 32;

    {
        cp_async16(smem_u32(&As[0][lr*HSTR + lc]),        Ag);
        cp_async16(smem_u32(&As[0][(lr+64)*HSTR + lc]),   Ag + (size_t)64*K);
        cp_async16(smem_u32(&Bs[0][lr*HSTR + lc]),        Bg);
        cp_async16(smem_u32(&Bs[0][(lr+64)*HSTR + lc]),   Bg + (size_t)64*K);
        cp_commit();
    }

    int row_a  = wm*32 + (lane & 7) + ((lane >> 3) & 1) * 8;
    int koff_a = ((lane >> 4) & 1) * 8;
    int row_b  = wn*64 + (lane & 7) + ((lane >> 4) & 1) * 8;
    int koff_b = ((lane >> 3) & 1) * 8;

    int mrow = wm*32 + (lane >> 2);

    for (int kt = 0; kt < nk; kt++) {
        cp_wait_all();
        __syncthreads();
        int cur = kt & 1;

        if (kt + 1 < nk) {
            int nxt = cur ^ 1;
            const __half* Agn = Ag + (size_t)(kt+1)*32;
            const __half* Bgn = Bg + (size_t)(kt+1)*32;
            cp_async16(smem_u32(&As[nxt][lr*HSTR + lc]),      Agn);
            cp_async16(smem_u32(&As[nxt][(lr+64)*HSTR + lc]), Agn + (size_t)64*K);
            cp_async16(smem_u32(&Bs[nxt][lr*HSTR + lc]),      Bgn);
            cp_async16(smem_u32(&Bs[nxt][(lr+64)*HSTR + lc]), Bgn + (size_t)64*K);
            cp_commit();
        }

        uint32_t aB = smem_u32(As[cur]);
        uint32_t bB = smem_u32(Bs[cur]);

        #pragma unroll
        for (int ks = 0; ks < 2; ks++) {
            uint32_t af[2][4];
            #pragma unroll
            for (int mt = 0; mt < 2; mt++)
                ldsm_x4(af[mt][0], af[mt][1], af[mt][2], af[mt][3],
                        aB + (uint32_t)(((row_a + mt*16)*HSTR + ks*16 + koff_a) * 2));
            #pragma unroll
            for (int p = 0; p < 4; p++) {
                uint32_t b0, b1, b2, b3;
                ldsm_x4(b0, b1, b2, b3,
                        bB + (uint32_t)(((row_b + p*16)*HSTR + ks*16 + koff_b) * 2));
                uint32_t bf0[2] = {b0, b1};
                uint32_t bf1[2] = {b2, b3};
                mma_f16(acc[0][2*p],   af[0], bf0);
                mma_f16(acc[1][2*p],   af[1], bf0);
                mma_f16(acc[0][2*p+1], af[0], bf1);
                mma_f16(acc[1][2*p+1], af[1], bf1);
            }
        }
    }

    #pragma unroll
    for (int mt = 0; mt < 2; mt++) {
        #pragma unroll
        for (int i = 0; i < 2; i++) {
            size_t r = row0 + mrow + mt*16 + i*8;
            #pragma unroll
            for (int nt = 0; nt < 8; nt++) {
                int c = col0 + wn*64 + nt*8 + 2*(lane & 3);
                float v0 = acc[mt][nt][2*i + 0];
                float v1 = acc[mt][nt][2*i + 1];
                if (EPI & 1) { v0 += bias[c]; v1 += bias[c+1]; }
                if (EPI & 2) { v0 = gelu_exact(v0); v1 = gelu_exact(v1); }
                if (EPI & 4) {
                    float2 rr = *(const float2*)&res[r * N + c];
                    v0 += rr.x; v1 += rr.y;
                }
                if (EPI & 16) {
                    *(__half2*)&((__half*)Cv)[r * N + c] = __floats2half2_rn(v0, v1);
                } else {
                    *(float2*)&((float*)Cv)[r * N + c] = make_float2(v0, v1);
                }
            }
        }
    }
}

// ---------------------------------------------------------------------------
// FP16 flash attention: TWO kv-tiles per __syncthreads (4-buffer K/V ring),
// ldmatrix fragments. Halves barrier count and lets warps drift across a
// 2-tile window so softmax overlaps other warps' mma.
// ---------------------------------------------------------------------------
#define FSTR 36
#define NTILES (Sq/64)
#define NSUPER (NTILES/2)
#define KVBUF (64*FSTR)
#define FAH_SMEM ((128*FSTR + 128*FSTR + 4*KVBUF + 4*KVBUF) * 4)   // 110592 B

__global__ void __launch_bounds__(256, 2) flash_attn_h16(const __half* __restrict__ qkv,
                                                         __half* __restrict__ ctx)
{
    extern __shared__ uint32_t usm[];
    uint32_t* Qs = usm;                       // [128][36]
    uint32_t* Ps = Qs + 128*FSTR;             // [128][36]
    uint32_t* Kbase = Ps + 128*FSTR;          // 4 x [64][36]
    uint32_t* Vbase = Kbase + 4*KVBUF;        // 4 x [64][36]

    int bh = blockIdx.y;
    int b = bh / Hh, h = bh % Hh;
    int q0 = blockIdx.x * 128;
    int tid = threadIdx.x;
    int lane = tid & 31;
    int w = tid >> 5;
    int r4 = lane >> 2;
    int j4 = lane & 3;

    const __half* qbase = qkv + (size_t)(b*Sq)*NQKV + h*DHd;
    const __half* kbase = qbase + Hh*DHd;
    const __half* vbase = qbase + 2*Hh*DHd;

    int rowsel = (lane & 7);
    uint32_t qa_base = smem_u32(Qs)
        + (uint32_t)(((w*16 + rowsel + ((lane >> 3) & 1)*8) * FSTR) * 4)
        + (uint32_t)(((lane >> 4) & 1) * 16);
    uint32_t pa_base = qa_base + (uint32_t)(128*FSTR*4);
    uint32_t kb_off  = (uint32_t)(((rowsel + ((lane >> 4) & 1)*8) * FSTR) * 4)
        + (uint32_t)(((lane >> 3) & 1) * 16);

    // prologue: stage Q + K0 + K1 (one group); V0,V1 via LDG->STS transpose
    #pragma unroll
    for (int i = tid; i < 128*8; i += 256) {
        int r = i >> 3, seg = i & 7;
        cp_async16(smem_u32(&Qs[r*FSTR + seg*4]),
                   qbase + (size_t)(q0 + r)*NQKV + seg*8);
    }
    #pragma unroll
    for (int hf = 0; hf < 2; hf++) {
        #pragma unroll
        for (int i = tid; i < 64*8; i += 256) {
            int r = i >> 3, seg = i & 7;
            cp_async16(smem_u32(&Kbase[hf*KVBUF + r*FSTR + seg*4]),
                       kbase + (size_t)(hf*64 + r)*NQKV + seg*8);
        }
    }
    cp_commit();
    #pragma unroll
    for (int hf = 0; hf < 2; hf++) {
        int tp = tid & 31, eg = tid >> 5;
        const __half* v0p = vbase + (size_t)(hf*64 + 2*tp)*NQKV + eg*8;
        uint4 x0 = *(const uint4*)v0p;
        uint4 x1 = *(const uint4*)(v0p + NQKV);
        const unsigned short* h0 = (const unsigned short*)&x0;
        const unsigned short* h1 = (const unsigned short*)&x1;
        #pragma unroll
        for (int j = 0; j < 8; j++)
            Vbase[hf*KVBUF + (eg*8 + j)*FSTR + tp] = (uint32_t)h0[j] | ((uint32_t)h1[j] << 16);
    }

    float o[8][4];
    #pragma unroll
    for (int nt = 0; nt < 8; nt++)
        #pragma unroll
        for (int q = 0; q < 4; q++) o[nt][q] = 0.0f;
    float mreg[2] = {-INFINITY, -INFINITY};
    float lreg[2] = {0.0f, 0.0f};

    int prow = w*16 + r4;

    for (int st = 0; st < NSUPER; st++) {
        int cur = st & 1, nxt = cur ^ 1;
        // K pair for this super landed (committed last super or prologue)
        cp_wait_all();
        // Single barrier per super: all warps finished previous super (so the
        // nxt pair of buffers is free) AND current K/V stores visible.
        __syncthreads();

        if (st + 1 < NSUPER) {
            // prefetch K pair (tiles 2*st+2, 2*st+3)
            #pragma unroll
            for (int hf = 0; hf < 2; hf++) {
                #pragma unroll
                for (int i = tid; i < 64*8; i += 256) {
                    int r = i >> 3, seg = i & 7;
                    cp_async16(smem_u32(&Kbase[(nxt*2 + hf)*KVBUF + r*FSTR + seg*4]),
                               kbase + (size_t)((2*st + 2 + hf)*64 + r)*NQKV + seg*8);
                }
            }
            cp_commit();
            // prefetch V pair via LDG->STS transpose
            #pragma unroll
            for (int hf = 0; hf < 2; hf++) {
                int tp = tid & 31, eg = tid >> 5;
                const __half* v0p = vbase + (size_t)((2*st + 2 + hf)*64 + 2*tp)*NQKV + eg*8;
                uint4 x0 = *(const uint4*)v0p;
                uint4 x1 = *(const uint4*)(v0p + NQKV);
                const unsigned short* h0 = (const unsigned short*)&x0;
                const unsigned short* h1 = (const unsigned short*)&x1;
                #pragma unroll
                for (int j = 0; j < 8; j++)
                    Vbase[(nxt*2 + hf)*KVBUF + (eg*8 + j)*FSTR + tp] =
                        (uint32_t)h0[j] | ((uint32_t)h1[j] << 16);
            }
        }

        // process the two tiles of this super-iteration
        #pragma unroll
        for (int hf = 0; hf < 2; hf++) {
            uint32_t kB = smem_u32(&Kbase[(cur*2 + hf)*KVBUF]) + kb_off;
            uint32_t vB = smem_u32(&Vbase[(cur*2 + hf)*KVBUF]) + kb_off;

            // S = Q K^T
            float s[8][4];
            #pragma unroll
            for (int nt = 0; nt < 8; nt++)
                #pragma unroll
                for (int q = 0; q < 4; q++) s[nt][q] = 0.0f;

            #pragma unroll
            for (int ks = 0; ks < 4; ks++) {
                uint32_t a[4];
                ldsm_x4(a[0], a[1], a[2], a[3], qa_base + ks*32);
                #pragma unroll
                for (int p = 0; p < 4; p++) {
                    uint32_t b0, b1, b2, b3;
                    ldsm_x4(b0, b1, b2, b3, kB + (uint32_t)(p*16*FSTR*4) + ks*32);
                    uint32_t bf0[2] = {b0, b1};
                    uint32_t bf1[2] = {b2, b3};
                    mma_f16(s[2*p],   a, bf0);
                    mma_f16(s[2*p+1], a, bf1);
                }
            }

            // online softmax (rows prow, prow+8), quad reductions
            float mx0 = -INFINITY, mx1 = -INFINITY;
            #pragma unroll
            for (int nt = 0; nt < 8; nt++) {
                mx0 = fmaxf(mx0, fmaxf(s[nt][0], s[nt][1]));
                mx1 = fmaxf(mx1, fmaxf(s[nt][2], s[nt][3]));
            }
            mx0 = fmaxf(mx0, __shfl_xor_sync(0xffffffffu, mx0, 1));
            mx0 = fmaxf(mx0, __shfl_xor_sync(0xffffffffu, mx0, 2));
            mx1 = fmaxf(mx1, __shfl_xor_sync(0xffffffffu, mx1, 1));
            mx1 = fmaxf(mx1, __shfl_xor_sync(0xffffffffu, mx1, 2));

            float mn0 = fmaxf(mreg[0], mx0);
            float mn1 = fmaxf(mreg[1], mx1);
            float al0 = __expf(mreg[0] - mn0);
            float al1 = __expf(mreg[1] - mn1);

            float sum0 = 0.0f, sum1 = 0.0f;
            #pragma unroll
            for (int nt = 0; nt < 8; nt++) {
                s[nt][0] = __expf(s[nt][0] - mn0);
                s[nt][1] = __expf(s[nt][1] - mn0);
                s[nt][2] = __expf(s[nt][2] - mn1);
                s[nt][3] = __expf(s[nt][3] - mn1);
                sum0 += s[nt][0] + s[nt][1];
                sum1 += s[nt][2] + s[nt][3];
            }
            sum0 += __shfl_xor_sync(0xffffffffu, sum0, 1);
            sum0 += __shfl_xor_sync(0xffffffffu, sum0, 2);
            sum1 += __shfl_xor_sync(0xffffffffu, sum1, 1);
            sum1 += __shfl_xor_sync(0xffffffffu, sum1, 2);

            lreg[0] = lreg[0]*al0 + sum0;  mreg[0] = mn0;
            lreg[1] = lreg[1]*al1 + sum1;  mreg[1] = mn1;

            #pragma unroll
            for (int nt = 0; nt < 8; nt++) {
                o[nt][0] *= al0; o[nt][1] *= al0;
                o[nt][2] *= al1; o[nt][3] *= al1;
            }

            // P -> half2 in A-frag layout (own rows only)
            #pragma unroll
            for (int nt = 0; nt < 8; nt++) {
                Ps[prow*FSTR + nt*4 + j4]     = pack_h2(s[nt][0], s[nt][1]);
                Ps[(prow+8)*FSTR + nt*4 + j4] = pack_h2(s[nt][2], s[nt][3]);
            }
            __syncwarp();

            // O += P V
            #pragma unroll
            for (int ks = 0; ks < 4; ks++) {
                uint32_t a[4];
                ldsm_x4(a[0], a[1], a[2], a[3], pa_base + ks*32);
                #pragma unroll
                for (int p = 0; p < 4; p++) {
                    uint32_t b0, b1, b2, b3;
                    ldsm_x4(b0, b1, b2, b3, vB + (uint32_t)(p*16*FSTR*4) + ks*32);
                    uint32_t bf0[2] = {b0, b1};
                    uint32_t bf1[2] = {b2, b3};
                    mma_f16(o[2*p],   a, bf0);
                    mma_f16(o[2*p+1], a, bf1);
                }
            }
        }
    }

    float inv0 = 1.0f / lreg[0];
    float inv1 = 1.0f / lreg[1];
    int gr0 = q0 + prow;
    int gr1 = gr0 + 8;
    #pragma unroll
    for (int nt = 0; nt < 8; nt++) {
        int c = nt*8 + 2*j4;
        *(__half2*)&ctx[((size_t)(b*Sq + gr0)*Hh + h)*DHd + c] =
            __floats2half2_rn(o[nt][0]*inv0, o[nt][1]*inv0);
        *(__half2*)&ctx[((size_t)(b*Sq + gr1)*Hh + h)*DHd + c] =
            __floats2half2_rn(o[nt][2]*inv1, o[nt][3]*inv1);
    }
}

// ---------------------------------------------------------------------------
// Launch — prep kernels forked onto a second stream (graph fork/join)
// ---------------------------------------------------------------------------
extern "C" void kernel_launch(void* const* d_in, const int* in_sizes, int n_in,
                              void* d_out, int out_size)
{
    (void)in_sizes; (void)n_in; (void)out_size;
    const float* x     = (const float*)d_in[0];
    const float* ln1_w = (const float*)d_in[1];
    const float* ln1_b = (const float*)d_in[2];
    const float* ln2_w = (const float*)d_in[3];
    const float* ln2_b = (const float*)d_in[4];
    const float* Wq    = (const float*)d_in[5];
    const float* bq    = (const float*)d_in[6];
    const float* Wk    = (const float*)d_in[7];
    const float* bk    = (const float*)d_in[8];
    const float* Wv    = (const float*)d_in[9];
    const float* bv    = (const float*)d_in[10];
    const float* Wo    = (const float*)d_in[11];
    const float* bo    = (const float*)d_in[12];
    const float* fc1_w = (const float*)d_in[13];
    const float* fc1_b = (const float*)d_in[14];
    const float* fc2_w = (const float*)d_in[15];
    const float* fc2_b = (const float*)d_in[16];
    float* out = (float*)d_out;

    __half *p_wqkv, *p_wo, *p_fc1, *p_fc2, *p_h1, *p_qkv, *p_ctx, *p_h2, *p_a1;
    float *p_bqkv, *p_y1;
    cudaGetSymbolAddress((void**)&p_wqkv, g_wqkv_h);
    cudaGetSymbolAddress((void**)&p_bqkv, g_bqkv);
    cudaGetSymbolAddress((void**)&p_wo,   g_wo_h);
    cudaGetSymbolAddress((void**)&p_fc1,  g_fc1_h);
    cudaGetSymbolAddress((void**)&p_fc2,  g_fc2_h);
    cudaGetSymbolAddress((void**)&p_h1,   g_h1);
    cudaGetSymbolAddress((void**)&p_qkv,  g_qkv);
    cudaGetSymbolAddress((void**)&p_ctx,  g_ctx);
    cudaGetSymbolAddress((void**)&p_y1,   g_y1);
    cudaGetSymbolAddress((void**)&p_h2,   g_h2);
    cudaGetSymbolAddress((void**)&p_a1,   g_a1);

    static cudaStream_t s2 = nullptr;
    static cudaEvent_t ev_fork = nullptr, ev_repack = nullptr, ev_conv = nullptr;
    static int fa_attr_set = 0;
    if (!fa_attr_set) {
        cudaFuncSetAttribute(flash_attn_h16,
                             cudaFuncAttributeMaxDynamicSharedMemorySize, (int)FAH_SMEM);
        cudaStreamCreateWithFlags(&s2, cudaStreamNonBlocking);
        cudaEventCreateWithFlags(&ev_fork,   cudaEventDisableTiming);
        cudaEventCreateWithFlags(&ev_repack, cudaEventDisableTiming);
        cudaEventCreateWithFlags(&ev_conv,   cudaEventDisableTiming);
        fa_attr_set = 1;
    }

    // fork side stream from the (capture) default stream
    cudaEventRecord(ev_fork, 0);
    cudaStreamWaitEvent(s2, ev_fork, 0);

    // side stream: repack (needed by step 3), then weight transposes (7/9/10)
    repack_qkv_kernel<<<(Dm*NQKV + 255)/256, 256, 0, s2>>>(Wq, bq, Wk, bk, Wv, bv);
    cudaEventRecord(ev_repack, s2);
    conv_t<<<dim3(Dm/32, Dm/32), dim3(32,8), 0, s2>>>(Wo,    p_wo,  Dm, Dm);
    conv_t<<<dim3(Ff/32, Dm/32), dim3(32,8), 0, s2>>>(fc1_w, p_fc1, Dm, Ff);
    conv_t<<<dim3(Dm/32, Ff/32), dim3(32,8), 0, s2>>>(fc2_w, p_fc2, Ff, Dm);
    cudaEventRecord(ev_conv, s2);

    // main stream: ln1 overlaps repack
    ln_kernel<<<Mrows/8, 256>>>(x, ln1_w, ln1_b, p_h1);

    // join 1: repack done before QKV GEMM
    cudaStreamWaitEvent(0, ev_repack, 0);

    // 3. qkv = h1 @ Wqkv + bqkv   [8192, 2304] half
    hgemm128<1|16><<<dim3(NQKV/128, Mrows/128), 256>>>(p_h1, p_wqkv, p_bqkv, nullptr,
                                                       (void*)p_qkv, Mrows, NQKV, Dm);

    // 4-6. fp16 tensor-core attention -> ctx [8192, 768] half
    flash_attn_h16<<<dim3(Sq/128, Bsz*Hh), 256, FAH_SMEM>>>(p_qkv, p_ctx);

    // join 2: weight transposes done before Wo GEMM (covers fc1/fc2 too)
    cudaStreamWaitEvent(0, ev_conv, 0);

    // 7. y1 = x + ctx @ Wo + bo  (f32)
    hgemm128<1|4><<<dim3(Dm/128, Mrows/128), 256>>>(p_ctx, p_wo, bo, x,
                                                    (void*)p_y1, Mrows, Dm, Dm);

    // 8. h2 = ln2(y1) (half)
    ln_kernel<<<Mrows/8, 256>>>(p_y1, ln2_w, ln2_b, p_h2);

    // 9. a1 = gelu(h2 @ fc1_w + fc1_b) (half)
    hgemm128<1|2|16><<<dim3(Ff/128, Mrows/128), 256>>>(p_h2, p_fc1, fc1_b, nullptr,
                                                       (void*)p_a1, Mrows, Ff, Dm);

    // 10. out = y1 + a1 @ fc2_w + fc2_b  (f32)
    hgemm128<1|4><<<dim3(Dm/128, Mrows/128), 256>>>(p_a1, p_fc2, fc2_b, p_y1,
                                                    (void*)out, Mrows, Dm, Ff);
}